// round 11
// baseline (speedup 1.0000x reference)
#include <cuda_runtime.h>
#include <cuda_bf16.h>
#include <math.h>
#include <stdint.h>

#define E_ 768
#define L_ 12
#define H_ 12
#define D_ 64
#define B_ 2
#define T_ 1024
#define V_ 50257
#define VP_ 50304
#define M_ (B_*T_)
#define BHTD_ (B_*H_*T_*D_)

// ---------------- scratch ----------------
__device__ float g_x   [M_*E_];
__device__ __nv_bfloat16 g_qkv6[6*BHTD_];    // qh,ql,kh,kl,vh,vl each [B,H,T,D]
__device__ __nv_bfloat16 g_xh [M_*E_],  g_xl [M_*E_];
__device__ __nv_bfloat16 g_yh [M_*E_],  g_yl [M_*E_];
__device__ __nv_bfloat16 g_h4h[M_*4*E_],g_h4l[M_*4*E_];
__device__ __nv_bfloat16 g_attnTh[L_*3*E_*E_], g_attnTl[L_*3*E_*E_];
__device__ __nv_bfloat16 g_projTh[L_*E_*E_],   g_projTl[L_*E_*E_];
__device__ __nv_bfloat16 g_fcTh  [L_*4*E_*E_], g_fcTl  [L_*4*E_*E_];
__device__ __nv_bfloat16 g_fcpTh [L_*4*E_*E_], g_fcpTl [L_*4*E_*E_];
__device__ __nv_bfloat16 g_wteh  [VP_*E_],     g_wtel  [VP_*E_];

// ---------------- helpers ----------------
__device__ __forceinline__ uint32_t cvta_smem(const void* p){
    uint32_t a;
    asm("{.reg .u64 t; cvta.to.shared.u64 t, %1; cvt.u32.u64 %0, t;}" : "=r"(a) : "l"(p));
    return a;
}
__device__ __forceinline__ void ldsm4(uint32_t* r, uint32_t addr){
    asm volatile("ldmatrix.sync.aligned.m8n8.x4.shared.b16 {%0,%1,%2,%3}, [%4];"
        : "=r"(r[0]),"=r"(r[1]),"=r"(r[2]),"=r"(r[3]) : "r"(addr));
}
__device__ __forceinline__ void ldsm4t(uint32_t* r, uint32_t addr){
    asm volatile("ldmatrix.sync.aligned.m8n8.x4.trans.shared.b16 {%0,%1,%2,%3}, [%4];"
        : "=r"(r[0]),"=r"(r[1]),"=r"(r[2]),"=r"(r[3]) : "r"(addr));
}
__device__ __forceinline__ void mma16816(float* d, const uint32_t* a, const uint32_t* b){
    asm volatile("mma.sync.aligned.m16n8k16.row.col.f32.bf16.bf16.f32 "
        "{%0,%1,%2,%3}, {%4,%5,%6,%7}, {%8,%9}, {%0,%1,%2,%3};"
        : "+f"(d[0]),"+f"(d[1]),"+f"(d[2]),"+f"(d[3])
        : "r"(a[0]),"r"(a[1]),"r"(a[2]),"r"(a[3]), "r"(b[0]),"r"(b[1]));
}
__device__ __forceinline__ void cpa16(uint32_t s, const void* g){
    asm volatile("cp.async.cg.shared.global [%0], [%1], 16;" :: "r"(s), "l"(g));
}
__device__ __forceinline__ float gelu_f(float v){
    return 0.5f * v * (1.0f + erff(v * 0.70710678118654752f));
}
__device__ __forceinline__ uint32_t packbf(float a, float b){
    __nv_bfloat162 t = __floats2bfloat162_rn(a, b);
    return *reinterpret_cast<uint32_t*>(&t);
}
__device__ __forceinline__ float bfhi(float a){
    return __bfloat162float(__float2bfloat16_rn(a));
}
__device__ __forceinline__ void split_bf(float v, __nv_bfloat16& h, __nv_bfloat16& l){
    h = __float2bfloat16_rn(v);
    l = __float2bfloat16_rn(v - __bfloat162float(h));
}

// ------- bf16-split mma.sync GEMM: 128x128x32, 3-stage single-sync ring ------
// row layout (144B): [32 bf16 hi | 32 bf16 lo | 16B pad]; A at 0, B at +18432
#define GROWB 144
#define GOPB  18432
#define GSTAGE 36864
#define GEMM_SMEM (3*GSTAGE)     // 110592 -> 2 CTAs/SM

// EPI: 0 none, 1 +bias, 2 gelu(+bias), 3 +bias+residual
// OUT: 0 fp32 C, 1 bf16 hi/lo (Ch,Cl), 2 qkv hi/lo head-scatter into Ch
template<int EPI, int OUT>
__global__ void __launch_bounds__(256, 2)
gemm_bf(const __nv_bfloat16* __restrict__ Ahg, const __nv_bfloat16* __restrict__ Alg,
        const __nv_bfloat16* __restrict__ Bhg, const __nv_bfloat16* __restrict__ Blg,
        const float* __restrict__ bias, const float* __restrict__ res,
        float* __restrict__ C, __nv_bfloat16* __restrict__ Ch,
        __nv_bfloat16* __restrict__ Cl, int M, int N, int K) {
    extern __shared__ char smraw[];
    const uint32_t sb = cvta_smem(smraw);
    const int tid = threadIdx.x;
    const int lane = tid & 31, wid = tid >> 5;
    const int wm = wid & 3, wn = wid >> 2;
    const int m0 = blockIdx.x * 128, n0 = blockIdx.y * 128;
    const int nkb = K >> 5;

    float acc[2][8][4];
    #pragma unroll
    for (int i = 0; i < 2; i++)
        #pragma unroll
        for (int j = 0; j < 8; j++)
            #pragma unroll
            for (int t = 0; t < 4; t++) acc[i][j][t] = 0.f;

    auto load_stage = [&](int kb){
        const uint32_t st = sb + (uint32_t)(kb % 3) * GSTAGE;
        const int k0 = kb * 32;
        #pragma unroll
        for (int i = 0; i < 8; i++) {
            int j = tid + (i << 8);
            int op = j >> 10, row = (j >> 3) & 127, ch = j & 7;
            const __nv_bfloat16* src =
                (op ? (ch < 4 ? Bhg : Blg) : (ch < 4 ? Ahg : Alg))
                + (size_t)((op ? n0 : m0) + row) * K + k0 + (ch & 3) * 8;
            cpa16(st + (uint32_t)(op*GOPB + row*GROWB + ch*16), src);
        }
    };

    load_stage(0);
    asm volatile("cp.async.commit_group;" ::: "memory");
    load_stage(1);
    asm volatile("cp.async.commit_group;" ::: "memory");

    for (int kb = 0; kb < nkb; kb++) {
        asm volatile("cp.async.wait_group 1;" ::: "memory");
        __syncthreads();
        if (kb + 2 < nkb) load_stage(kb + 2);
        asm volatile("cp.async.commit_group;" ::: "memory");

        const uint32_t st = sb + (uint32_t)(kb % 3) * GSTAGE;
        const uint32_t Ab = st, Bb = st + GOPB;
        #pragma unroll
        for (int ks = 0; ks < 2; ks++) {
            uint32_t ah[2][4], al[2][4], bhf[8][2], blf[8][2];
            #pragma unroll
            for (int mi = 0; mi < 2; mi++) {
                int row = wm*32 + mi*16 + (lane & 15);
                int ch  = 2*ks + (lane >> 4);
                uint32_t off = (uint32_t)(row*GROWB + ch*16);
                ldsm4(ah[mi], Ab + off);
                ldsm4(al[mi], Ab + off + 64);
            }
            #pragma unroll
            for (int p2 = 0; p2 < 4; p2++) {
                int nr = wn*64 + p2*16 + (lane & 7) + ((lane >> 4) << 3);
                int ch = 2*ks + ((lane >> 3) & 1);
                uint32_t off = (uint32_t)(nr*GROWB + ch*16);
                uint32_t t[4];
                ldsm4(t, Bb + off);
                bhf[2*p2][0]=t[0]; bhf[2*p2][1]=t[1]; bhf[2*p2+1][0]=t[2]; bhf[2*p2+1][1]=t[3];
                ldsm4(t, Bb + off + 64);
                blf[2*p2][0]=t[0]; blf[2*p2][1]=t[1]; blf[2*p2+1][0]=t[2]; blf[2*p2+1][1]=t[3];
            }
            #pragma unroll
            for (int mi = 0; mi < 2; mi++)
                #pragma unroll
                for (int nj = 0; nj < 8; nj++) {
                    mma16816(acc[mi][nj], ah[mi], bhf[nj]);
                    mma16816(acc[mi][nj], ah[mi], blf[nj]);
                    mma16816(acc[mi][nj], al[mi], bhf[nj]);
                }
        }
    }

    // ---- epilogue ----
    const int mrow = m0 + wm*32 + (lane >> 2);
    const int ncol = n0 + wn*64 + 2*(lane & 3);
    const bool vec_ok = ((N & 1) == 0);
    #pragma unroll
    for (int mi = 0; mi < 2; mi++) {
        #pragma unroll
        for (int nj = 0; nj < 8; nj++) {
            int c = ncol + nj*8;
            #pragma unroll
            for (int h2 = 0; h2 < 2; h2++) {
                int rr = mrow + mi*16 + h2*8;
                float v0 = acc[mi][nj][h2*2], v1 = acc[mi][nj][h2*2+1];
                if (EPI >= 1 && c < N)     v0 += bias[c];
                if (EPI >= 1 && c+1 < N)   v1 += bias[c+1];
                if (EPI == 2) { v0 = gelu_f(v0); v1 = gelu_f(v1); }
                if (OUT == 2) {
                    int which = c / E_, e = c % E_;
                    int hh = e >> 6, d = e & 63;
                    int b = rr >> 10, t = rr & (T_-1);
                    if (which == 0) { v0 *= 0.125f; v1 *= 0.125f; }
                    size_t off = (((size_t)(b*H_ + hh)*T_) + t)*D_ + d;
                    __nv_bfloat16 h0, l0, h1, l1;
                    split_bf(v0, h0, l0); split_bf(v1, h1, l1);
                    __nv_bfloat162 hv; hv.x = h0; hv.y = h1;
                    __nv_bfloat162 lv; lv.x = l0; lv.y = l1;
                    *(__nv_bfloat162*)(Ch + (size_t)(2*which)*BHTD_ + off)   = hv;
                    *(__nv_bfloat162*)(Ch + (size_t)(2*which+1)*BHTD_ + off) = lv;
                } else if (OUT == 1) {
                    if (EPI == 3) {
                        v0 += res[(size_t)rr*N + c]; v1 += res[(size_t)rr*N + c + 1];
                    }
                    __nv_bfloat16 h0, l0, h1, l1;
                    split_bf(v0, h0, l0); split_bf(v1, h1, l1);
                    __nv_bfloat162 hv; hv.x = h0; hv.y = h1;
                    __nv_bfloat162 lv; lv.x = l0; lv.y = l1;
                    *(__nv_bfloat162*)(Ch + (size_t)rr*N + c) = hv;
                    *(__nv_bfloat162*)(Cl + (size_t)rr*N + c) = lv;
                } else {
                    if (vec_ok && c + 1 < N) {
                        if (EPI == 3) {
                            v0 += res[(size_t)rr*N + c]; v1 += res[(size_t)rr*N + c + 1];
                        }
                        float2 o; o.x = v0; o.y = v1;
                        *(float2*)(C + (size_t)rr*N + c) = o;
                    } else {
                        if (c < N) {
                            if (EPI == 3) v0 += res[(size_t)rr*N + c];
                            C[(size_t)rr*N + c] = v0;
                        }
                        if (c + 1 < N) {
                            if (EPI == 3) v1 += res[(size_t)rr*N + c + 1];
                            C[(size_t)rr*N + c + 1] = v1;
                        }
                    }
                }
            }
        }
    }
}

// ------ tensor-core flash attention: serial K/V loads (36KB, high occ) -------
// Round-8 structure + masked-block skips from Round 9.
#define FROW 144
#define FA2_SMEM 36864

__global__ void __launch_bounds__(256)
flash2_k(const __nv_bfloat16* __restrict__ qkv6,
         __nv_bfloat16* __restrict__ yh, __nv_bfloat16* __restrict__ yl) {
    extern __shared__ char fsm[];
    const uint32_t sb = cvta_smem(fsm);
    const int tid = threadIdx.x, lane = tid & 31, w = tid >> 5;
    const int q0 = blockIdx.x * 128, bh = blockIdx.y;
    const __nv_bfloat16 *qh_g = qkv6,            *ql_g = qkv6 + BHTD_;
    const __nv_bfloat16 *kh_g = qkv6 + 2*BHTD_,  *kl_g = qkv6 + 3*BHTD_;
    const __nv_bfloat16 *vh_g = qkv6 + 4*BHTD_,  *vl_g = qkv6 + 5*BHTD_;
    const size_t hb = (size_t)bh * T_ * D_;

    // ---- stage Q (128 x 64) hi/lo into smem, pull A-frags ----
    #pragma unroll
    for (int i = 0; i < 8; i++) {
        int j = tid + i*256;
        int arr = j >> 10;
        int row = (j >> 3) & 127, ch = j & 7;
        const __nv_bfloat16* src = (arr ? ql_g : qh_g) + hb + (size_t)(q0+row)*D_ + ch*8;
        cpa16(sb + (uint32_t)arr*18432u + (uint32_t)(row*FROW + ch*16), src);
    }
    asm volatile("cp.async.commit_group;" ::: "memory");
    asm volatile("cp.async.wait_group 0;" ::: "memory");
    __syncthreads();

    uint32_t qah[4][4], qal[4][4];
    {
        uint32_t base = sb + (uint32_t)((w*16 + (lane&15))*FROW) + (uint32_t)((lane>>4)*16);
        #pragma unroll
        for (int kc = 0; kc < 4; kc++) {
            ldsm4(qah[kc], base + kc*32);
            ldsm4(qal[kc], base + 18432u + kc*32);
        }
    }
    __syncthreads();

    const uint32_t Kh = sb, Kl = sb + 9216u, Vh = sb + 18432u, Vl = sb + 27648u;
    float m0 = -1e30f, m1 = -1e30f, l0 = 0.f, l1 = 0.f;
    float acc[8][4];
    #pragma unroll
    for (int nj = 0; nj < 8; nj++)
        #pragma unroll
        for (int t = 0; t < 4; t++) acc[nj][t] = 0.f;

    const int my_qmax = q0 + w*16 + 15;
    const int nkt = (q0 + 128) >> 6;
    for (int kt = 0; kt < nkt; kt++) {
        __syncthreads();
        #pragma unroll
        for (int i = 0; i < 8; i++) {
            int j = tid + i*256;
            int arr = j >> 9;
            int row = (j >> 3) & 63, ch = j & 7;
            const __nv_bfloat16* src =
                (arr==0 ? kh_g : arr==1 ? kl_g : arr==2 ? vh_g : vl_g)
                + hb + (size_t)(kt*64+row)*D_ + ch*8;
            cpa16(sb + (uint32_t)arr*9216u + (uint32_t)(row*FROW + ch*16), src);
        }
        asm volatile("cp.async.commit_group;" ::: "memory");
        asm volatile("cp.async.wait_group 0;" ::: "memory");
        __syncthreads();
        if (kt*64 > my_qmax) continue;

        float f[8][4];
        #pragma unroll
        for (int nj = 0; nj < 8; nj++)
            #pragma unroll
            for (int t = 0; t < 4; t++) f[nj][t] = 0.f;
        #pragma unroll
        for (int kc = 0; kc < 4; kc++) {
            uint32_t koff = (uint32_t)(((lane&7) + ((lane>>4)<<3))*FROW)
                          + (uint32_t)(kc*32 + (((lane>>3)&1)<<4));
            #pragma unroll
            for (int ng = 0; ng < 4; ng++) {
                if (kt*64 + ng*16 > my_qmax) continue;   // fully-masked block
                uint32_t th[4], tl[4];
                ldsm4(th, Kh + (uint32_t)(ng*16*FROW) + koff);
                ldsm4(tl, Kl + (uint32_t)(ng*16*FROW) + koff);
                mma16816(f[2*ng],   qah[kc], th);
                mma16816(f[2*ng],   qal[kc], th);
                mma16816(f[2*ng],   qah[kc], tl);
                mma16816(f[2*ng+1], qah[kc], th+2);
                mma16816(f[2*ng+1], qal[kc], th+2);
                mma16816(f[2*ng+1], qah[kc], tl+2);
            }
        }
        if (kt*64 + 63 > q0 + w*16) {
            int qg0 = q0 + w*16 + (lane>>2), qg1 = qg0 + 8;
            #pragma unroll
            for (int nj = 0; nj < 8; nj++) {
                int cc0 = kt*64 + nj*8 + 2*(lane&3), cc1 = cc0 + 1;
                if (cc0 > qg0) f[nj][0] = -1e30f;
                if (cc1 > qg0) f[nj][1] = -1e30f;
                if (cc0 > qg1) f[nj][2] = -1e30f;
                if (cc1 > qg1) f[nj][3] = -1e30f;
            }
        }
        float mx0 = -1e30f, mx1 = -1e30f;
        #pragma unroll
        for (int nj = 0; nj < 8; nj++) {
            mx0 = fmaxf(mx0, fmaxf(f[nj][0], f[nj][1]));
            mx1 = fmaxf(mx1, fmaxf(f[nj][2], f[nj][3]));
        }
        mx0 = fmaxf(mx0, __shfl_xor_sync(0xffffffffu, mx0, 1));
        mx0 = fmaxf(mx0, __shfl_xor_sync(0xffffffffu, mx0, 2));
        mx1 = fmaxf(mx1, __shfl_xor_sync(0xffffffffu, mx1, 1));
        mx1 = fmaxf(mx1, __shfl_xor_sync(0xffffffffu, mx1, 2));
        float nm0 = fmaxf(m0, mx0), nm1 = fmaxf(m1, mx1);
        float al0 = __expf(m0 - nm0), al1 = __expf(m1 - nm1);
        m0 = nm0; m1 = nm1;

        float s0 = 0.f, s1 = 0.f;
        uint32_t ph[4][4], pl[4][4];
        #pragma unroll
        for (int kc = 0; kc < 4; kc++) {
            float e0 = __expf(f[2*kc][0]   - nm0), e1 = __expf(f[2*kc][1]   - nm0);
            float e2 = __expf(f[2*kc][2]   - nm1), e3 = __expf(f[2*kc][3]   - nm1);
            float g0 = __expf(f[2*kc+1][0] - nm0), g1 = __expf(f[2*kc+1][1] - nm0);
            float g2 = __expf(f[2*kc+1][2] - nm1), g3 = __expf(f[2*kc+1][3] - nm1);
            s0 += e0 + e1 + g0 + g1;
            s1 += e2 + e3 + g2 + g3;
            ph[kc][0] = packbf(e0, e1);  pl[kc][0] = packbf(e0-bfhi(e0), e1-bfhi(e1));
            ph[kc][1] = packbf(e2, e3);  pl[kc][1] = packbf(e2-bfhi(e2), e3-bfhi(e3));
            ph[kc][2] = packbf(g0, g1);  pl[kc][2] = packbf(g0-bfhi(g0), g1-bfhi(g1));
            ph[kc][3] = packbf(g2, g3);  pl[kc][3] = packbf(g2-bfhi(g2), g3-bfhi(g3));
        }
        s0 += __shfl_xor_sync(0xffffffffu, s0, 1);
        s0 += __shfl_xor_sync(0xffffffffu, s0, 2);
        s1 += __shfl_xor_sync(0xffffffffu, s1, 1);
        s1 += __shfl_xor_sync(0xffffffffu, s1, 2);
        l0 = l0 * al0 + s0;
        l1 = l1 * al1 + s1;
        #pragma unroll
        for (int nj = 0; nj < 8; nj++) {
            acc[nj][0] *= al0; acc[nj][1] *= al0;
            acc[nj][2] *= al1; acc[nj][3] *= al1;
        }
        #pragma unroll
        for (int kc = 0; kc < 4; kc++) {
            if (kt*64 + kc*16 > my_qmax) continue;       // P block all zero
            uint32_t voff = (uint32_t)((kc*16 + (lane&7) + (((lane>>3)&1)<<3))*FROW)
                          + (uint32_t)((lane>>4)*16);
            #pragma unroll
            for (int ng = 0; ng < 4; ng++) {
                uint32_t th[4], tl[4];
                ldsm4t(th, Vh + voff + (uint32_t)(ng*32));
                ldsm4t(tl, Vl + voff + (uint32_t)(ng*32));
                mma16816(acc[2*ng],   ph[kc], th);
                mma16816(acc[2*ng],   pl[kc], th);
                mma16816(acc[2*ng],   ph[kc], tl);
                mma16816(acc[2*ng+1], ph[kc], th+2);
                mma16816(acc[2*ng+1], pl[kc], th+2);
                mma16816(acc[2*ng+1], ph[kc], tl+2);
            }
        }
    }

    const float inv0 = 1.f / l0, inv1 = 1.f / l1;
    const int b = bh / H_, h = bh % H_;
    const int r0g = q0 + w*16 + (lane >> 2);
    const size_t base0 = (size_t)(b*T_ + r0g)*E_ + h*64 + 2*(lane & 3);
    const size_t base1 = base0 + (size_t)8*E_;
    #pragma unroll
    for (int nj = 0; nj < 8; nj++) {
        float o0 = acc[nj][0]*inv0, o1 = acc[nj][1]*inv0;
        float o2 = acc[nj][2]*inv1, o3 = acc[nj][3]*inv1;
        __nv_bfloat16 h0,lo0,h1,lo1,h2,lo2,h3,lo3;
        split_bf(o0,h0,lo0); split_bf(o1,h1,lo1);
        split_bf(o2,h2,lo2); split_bf(o3,h3,lo3);
        __nv_bfloat162 a; a.x=h0; a.y=h1;
        __nv_bfloat162 c; c.x=lo0; c.y=lo1;
        __nv_bfloat162 d2; d2.x=h2; d2.y=h3;
        __nv_bfloat162 e2; e2.x=lo2; e2.y=lo3;
        *(__nv_bfloat162*)(yh + base0 + nj*8) = a;
        *(__nv_bfloat162*)(yl + base0 + nj*8) = c;
        *(__nv_bfloat162*)(yh + base1 + nj*8) = d2;
        *(__nv_bfloat162*)(yl + base1 + nj*8) = e2;
    }
}

// ---------------- weight transpose+split ----------------
__global__ void transpose_split_k(const float* __restrict__ W,
                                  __nv_bfloat16* __restrict__ WTh,
                                  __nv_bfloat16* __restrict__ WTl,
                                  int K, int N) {
    __shared__ float t[32][33];
    const size_t lstride = (size_t)K * N;
    const float* Wl = W + lstride * blockIdx.z;
    __nv_bfloat16* Hh = WTh + lstride * blockIdx.z;
    __nv_bfloat16* Hl = WTl + lstride * blockIdx.z;
    int n0 = blockIdx.x * 32, k0 = blockIdx.y * 32;
    int x = threadIdx.x, y = threadIdx.y;
    #pragma unroll
    for (int i = 0; i < 32; i += 8)
        t[y + i][x] = Wl[(size_t)(k0 + y + i) * N + n0 + x];
    __syncthreads();
    #pragma unroll
    for (int i = 0; i < 32; i += 8) {
        float v = t[x][y + i];
        __nv_bfloat16 h, l; split_bf(v, h, l);
        Hh[(size_t)(n0 + y + i) * K + k0 + x] = h;
        Hl[(size_t)(n0 + y + i) * K + k0 + x] = l;
    }
}

// ---------------- wte pad+split ----------------
__global__ void wte_split_k(const float* __restrict__ wte,
                            __nv_bfloat16* __restrict__ wh,
                            __nv_bfloat16* __restrict__ wl) {
    int i = blockIdx.x * blockDim.x + threadIdx.x;
    if (i >= VP_*E_) return;
    int row = i / E_;
    float v = (row < V_) ? wte[i] : 0.f;
    __nv_bfloat16 h, l; split_bf(v, h, l);
    wh[i] = h; wl[i] = l;
}

// ---------------- embedding ----------------
__global__ void embed_k(const int* __restrict__ idx, const float* __restrict__ wte,
                        const float* __restrict__ wpe, float* __restrict__ x) {
    int i = blockIdx.x * blockDim.x + threadIdx.x;
    if (i >= M_*E_) return;
    int row = i / E_, e = i % E_;
    int t = row & (T_-1);
    x[i] = wte[(size_t)idx[row]*E_ + e] + wpe[t*E_ + e];
}

// ---------------- layernorm: 1 warp / row ----------------
__global__ void __launch_bounds__(256)
ln_k(const float* __restrict__ x, const float* __restrict__ g,
     const float* __restrict__ b,
     __nv_bfloat16* __restrict__ oh, __nv_bfloat16* __restrict__ ol) {
    const int lane = threadIdx.x & 31;
    const int row = blockIdx.x * 8 + (threadIdx.x >> 5);
    const float* xr = x + (size_t)row*E_;
    float4 v4[6];
    float a = 0.f, q = 0.f;
    #pragma unroll
    for (int i = 0; i < 6; i++) {
        v4[i] = *(const float4*)(xr + (i*32 + lane)*4);
        a += v4[i].x + v4[i].y + v4[i].z + v4[i].w;
        q += v4[i].x*v4[i].x + v4[i].y*v4[i].y + v4[i].z*v4[i].z + v4[i].w*v4[i].w;
    }
    #pragma unroll
    for (int off = 16; off > 0; off >>= 1) {
        a += __shfl_xor_sync(0xffffffffu, a, off);
        q += __shfl_xor_sync(0xffffffffu, q, off);
    }
    float mu  = a * (1.f/E_);
    float var = q * (1.f/E_) - mu*mu;
    float inv = rsqrtf(var + 1e-5f);
    #pragma unroll
    for (int i = 0; i < 6; i++) {
        int e = (i*32 + lane)*4;
        float o0 = (v4[i].x - mu)*inv*g[e+0] + b[e+0];
        float o1 = (v4[i].y - mu)*inv*g[e+1] + b[e+1];
        float o2 = (v4[i].z - mu)*inv*g[e+2] + b[e+2];
        float o3 = (v4[i].w - mu)*inv*g[e+3] + b[e+3];
        __nv_bfloat16 h0,l0,h1,l1,h2,l2,h3,l3;
        split_bf(o0,h0,l0); split_bf(o1,h1,l1);
        split_bf(o2,h2,l2); split_bf(o3,h3,l3);
        __nv_bfloat162 hv0; hv0.x=h0; hv0.y=h1;
        __nv_bfloat162 hv1; hv1.x=h2; hv1.y=h3;
        __nv_bfloat162 lv0; lv0.x=l0; lv0.y=l1;
        __nv_bfloat162 lv1; lv1.x=l2; lv1.y=l3;
        *(__nv_bfloat162*)(oh + (size_t)row*E_ + e)     = hv0;
        *(__nv_bfloat162*)(oh + (size_t)row*E_ + e + 2) = hv1;
        *(__nv_bfloat162*)(ol + (size_t)row*E_ + e)     = lv0;
        *(__nv_bfloat162*)(ol + (size_t)row*E_ + e + 2) = lv1;
    }
}

// ---------------- launch ----------------
extern "C" void kernel_launch(void* const* d_in, const int* in_sizes, int n_in,
                              void* d_out, int out_size) {
    const int*   idx    = (const int*)  d_in[0];
    const float* wte    = (const float*)d_in[1];
    const float* wpe    = (const float*)d_in[2];
    const float* ln1_g  = (const float*)d_in[3];
    const float* ln1_b  = (const float*)d_in[4];
    const float* attn_w = (const float*)d_in[5];
    const float* attn_b = (const float*)d_in[6];
    const float* proj_w = (const float*)d_in[7];
    const float* proj_b = (const float*)d_in[8];
    const float* ln2_g  = (const float*)d_in[9];
    const float* ln2_b  = (const float*)d_in[10];
    const float* fc_w   = (const float*)d_in[11];
    const float* fc_b   = (const float*)d_in[12];
    const float* fcp_w  = (const float*)d_in[13];
    const float* fcp_b  = (const float*)d_in[14];
    const float* lnf_g  = (const float*)d_in[15];
    const float* lnf_b  = (const float*)d_in[16];
    float* out = (float*)d_out;

    float *x;
    __nv_bfloat16 *qkv6, *xh, *xl, *yh, *yl, *h4h, *h4l;
    __nv_bfloat16 *attnTh, *attnTl, *projTh, *projTl, *fcTh, *fcTl, *fcpTh, *fcpTl;
    __nv_bfloat16 *wteh, *wtel;
    cudaGetSymbolAddress((void**)&x,    g_x);
    cudaGetSymbolAddress((void**)&qkv6, g_qkv6);
    cudaGetSymbolAddress((void**)&xh,   g_xh);   cudaGetSymbolAddress((void**)&xl,  g_xl);
    cudaGetSymbolAddress((void**)&yh,   g_yh);   cudaGetSymbolAddress((void**)&yl,  g_yl);
    cudaGetSymbolAddress((void**)&h4h,  g_h4h);  cudaGetSymbolAddress((void**)&h4l, g_h4l);
    cudaGetSymbolAddress((void**)&attnTh, g_attnTh); cudaGetSymbolAddress((void**)&attnTl, g_attnTl);
    cudaGetSymbolAddress((void**)&projTh, g_projTh); cudaGetSymbolAddress((void**)&projTl, g_projTl);
    cudaGetSymbolAddress((void**)&fcTh,   g_fcTh);   cudaGetSymbolAddress((void**)&fcTl,   g_fcTl);
    cudaGetSymbolAddress((void**)&fcpTh,  g_fcpTh);  cudaGetSymbolAddress((void**)&fcpTl,  g_fcpTl);
    cudaGetSymbolAddress((void**)&wteh,   g_wteh);   cudaGetSymbolAddress((void**)&wtel,   g_wtel);

    cudaFuncSetAttribute(gemm_bf<1,2>, cudaFuncAttributeMaxDynamicSharedMemorySize, GEMM_SMEM);
    cudaFuncSetAttribute(gemm_bf<3,0>, cudaFuncAttributeMaxDynamicSharedMemorySize, GEMM_SMEM);
    cudaFuncSetAttribute(gemm_bf<2,1>, cudaFuncAttributeMaxDynamicSharedMemorySize, GEMM_SMEM);
    cudaFuncSetAttribute(gemm_bf<0,0>, cudaFuncAttributeMaxDynamicSharedMemorySize, GEMM_SMEM);
    cudaFuncSetAttribute(flash2_k,     cudaFuncAttributeMaxDynamicSharedMemorySize, FA2_SMEM);

    dim3 tb(32, 8);
    transpose_split_k<<<dim3(3*E_/32, E_/32, L_), tb>>>(attn_w, attnTh, attnTl, E_, 3*E_);
    transpose_split_k<<<dim3(E_/32,   E_/32, L_), tb>>>(proj_w, projTh, projTl, E_, E_);
    transpose_split_k<<<dim3(4*E_/32, E_/32, L_), tb>>>(fc_w,   fcTh,   fcTl,   E_, 4*E_);
    transpose_split_k<<<dim3(E_/32, 4*E_/32, L_), tb>>>(fcp_w,  fcpTh,  fcpTl,  4*E_, E_);
    wte_split_k<<<(VP_*E_ + 255)/256, 256>>>(wte, wteh, wtel);

    embed_k<<<(M_*E_ + 255)/256, 256>>>(idx, wte, wpe, x);

    for (int l = 0; l < L_; l++) {
        ln_k<<<M_/8, 256>>>(x, ln1_g + l*E_, ln1_b + l*E_, xh, xl);
        gemm_bf<1,2><<<dim3(M_/128, 3*E_/128), 256, GEMM_SMEM>>>(
            xh, xl, attnTh + (size_t)l*3*E_*E_, attnTl + (size_t)l*3*E_*E_,
            attn_b + l*3*E_, nullptr, nullptr, qkv6, nullptr, M_, 3*E_, E_);
        flash2_k<<<dim3(T_/128, B_*H_), 256, FA2_SMEM>>>(qkv6, yh, yl);
        gemm_bf<3,0><<<dim3(M_/128, E_/128), 256, GEMM_SMEM>>>(
            yh, yl, projTh + (size_t)l*E_*E_, projTl + (size_t)l*E_*E_,
            proj_b + l*E_, x, x, nullptr, nullptr, M_, E_, E_);
        ln_k<<<M_/8, 256>>>(x, ln2_g + l*E_, ln2_b + l*E_, xh, xl);
        gemm_bf<2,1><<<dim3(M_/128, 4*E_/128), 256, GEMM_SMEM>>>(
            xh, xl, fcTh + (size_t)l*4*E_*E_, fcTl + (size_t)l*4*E_*E_,
            fc_b + l*4*E_, nullptr, nullptr, h4h, h4l, M_, 4*E_, E_);
        gemm_bf<3,0><<<dim3(M_/128, E_/128), 256, GEMM_SMEM>>>(
            h4h, h4l, fcpTh + (size_t)l*4*E_*E_, fcpTl + (size_t)l*4*E_*E_,
            fcp_b + l*E_, x, x, nullptr, nullptr, M_, E_, 4*E_);
    }

    ln_k<<<M_/8, 256>>>(x, lnf_g, lnf_b, xh, xl);
    gemm_bf<0,0><<<dim3(M_/128, VP_/128), 256, GEMM_SMEM>>>(
        xh, xl, wteh, wtel, nullptr, nullptr, out, nullptr, nullptr, M_, V_, E_);
}

// round 12
// speedup vs baseline: 1.0354x; 1.0354x over previous
#include <cuda_runtime.h>
#include <cuda_bf16.h>
#include <math.h>
#include <stdint.h>

#define E_ 768
#define L_ 12
#define H_ 12
#define D_ 64
#define B_ 2
#define T_ 1024
#define V_ 50257
#define VP_ 50304
#define M_ (B_*T_)
#define BHTD_ (B_*H_*T_*D_)

// ---------------- scratch ----------------
__device__ float g_x   [M_*E_];
__device__ __nv_bfloat16 g_qkv6[6*BHTD_];    // qh,ql,kh,kl,vh,vl each [B,H,T,D]
__device__ __nv_bfloat16 g_xh [M_*E_],  g_xl [M_*E_];
__device__ __nv_bfloat16 g_yh [M_*E_],  g_yl [M_*E_];
__device__ __nv_bfloat16 g_h4h[M_*4*E_],g_h4l[M_*4*E_];
__device__ __nv_bfloat16 g_attnTh[L_*3*E_*E_], g_attnTl[L_*3*E_*E_];
__device__ __nv_bfloat16 g_projTh[L_*E_*E_],   g_projTl[L_*E_*E_];
__device__ __nv_bfloat16 g_fcTh  [L_*4*E_*E_], g_fcTl  [L_*4*E_*E_];
__device__ __nv_bfloat16 g_fcpTh [L_*4*E_*E_], g_fcpTl [L_*4*E_*E_];
__device__ __nv_bfloat16 g_wteh  [VP_*E_],     g_wtel  [VP_*E_];

// ---------------- helpers ----------------
__device__ __forceinline__ uint32_t cvta_smem(const void* p){
    uint32_t a;
    asm("{.reg .u64 t; cvta.to.shared.u64 t, %1; cvt.u32.u64 %0, t;}" : "=r"(a) : "l"(p));
    return a;
}
__device__ __forceinline__ void ldsm4(uint32_t* r, uint32_t addr){
    asm volatile("ldmatrix.sync.aligned.m8n8.x4.shared.b16 {%0,%1,%2,%3}, [%4];"
        : "=r"(r[0]),"=r"(r[1]),"=r"(r[2]),"=r"(r[3]) : "r"(addr));
}
__device__ __forceinline__ void ldsm4t(uint32_t* r, uint32_t addr){
    asm volatile("ldmatrix.sync.aligned.m8n8.x4.trans.shared.b16 {%0,%1,%2,%3}, [%4];"
        : "=r"(r[0]),"=r"(r[1]),"=r"(r[2]),"=r"(r[3]) : "r"(addr));
}
__device__ __forceinline__ void mma16816(float* d, const uint32_t* a, const uint32_t* b){
    asm volatile("mma.sync.aligned.m16n8k16.row.col.f32.bf16.bf16.f32 "
        "{%0,%1,%2,%3}, {%4,%5,%6,%7}, {%8,%9}, {%0,%1,%2,%3};"
        : "+f"(d[0]),"+f"(d[1]),"+f"(d[2]),"+f"(d[3])
        : "r"(a[0]),"r"(a[1]),"r"(a[2]),"r"(a[3]), "r"(b[0]),"r"(b[1]));
}
__device__ __forceinline__ void cpa16(uint32_t s, const void* g){
    asm volatile("cp.async.cg.shared.global [%0], [%1], 16;" :: "r"(s), "l"(g));
}
__device__ __forceinline__ float gelu_f(float v){
    return 0.5f * v * (1.0f + erff(v * 0.70710678118654752f));
}
__device__ __forceinline__ uint32_t packbf(float a, float b){
    __nv_bfloat162 t = __floats2bfloat162_rn(a, b);
    return *reinterpret_cast<uint32_t*>(&t);
}
__device__ __forceinline__ float bfhi(float a){
    return __bfloat162float(__float2bfloat16_rn(a));
}
__device__ __forceinline__ void split_bf(float v, __nv_bfloat16& h, __nv_bfloat16& l){
    h = __float2bfloat16_rn(v);
    l = __float2bfloat16_rn(v - __bfloat162float(h));
}

// ------- bf16-split mma.sync GEMM: 128x128x32, 3-stage single-sync ring ------
#define GROWB 144
#define GOPB  18432
#define GSTAGE 36864
#define GEMM_SMEM (3*GSTAGE)     // 110592 -> 2 CTAs/SM

// EPI: 0 none, 1 +bias, 2 gelu(+bias), 3 +bias+residual
// OUT: 0 fp32 C, 1 bf16 hi/lo (Ch,Cl), 2 qkv hi/lo head-scatter into Ch
template<int EPI, int OUT>
__global__ void __launch_bounds__(256, 2)
gemm_bf(const __nv_bfloat16* __restrict__ Ahg, const __nv_bfloat16* __restrict__ Alg,
        const __nv_bfloat16* __restrict__ Bhg, const __nv_bfloat16* __restrict__ Blg,
        const float* __restrict__ bias, const float* __restrict__ res,
        float* __restrict__ C, __nv_bfloat16* __restrict__ Ch,
        __nv_bfloat16* __restrict__ Cl, int M, int N, int K) {
    extern __shared__ char smraw[];
    const uint32_t sb = cvta_smem(smraw);
    const int tid = threadIdx.x;
    const int lane = tid & 31, wid = tid >> 5;
    const int wm = wid & 3, wn = wid >> 2;
    const int m0 = blockIdx.x * 128, n0 = blockIdx.y * 128;
    const int nkb = K >> 5;

    float acc[2][8][4];
    #pragma unroll
    for (int i = 0; i < 2; i++)
        #pragma unroll
        for (int j = 0; j < 8; j++)
            #pragma unroll
            for (int t = 0; t < 4; t++) acc[i][j][t] = 0.f;

    auto load_stage = [&](int kb){
        const uint32_t st = sb + (uint32_t)(kb % 3) * GSTAGE;
        const int k0 = kb * 32;
        #pragma unroll
        for (int i = 0; i < 8; i++) {
            int j = tid + (i << 8);
            int op = j >> 10, row = (j >> 3) & 127, ch = j & 7;
            const __nv_bfloat16* src =
                (op ? (ch < 4 ? Bhg : Blg) : (ch < 4 ? Ahg : Alg))
                + (size_t)((op ? n0 : m0) + row) * K + k0 + (ch & 3) * 8;
            cpa16(st + (uint32_t)(op*GOPB + row*GROWB + ch*16), src);
        }
    };

    load_stage(0);
    asm volatile("cp.async.commit_group;" ::: "memory");
    load_stage(1);
    asm volatile("cp.async.commit_group;" ::: "memory");

    for (int kb = 0; kb < nkb; kb++) {
        asm volatile("cp.async.wait_group 1;" ::: "memory");
        __syncthreads();
        if (kb + 2 < nkb) load_stage(kb + 2);
        asm volatile("cp.async.commit_group;" ::: "memory");

        const uint32_t st = sb + (uint32_t)(kb % 3) * GSTAGE;
        const uint32_t Ab = st, Bb = st + GOPB;
        #pragma unroll
        for (int ks = 0; ks < 2; ks++) {
            uint32_t ah[2][4], al[2][4], bhf[8][2], blf[8][2];
            #pragma unroll
            for (int mi = 0; mi < 2; mi++) {
                int row = wm*32 + mi*16 + (lane & 15);
                int ch  = 2*ks + (lane >> 4);
                uint32_t off = (uint32_t)(row*GROWB + ch*16);
                ldsm4(ah[mi], Ab + off);
                ldsm4(al[mi], Ab + off + 64);
            }
            #pragma unroll
            for (int p2 = 0; p2 < 4; p2++) {
                int nr = wn*64 + p2*16 + (lane & 7) + ((lane >> 4) << 3);
                int ch = 2*ks + ((lane >> 3) & 1);
                uint32_t off = (uint32_t)(nr*GROWB + ch*16);
                uint32_t t[4];
                ldsm4(t, Bb + off);
                bhf[2*p2][0]=t[0]; bhf[2*p2][1]=t[1]; bhf[2*p2+1][0]=t[2]; bhf[2*p2+1][1]=t[3];
                ldsm4(t, Bb + off + 64);
                blf[2*p2][0]=t[0]; blf[2*p2][1]=t[1]; blf[2*p2+1][0]=t[2]; blf[2*p2+1][1]=t[3];
            }
            #pragma unroll
            for (int mi = 0; mi < 2; mi++)
                #pragma unroll
                for (int nj = 0; nj < 8; nj++) {
                    mma16816(acc[mi][nj], ah[mi], bhf[nj]);
                    mma16816(acc[mi][nj], ah[mi], blf[nj]);
                    mma16816(acc[mi][nj], al[mi], bhf[nj]);
                }
        }
    }

    // ---- epilogue ----
    const int mrow = m0 + wm*32 + (lane >> 2);
    const int ncol = n0 + wn*64 + 2*(lane & 3);
    const bool vec_ok = ((N & 1) == 0);
    #pragma unroll
    for (int mi = 0; mi < 2; mi++) {
        #pragma unroll
        for (int nj = 0; nj < 8; nj++) {
            int c = ncol + nj*8;
            #pragma unroll
            for (int h2 = 0; h2 < 2; h2++) {
                int rr = mrow + mi*16 + h2*8;
                float v0 = acc[mi][nj][h2*2], v1 = acc[mi][nj][h2*2+1];
                if (EPI >= 1 && c < N)     v0 += bias[c];
                if (EPI >= 1 && c+1 < N)   v1 += bias[c+1];
                if (EPI == 2) { v0 = gelu_f(v0); v1 = gelu_f(v1); }
                if (OUT == 2) {
                    int which = c / E_, e = c % E_;
                    int hh = e >> 6, d = e & 63;
                    int b = rr >> 10, t = rr & (T_-1);
                    if (which == 0) { v0 *= 0.125f; v1 *= 0.125f; }
                    size_t off = (((size_t)(b*H_ + hh)*T_) + t)*D_ + d;
                    __nv_bfloat16 h0, l0, h1, l1;
                    split_bf(v0, h0, l0); split_bf(v1, h1, l1);
                    __nv_bfloat162 hv; hv.x = h0; hv.y = h1;
                    __nv_bfloat162 lv; lv.x = l0; lv.y = l1;
                    *(__nv_bfloat162*)(Ch + (size_t)(2*which)*BHTD_ + off)   = hv;
                    *(__nv_bfloat162*)(Ch + (size_t)(2*which+1)*BHTD_ + off) = lv;
                } else if (OUT == 1) {
                    if (EPI == 3) {
                        v0 += res[(size_t)rr*N + c]; v1 += res[(size_t)rr*N + c + 1];
                    }
                    __nv_bfloat16 h0, l0, h1, l1;
                    split_bf(v0, h0, l0); split_bf(v1, h1, l1);
                    __nv_bfloat162 hv; hv.x = h0; hv.y = h1;
                    __nv_bfloat162 lv; lv.x = l0; lv.y = l1;
                    *(__nv_bfloat162*)(Ch + (size_t)rr*N + c) = hv;
                    *(__nv_bfloat162*)(Cl + (size_t)rr*N + c) = lv;
                } else {
                    if (vec_ok && c + 1 < N) {
                        if (EPI == 3) {
                            v0 += res[(size_t)rr*N + c]; v1 += res[(size_t)rr*N + c + 1];
                        }
                        float2 o; o.x = v0; o.y = v1;
                        *(float2*)(C + (size_t)rr*N + c) = o;
                    } else {
                        if (c < N) {
                            if (EPI == 3) v0 += res[(size_t)rr*N + c];
                            C[(size_t)rr*N + c] = v0;
                        }
                        if (c + 1 < N) {
                            if (EPI == 3) v1 += res[(size_t)rr*N + c + 1];
                            C[(size_t)rr*N + c + 1] = v1;
                        }
                    }
                }
            }
        }
    }
}

// ------ tensor-core flash attention: 64-row q-tiles, 128 threads, 384 CTAs ---
// R8 body (serial K/V loads, no inner skips); warp = 16 q-rows x 64 k-cols.
#define FROW 144
#define FA2_SMEM 36864

__global__ void __launch_bounds__(128)
flash2_k(const __nv_bfloat16* __restrict__ qkv6,
         __nv_bfloat16* __restrict__ yh, __nv_bfloat16* __restrict__ yl) {
    extern __shared__ char fsm[];
    const uint32_t sb = cvta_smem(fsm);
    const int tid = threadIdx.x, lane = tid & 31, w = tid >> 5;   // w in 0..3
    const int q0 = blockIdx.x * 64, bh = blockIdx.y;
    const __nv_bfloat16 *qh_g = qkv6,            *ql_g = qkv6 + BHTD_;
    const __nv_bfloat16 *kh_g = qkv6 + 2*BHTD_,  *kl_g = qkv6 + 3*BHTD_;
    const __nv_bfloat16 *vh_g = qkv6 + 4*BHTD_,  *vl_g = qkv6 + 5*BHTD_;
    const size_t hb = (size_t)bh * T_ * D_;

    // ---- stage Q (64 x 64) hi/lo into smem, pull A-frags ----
    #pragma unroll
    for (int i = 0; i < 8; i++) {
        int j = tid + i*128;                 // 0..1023
        int arr = j >> 9;                    // 0 hi, 1 lo
        int row = (j >> 3) & 63, ch = j & 7;
        const __nv_bfloat16* src = (arr ? ql_g : qh_g) + hb + (size_t)(q0+row)*D_ + ch*8;
        cpa16(sb + (uint32_t)arr*18432u + (uint32_t)(row*FROW + ch*16), src);
    }
    asm volatile("cp.async.commit_group;" ::: "memory");
    asm volatile("cp.async.wait_group 0;" ::: "memory");
    __syncthreads();

    uint32_t qah[4][4], qal[4][4];
    {
        uint32_t base = sb + (uint32_t)((w*16 + (lane&15))*FROW) + (uint32_t)((lane>>4)*16);
        #pragma unroll
        for (int kc = 0; kc < 4; kc++) {
            ldsm4(qah[kc], base + kc*32);
            ldsm4(qal[kc], base + 18432u + kc*32);
        }
    }
    __syncthreads();

    const uint32_t Kh = sb, Kl = sb + 9216u, Vh = sb + 18432u, Vl = sb + 27648u;
    float m0 = -1e30f, m1 = -1e30f, l0 = 0.f, l1 = 0.f;
    float acc[8][4];
    #pragma unroll
    for (int nj = 0; nj < 8; nj++)
        #pragma unroll
        for (int t = 0; t < 4; t++) acc[nj][t] = 0.f;

    const int nkt = blockIdx.x + 1;          // (q0+64)/64
    for (int kt = 0; kt < nkt; kt++) {
        __syncthreads();
        #pragma unroll
        for (int i = 0; i < 16; i++) {
            int j = tid + i*128;             // 0..2047
            int arr = j >> 9;                // 0 kh, 1 kl, 2 vh, 3 vl
            int row = (j >> 3) & 63, ch = j & 7;
            const __nv_bfloat16* src =
                (arr==0 ? kh_g : arr==1 ? kl_g : arr==2 ? vh_g : vl_g)
                + hb + (size_t)(kt*64+row)*D_ + ch*8;
            cpa16(sb + (uint32_t)arr*9216u + (uint32_t)(row*FROW + ch*16), src);
        }
        asm volatile("cp.async.commit_group;" ::: "memory");
        asm volatile("cp.async.wait_group 0;" ::: "memory");
        __syncthreads();

        float f[8][4];
        #pragma unroll
        for (int nj = 0; nj < 8; nj++)
            #pragma unroll
            for (int t = 0; t < 4; t++) f[nj][t] = 0.f;
        #pragma unroll
        for (int kc = 0; kc < 4; kc++) {
            uint32_t koff = (uint32_t)(((lane&7) + ((lane>>4)<<3))*FROW)
                          + (uint32_t)(kc*32 + (((lane>>3)&1)<<4));
            #pragma unroll
            for (int ng = 0; ng < 4; ng++) {
                uint32_t th[4], tl[4];
                ldsm4(th, Kh + (uint32_t)(ng*16*FROW) + koff);
                ldsm4(tl, Kl + (uint32_t)(ng*16*FROW) + koff);
                mma16816(f[2*ng],   qah[kc], th);
                mma16816(f[2*ng],   qal[kc], th);
                mma16816(f[2*ng],   qah[kc], tl);
                mma16816(f[2*ng+1], qah[kc], th+2);
                mma16816(f[2*ng+1], qal[kc], th+2);
                mma16816(f[2*ng+1], qah[kc], tl+2);
            }
        }
        if (kt*64 + 63 > q0 + w*16) {
            int qg0 = q0 + w*16 + (lane>>2), qg1 = qg0 + 8;
            #pragma unroll
            for (int nj = 0; nj < 8; nj++) {
                int cc0 = kt*64 + nj*8 + 2*(lane&3), cc1 = cc0 + 1;
                if (cc0 > qg0) f[nj][0] = -1e30f;
                if (cc1 > qg0) f[nj][1] = -1e30f;
                if (cc0 > qg1) f[nj][2] = -1e30f;
                if (cc1 > qg1) f[nj][3] = -1e30f;
            }
        }
        float mx0 = -1e30f, mx1 = -1e30f;
        #pragma unroll
        for (int nj = 0; nj < 8; nj++) {
            mx0 = fmaxf(mx0, fmaxf(f[nj][0], f[nj][1]));
            mx1 = fmaxf(mx1, fmaxf(f[nj][2], f[nj][3]));
        }
        mx0 = fmaxf(mx0, __shfl_xor_sync(0xffffffffu, mx0, 1));
        mx0 = fmaxf(mx0, __shfl_xor_sync(0xffffffffu, mx0, 2));
        mx1 = fmaxf(mx1, __shfl_xor_sync(0xffffffffu, mx1, 1));
        mx1 = fmaxf(mx1, __shfl_xor_sync(0xffffffffu, mx1, 2));
        float nm0 = fmaxf(m0, mx0), nm1 = fmaxf(m1, mx1);
        float al0 = __expf(m0 - nm0), al1 = __expf(m1 - nm1);
        m0 = nm0; m1 = nm1;

        float s0 = 0.f, s1 = 0.f;
        uint32_t ph[4][4], pl[4][4];
        #pragma unroll
        for (int kc = 0; kc < 4; kc++) {
            float e0 = __expf(f[2*kc][0]   - nm0), e1 = __expf(f[2*kc][1]   - nm0);
            float e2 = __expf(f[2*kc][2]   - nm1), e3 = __expf(f[2*kc][3]   - nm1);
            float g0 = __expf(f[2*kc+1][0] - nm0), g1 = __expf(f[2*kc+1][1] - nm0);
            float g2 = __expf(f[2*kc+1][2] - nm1), g3 = __expf(f[2*kc+1][3] - nm1);
            s0 += e0 + e1 + g0 + g1;
            s1 += e2 + e3 + g2 + g3;
            ph[kc][0] = packbf(e0, e1);  pl[kc][0] = packbf(e0-bfhi(e0), e1-bfhi(e1));
            ph[kc][1] = packbf(e2, e3);  pl[kc][1] = packbf(e2-bfhi(e2), e3-bfhi(e3));
            ph[kc][2] = packbf(g0, g1);  pl[kc][2] = packbf(g0-bfhi(g0), g1-bfhi(g1));
            ph[kc][3] = packbf(g2, g3);  pl[kc][3] = packbf(g2-bfhi(g2), g3-bfhi(g3));
        }
        s0 += __shfl_xor_sync(0xffffffffu, s0, 1);
        s0 += __shfl_xor_sync(0xffffffffu, s0, 2);
        s1 += __shfl_xor_sync(0xffffffffu, s1, 1);
        s1 += __shfl_xor_sync(0xffffffffu, s1, 2);
        l0 = l0 * al0 + s0;
        l1 = l1 * al1 + s1;
        #pragma unroll
        for (int nj = 0; nj < 8; nj++) {
            acc[nj][0] *= al0; acc[nj][1] *= al0;
            acc[nj][2] *= al1; acc[nj][3] *= al1;
        }
        #pragma unroll
        for (int kc = 0; kc < 4; kc++) {
            uint32_t voff = (uint32_t)((kc*16 + (lane&7) + (((lane>>3)&1)<<3))*FROW)
                          + (uint32_t)((lane>>4)*16);
            #pragma unroll
            for (int ng = 0; ng < 4; ng++) {
                uint32_t th[4], tl[4];
                ldsm4t(th, Vh + voff + (uint32_t)(ng*32));
                ldsm4t(tl, Vl + voff + (uint32_t)(ng*32));
                mma16816(acc[2*ng],   ph[kc], th);
                mma16816(acc[2*ng],   pl[kc], th);
                mma16816(acc[2*ng],   ph[kc], tl);
                mma16816(acc[2*ng+1], ph[kc], th+2);
                mma16816(acc[2*ng+1], pl[kc], th+2);
                mma16816(acc[2*ng+1], ph[kc], tl+2);
            }
        }
    }

    const float inv0 = 1.f / l0, inv1 = 1.f / l1;
    const int b = bh / H_, h = bh % H_;
    const int r0g = q0 + w*16 + (lane >> 2);
    const size_t base0 = (size_t)(b*T_ + r0g)*E_ + h*64 + 2*(lane & 3);
    const size_t base1 = base0 + (size_t)8*E_;
    #pragma unroll
    for (int nj = 0; nj < 8; nj++) {
        float o0 = acc[nj][0]*inv0, o1 = acc[nj][1]*inv0;
        float o2 = acc[nj][2]*inv1, o3 = acc[nj][3]*inv1;
        __nv_bfloat16 h0,lo0,h1,lo1,h2,lo2,h3,lo3;
        split_bf(o0,h0,lo0); split_bf(o1,h1,lo1);
        split_bf(o2,h2,lo2); split_bf(o3,h3,lo3);
        __nv_bfloat162 a; a.x=h0; a.y=h1;
        __nv_bfloat162 c; c.x=lo0; c.y=lo1;
        __nv_bfloat162 d2; d2.x=h2; d2.y=h3;
        __nv_bfloat162 e2; e2.x=lo2; e2.y=lo3;
        *(__nv_bfloat162*)(yh + base0 + nj*8) = a;
        *(__nv_bfloat162*)(yl + base0 + nj*8) = c;
        *(__nv_bfloat162*)(yh + base1 + nj*8) = d2;
        *(__nv_bfloat162*)(yl + base1 + nj*8) = e2;
    }
}

// ---------------- weight transpose+split ----------------
__global__ void transpose_split_k(const float* __restrict__ W,
                                  __nv_bfloat16* __restrict__ WTh,
                                  __nv_bfloat16* __restrict__ WTl,
                                  int K, int N) {
    __shared__ float t[32][33];
    const size_t lstride = (size_t)K * N;
    const float* Wl = W + lstride * blockIdx.z;
    __nv_bfloat16* Hh = WTh + lstride * blockIdx.z;
    __nv_bfloat16* Hl = WTl + lstride * blockIdx.z;
    int n0 = blockIdx.x * 32, k0 = blockIdx.y * 32;
    int x = threadIdx.x, y = threadIdx.y;
    #pragma unroll
    for (int i = 0; i < 32; i += 8)
        t[y + i][x] = Wl[(size_t)(k0 + y + i) * N + n0 + x];
    __syncthreads();
    #pragma unroll
    for (int i = 0; i < 32; i += 8) {
        float v = t[x][y + i];
        __nv_bfloat16 h, l; split_bf(v, h, l);
        Hh[(size_t)(n0 + y + i) * K + k0 + x] = h;
        Hl[(size_t)(n0 + y + i) * K + k0 + x] = l;
    }
}

// ---------------- wte pad+split ----------------
__global__ void wte_split_k(const float* __restrict__ wte,
                            __nv_bfloat16* __restrict__ wh,
                            __nv_bfloat16* __restrict__ wl) {
    int i = blockIdx.x * blockDim.x + threadIdx.x;
    if (i >= VP_*E_) return;
    int row = i / E_;
    float v = (row < V_) ? wte[i] : 0.f;
    __nv_bfloat16 h, l; split_bf(v, h, l);
    wh[i] = h; wl[i] = l;
}

// ---------------- embedding ----------------
__global__ void embed_k(const int* __restrict__ idx, const float* __restrict__ wte,
                        const float* __restrict__ wpe, float* __restrict__ x) {
    int i = blockIdx.x * blockDim.x + threadIdx.x;
    if (i >= M_*E_) return;
    int row = i / E_, e = i % E_;
    int t = row & (T_-1);
    x[i] = wte[(size_t)idx[row]*E_ + e] + wpe[t*E_ + e];
}

// ---------------- layernorm: 1 warp / row ----------------
__global__ void __launch_bounds__(256)
ln_k(const float* __restrict__ x, const float* __restrict__ g,
     const float* __restrict__ b,
     __nv_bfloat16* __restrict__ oh, __nv_bfloat16* __restrict__ ol) {
    const int lane = threadIdx.x & 31;
    const int row = blockIdx.x * 8 + (threadIdx.x >> 5);
    const float* xr = x + (size_t)row*E_;
    float4 v4[6];
    float a = 0.f, q = 0.f;
    #pragma unroll
    for (int i = 0; i < 6; i++) {
        v4[i] = *(const float4*)(xr + (i*32 + lane)*4);
        a += v4[i].x + v4[i].y + v4[i].z + v4[i].w;
        q += v4[i].x*v4[i].x + v4[i].y*v4[i].y + v4[i].z*v4[i].z + v4[i].w*v4[i].w;
    }
    #pragma unroll
    for (int off = 16; off > 0; off >>= 1) {
        a += __shfl_xor_sync(0xffffffffu, a, off);
        q += __shfl_xor_sync(0xffffffffu, q, off);
    }
    float mu  = a * (1.f/E_);
    float var = q * (1.f/E_) - mu*mu;
    float inv = rsqrtf(var + 1e-5f);
    #pragma unroll
    for (int i = 0; i < 6; i++) {
        int e = (i*32 + lane)*4;
        float o0 = (v4[i].x - mu)*inv*g[e+0] + b[e+0];
        float o1 = (v4[i].y - mu)*inv*g[e+1] + b[e+1];
        float o2 = (v4[i].z - mu)*inv*g[e+2] + b[e+2];
        float o3 = (v4[i].w - mu)*inv*g[e+3] + b[e+3];
        __nv_bfloat16 h0,l0,h1,l1,h2,l2,h3,l3;
        split_bf(o0,h0,l0); split_bf(o1,h1,l1);
        split_bf(o2,h2,l2); split_bf(o3,h3,l3);
        __nv_bfloat162 hv0; hv0.x=h0; hv0.y=h1;
        __nv_bfloat162 hv1; hv1.x=h2; hv1.y=h3;
        __nv_bfloat162 lv0; lv0.x=l0; lv0.y=l1;
        __nv_bfloat162 lv1; lv1.x=l2; lv1.y=l3;
        *(__nv_bfloat162*)(oh + (size_t)row*E_ + e)     = hv0;
        *(__nv_bfloat162*)(oh + (size_t)row*E_ + e + 2) = hv1;
        *(__nv_bfloat162*)(ol + (size_t)row*E_ + e)     = lv0;
        *(__nv_bfloat162*)(ol + (size_t)row*E_ + e + 2) = lv1;
    }
}

// ---------------- launch ----------------
extern "C" void kernel_launch(void* const* d_in, const int* in_sizes, int n_in,
                              void* d_out, int out_size) {
    const int*   idx    = (const int*)  d_in[0];
    const float* wte    = (const float*)d_in[1];
    const float* wpe    = (const float*)d_in[2];
    const float* ln1_g  = (const float*)d_in[3];
    const float* ln1_b  = (const float*)d_in[4];
    const float* attn_w = (const float*)d_in[5];
    const float* attn_b = (const float*)d_in[6];
    const float* proj_w = (const float*)d_in[7];
    const float* proj_b = (const float*)d_in[8];
    const float* ln2_g  = (const float*)d_in[9];
    const float* ln2_b  = (const float*)d_in[10];
    const float* fc_w   = (const float*)d_in[11];
    const float* fc_b   = (const float*)d_in[12];
    const float* fcp_w  = (const float*)d_in[13];
    const float* fcp_b  = (const float*)d_in[14];
    const float* lnf_g  = (const float*)d_in[15];
    const float* lnf_b  = (const float*)d_in[16];
    float* out = (float*)d_out;

    float *x;
    __nv_bfloat16 *qkv6, *xh, *xl, *yh, *yl, *h4h, *h4l;
    __nv_bfloat16 *attnTh, *attnTl, *projTh, *projTl, *fcTh, *fcTl, *fcpTh, *fcpTl;
    __nv_bfloat16 *wteh, *wtel;
    cudaGetSymbolAddress((void**)&x,    g_x);
    cudaGetSymbolAddress((void**)&qkv6, g_qkv6);
    cudaGetSymbolAddress((void**)&xh,   g_xh);   cudaGetSymbolAddress((void**)&xl,  g_xl);
    cudaGetSymbolAddress((void**)&yh,   g_yh);   cudaGetSymbolAddress((void**)&yl,  g_yl);
    cudaGetSymbolAddress((void**)&h4h,  g_h4h);  cudaGetSymbolAddress((void**)&h4l, g_h4l);
    cudaGetSymbolAddress((void**)&attnTh, g_attnTh); cudaGetSymbolAddress((void**)&attnTl, g_attnTl);
    cudaGetSymbolAddress((void**)&projTh, g_projTh); cudaGetSymbolAddress((void**)&projTl, g_projTl);
    cudaGetSymbolAddress((void**)&fcTh,   g_fcTh);   cudaGetSymbolAddress((void**)&fcTl,   g_fcTl);
    cudaGetSymbolAddress((void**)&fcpTh,  g_fcpTh);  cudaGetSymbolAddress((void**)&fcpTl,  g_fcpTl);
    cudaGetSymbolAddress((void**)&wteh,   g_wteh);   cudaGetSymbolAddress((void**)&wtel,   g_wtel);

    cudaFuncSetAttribute(gemm_bf<1,2>, cudaFuncAttributeMaxDynamicSharedMemorySize, GEMM_SMEM);
    cudaFuncSetAttribute(gemm_bf<3,0>, cudaFuncAttributeMaxDynamicSharedMemorySize, GEMM_SMEM);
    cudaFuncSetAttribute(gemm_bf<2,1>, cudaFuncAttributeMaxDynamicSharedMemorySize, GEMM_SMEM);
    cudaFuncSetAttribute(gemm_bf<0,0>, cudaFuncAttributeMaxDynamicSharedMemorySize, GEMM_SMEM);
    cudaFuncSetAttribute(flash2_k,     cudaFuncAttributeMaxDynamicSharedMemorySize, FA2_SMEM);

    dim3 tb(32, 8);
    transpose_split_k<<<dim3(3*E_/32, E_/32, L_), tb>>>(attn_w, attnTh, attnTl, E_, 3*E_);
    transpose_split_k<<<dim3(E_/32,   E_/32, L_), tb>>>(proj_w, projTh, projTl, E_, E_);
    transpose_split_k<<<dim3(4*E_/32, E_/32, L_), tb>>>(fc_w,   fcTh,   fcTl,   E_, 4*E_);
    transpose_split_k<<<dim3(E_/32, 4*E_/32, L_), tb>>>(fcp_w,  fcpTh,  fcpTl,  4*E_, E_);
    wte_split_k<<<(VP_*E_ + 255)/256, 256>>>(wte, wteh, wtel);

    embed_k<<<(M_*E_ + 255)/256, 256>>>(idx, wte, wpe, x);

    for (int l = 0; l < L_; l++) {
        ln_k<<<M_/8, 256>>>(x, ln1_g + l*E_, ln1_b + l*E_, xh, xl);
        gemm_bf<1,2><<<dim3(M_/128, 3*E_/128), 256, GEMM_SMEM>>>(
            xh, xl, attnTh + (size_t)l*3*E_*E_, attnTl + (size_t)l*3*E_*E_,
            attn_b + l*3*E_, nullptr, nullptr, qkv6, nullptr, M_, 3*E_, E_);
        flash2_k<<<dim3(T_/64, B_*H_), 128, FA2_SMEM>>>(qkv6, yh, yl);
        gemm_bf<3,0><<<dim3(M_/128, E_/128), 256, GEMM_SMEM>>>(
            yh, yl, projTh + (size_t)l*E_*E_, projTl + (size_t)l*E_*E_,
            proj_b + l*E_, x, x, nullptr, nullptr, M_, E_, E_);
        ln_k<<<M_/8, 256>>>(x, ln2_g + l*E_, ln2_b + l*E_, xh, xl);
        gemm_bf<2,1><<<dim3(M_/128, 4*E_/128), 256, GEMM_SMEM>>>(
            xh, xl, fcTh + (size_t)l*4*E_*E_, fcTl + (size_t)l*4*E_*E_,
            fc_b + l*4*E_, nullptr, nullptr, h4h, h4l, M_, 4*E_, E_);
        gemm_bf<3,0><<<dim3(M_/128, E_/128), 256, GEMM_SMEM>>>(
            h4h, h4l, fcpTh + (size_t)l*4*E_*E_, fcpTl + (size_t)l*4*E_*E_,
            fcp_b + l*E_, x, x, nullptr, nullptr, M_, E_, 4*E_);
    }

    ln_k<<<M_/8, 256>>>(x, lnf_g, lnf_b, xh, xl);
    gemm_bf<0,0><<<dim3(M_/128, VP_/128), 256, GEMM_SMEM>>>(
        xh, xl, wteh, wtel, nullptr, nullptr, out, nullptr, nullptr, M_, V_, E_);
}

// round 13
// speedup vs baseline: 1.3137x; 1.2689x over previous
#include <cuda_runtime.h>
#include <cuda_fp16.h>
#include <math.h>
#include <stdint.h>

#define E_ 768
#define L_ 12
#define H_ 12
#define D_ 64
#define B_ 2
#define T_ 1024
#define V_ 50257
#define VP_ 50304
#define M_ (B_*T_)
#define BHTD_ (B_*H_*T_*D_)

// ---------------- scratch ----------------
__device__ float g_x   [M_*E_];
__device__ __half g_qkv4[4*BHTD_];           // qh,ql,kh,vh each [B,H,T,D]
__device__ __half g_xh [M_*E_],  g_xl [M_*E_];
__device__ __half g_yh [M_*E_],  g_yl [M_*E_];
__device__ __half g_h4h[M_*4*E_],g_h4l[M_*4*E_];
// weights: hi only (encoder, 2-term)
__device__ __half g_attnTh[L_*3*E_*E_];
__device__ __half g_projTh[L_*E_*E_];
__device__ __half g_fcTh  [L_*4*E_*E_];
__device__ __half g_fcpTh [L_*4*E_*E_];
// lm_head: hi+lo (3-term)
__device__ __half g_wteh  [VP_*E_], g_wtel[VP_*E_];

// ---------------- helpers ----------------
__device__ __forceinline__ uint32_t cvta_smem(const void* p){
    uint32_t a;
    asm("{.reg .u64 t; cvta.to.shared.u64 t, %1; cvt.u32.u64 %0, t;}" : "=r"(a) : "l"(p));
    return a;
}
__device__ __forceinline__ void ldsm4(uint32_t* r, uint32_t addr){
    asm volatile("ldmatrix.sync.aligned.m8n8.x4.shared.b16 {%0,%1,%2,%3}, [%4];"
        : "=r"(r[0]),"=r"(r[1]),"=r"(r[2]),"=r"(r[3]) : "r"(addr));
}
__device__ __forceinline__ void ldsm4t(uint32_t* r, uint32_t addr){
    asm volatile("ldmatrix.sync.aligned.m8n8.x4.trans.shared.b16 {%0,%1,%2,%3}, [%4];"
        : "=r"(r[0]),"=r"(r[1]),"=r"(r[2]),"=r"(r[3]) : "r"(addr));
}
__device__ __forceinline__ void mma16816(float* d, const uint32_t* a, const uint32_t* b){
    asm volatile("mma.sync.aligned.m16n8k16.row.col.f32.f16.f16.f32 "
        "{%0,%1,%2,%3}, {%4,%5,%6,%7}, {%8,%9}, {%0,%1,%2,%3};"
        : "+f"(d[0]),"+f"(d[1]),"+f"(d[2]),"+f"(d[3])
        : "r"(a[0]),"r"(a[1]),"r"(a[2]),"r"(a[3]), "r"(b[0]),"r"(b[1]));
}
__device__ __forceinline__ void cpa16(uint32_t s, const void* g){
    asm volatile("cp.async.cg.shared.global [%0], [%1], 16;" :: "r"(s), "l"(g));
}
__device__ __forceinline__ float gelu_f(float v){
    return 0.5f * v * (1.0f + erff(v * 0.70710678118654752f));
}
__device__ __forceinline__ uint32_t packh(float a, float b){
    __half2 t = __floats2half2_rn(a, b);
    return *reinterpret_cast<uint32_t*>(&t);
}
__device__ __forceinline__ float hhi(float a){
    return __half2float(__float2half_rn(a));
}
__device__ __forceinline__ void split_h(float v, __half& h, __half& l){
    h = __float2half_rn(v);
    l = __float2half_rn(v - __half2float(h));
}

// ------ fp16-split mma.sync GEMM: 128x128x32, 3-stage single-sync ring -------
// A rows 144B: [32 h hi | 32 h lo | pad16]. B rows: B3 ? 144B (hi|lo) : 80B (hi).
#define GROWB 144
#define GOPB  18432

template<int EPI, int OUT, bool B3>
__global__ void __launch_bounds__(256, 2)
gemm_hf(const __half* __restrict__ Ahg, const __half* __restrict__ Alg,
        const __half* __restrict__ Bhg, const __half* __restrict__ Blg,
        const float* __restrict__ bias, const float* __restrict__ res,
        float* __restrict__ C, __half* __restrict__ Ch,
        __half* __restrict__ Cl, int M, int N, int K) {
    constexpr uint32_t BSTR = B3 ? 144u : 80u;
    constexpr uint32_t BREG = B3 ? 18432u : 10240u;
    constexpr uint32_t GSTG = GOPB + BREG;
    extern __shared__ char smraw[];
    const uint32_t sb = cvta_smem(smraw);
    const int tid = threadIdx.x;
    const int lane = tid & 31, wid = tid >> 5;
    const int wm = wid & 3, wn = wid >> 2;
    const int m0 = blockIdx.x * 128, n0 = blockIdx.y * 128;
    const int nkb = K >> 5;

    float acc[2][8][4];
    #pragma unroll
    for (int i = 0; i < 2; i++)
        #pragma unroll
        for (int j = 0; j < 8; j++)
            #pragma unroll
            for (int t = 0; t < 4; t++) acc[i][j][t] = 0.f;

    auto load_stage = [&](int kb){
        const uint32_t st = sb + (uint32_t)(kb % 3) * GSTG;
        const int k0 = kb * 32;
        if (B3) {
            #pragma unroll
            for (int i = 0; i < 8; i++) {
                int j = tid + (i << 8);
                int op = j >> 10, row = (j >> 3) & 127, ch = j & 7;
                const __half* src =
                    (op ? (ch < 4 ? Bhg : Blg) : (ch < 4 ? Ahg : Alg))
                    + (size_t)((op ? n0 : m0) + row) * K + k0 + (ch & 3) * 8;
                cpa16(st + (uint32_t)(op*GOPB + row*GROWB + ch*16), src);
            }
        } else {
            #pragma unroll
            for (int i = 0; i < 6; i++) {
                int j = tid + (i << 8);
                if (j < 1024) {
                    int row = j >> 3, ch = j & 7;
                    const __half* src = (ch < 4 ? Ahg : Alg)
                        + (size_t)(m0 + row) * K + k0 + (ch & 3) * 8;
                    cpa16(st + (uint32_t)(row*GROWB + ch*16), src);
                } else {
                    int jj = j - 1024;
                    int row = jj >> 2, ch = jj & 3;
                    const __half* src = Bhg + (size_t)(n0 + row) * K + k0 + ch * 8;
                    cpa16(st + GOPB + (uint32_t)(row*80 + ch*16), src);
                }
            }
        }
    };

    load_stage(0);
    asm volatile("cp.async.commit_group;" ::: "memory");
    load_stage(1);
    asm volatile("cp.async.commit_group;" ::: "memory");

    for (int kb = 0; kb < nkb; kb++) {
        asm volatile("cp.async.wait_group 1;" ::: "memory");
        __syncthreads();
        if (kb + 2 < nkb) load_stage(kb + 2);
        asm volatile("cp.async.commit_group;" ::: "memory");

        const uint32_t st = sb + (uint32_t)(kb % 3) * GSTG;
        const uint32_t Ab = st, Bb = st + GOPB;
        #pragma unroll
        for (int ks = 0; ks < 2; ks++) {
            uint32_t ah[2][4], al[2][4], bhf[8][2], blf[8][2];
            #pragma unroll
            for (int mi = 0; mi < 2; mi++) {
                int row = wm*32 + mi*16 + (lane & 15);
                int ch  = 2*ks + (lane >> 4);
                uint32_t off = (uint32_t)(row*GROWB + ch*16);
                ldsm4(ah[mi], Ab + off);
                ldsm4(al[mi], Ab + off + 64);
            }
            #pragma unroll
            for (int p2 = 0; p2 < 4; p2++) {
                int nr = wn*64 + p2*16 + (lane & 7) + ((lane >> 4) << 3);
                int ch = 2*ks + ((lane >> 3) & 1);
                uint32_t off = (uint32_t)nr*BSTR + (uint32_t)(ch*16);
                uint32_t t[4];
                ldsm4(t, Bb + off);
                bhf[2*p2][0]=t[0]; bhf[2*p2][1]=t[1]; bhf[2*p2+1][0]=t[2]; bhf[2*p2+1][1]=t[3];
                if (B3) {
                    ldsm4(t, Bb + off + 64);
                    blf[2*p2][0]=t[0]; blf[2*p2][1]=t[1]; blf[2*p2+1][0]=t[2]; blf[2*p2+1][1]=t[3];
                }
            }
            #pragma unroll
            for (int mi = 0; mi < 2; mi++)
                #pragma unroll
                for (int nj = 0; nj < 8; nj++) {
                    mma16816(acc[mi][nj], ah[mi], bhf[nj]);
                    mma16816(acc[mi][nj], al[mi], bhf[nj]);
                    if (B3) mma16816(acc[mi][nj], ah[mi], blf[nj]);
                }
        }
    }

    // ---- epilogue ----
    const int mrow = m0 + wm*32 + (lane >> 2);
    const int ncol = n0 + wn*64 + 2*(lane & 3);
    const bool vec_ok = ((N & 1) == 0);
    #pragma unroll
    for (int mi = 0; mi < 2; mi++) {
        #pragma unroll
        for (int nj = 0; nj < 8; nj++) {
            int c = ncol + nj*8;
            #pragma unroll
            for (int h2 = 0; h2 < 2; h2++) {
                int rr = mrow + mi*16 + h2*8;
                float v0 = acc[mi][nj][h2*2], v1 = acc[mi][nj][h2*2+1];
                if (EPI >= 1 && c < N)     v0 += bias[c];
                if (EPI >= 1 && c+1 < N)   v1 += bias[c+1];
                if (EPI == 2) { v0 = gelu_f(v0); v1 = gelu_f(v1); }
                if (OUT == 2) {
                    int which = c / E_, e = c % E_;
                    int hh2 = e >> 6, d = e & 63;
                    int b = rr >> 10, t = rr & (T_-1);
                    size_t off = (((size_t)(b*H_ + hh2)*T_) + t)*D_ + d;
                    if (which == 0) {
                        v0 *= 0.125f; v1 *= 0.125f;
                        __half h0, l0, h1, l1;
                        split_h(v0, h0, l0); split_h(v1, h1, l1);
                        __half2 hv; hv.x = h0; hv.y = h1;
                        __half2 lv; lv.x = l0; lv.y = l1;
                        *(__half2*)(Ch + off)          = hv;
                        *(__half2*)(Ch + BHTD_ + off)  = lv;
                    } else {
                        __half2 hv = __floats2half2_rn(v0, v1);
                        *(__half2*)(Ch + (size_t)(which+1)*BHTD_ + off) = hv;
                    }
                } else if (OUT == 1) {
                    if (EPI == 3) {
                        v0 += res[(size_t)rr*N + c]; v1 += res[(size_t)rr*N + c + 1];
                    }
                    __half h0, l0, h1, l1;
                    split_h(v0, h0, l0); split_h(v1, h1, l1);
                    __half2 hv; hv.x = h0; hv.y = h1;
                    __half2 lv; lv.x = l0; lv.y = l1;
                    *(__half2*)(Ch + (size_t)rr*N + c) = hv;
                    *(__half2*)(Cl + (size_t)rr*N + c) = lv;
                } else {
                    if (vec_ok && c + 1 < N) {
                        if (EPI == 3) {
                            v0 += res[(size_t)rr*N + c]; v1 += res[(size_t)rr*N + c + 1];
                        }
                        float2 o; o.x = v0; o.y = v1;
                        *(float2*)(C + (size_t)rr*N + c) = o;
                    } else {
                        if (c < N) {
                            if (EPI == 3) v0 += res[(size_t)rr*N + c];
                            C[(size_t)rr*N + c] = v0;
                        }
                        if (c + 1 < N) {
                            if (EPI == 3) v1 += res[(size_t)rr*N + c + 1];
                            C[(size_t)rr*N + c + 1] = v1;
                        }
                    }
                }
            }
        }
    }
}

#define GSMEM2 (3*(GOPB + 10240))   // 86016
#define GSMEM3 (3*(GOPB + 18432))   // 110592

// ------ fp16 flash attention: 64-q-row CTAs, 2-term (Q,P split; K,V hi) ------
#define FROW 144
#define FA2_SMEM 18432

__global__ void __launch_bounds__(128)
flash2_k(const __half* __restrict__ qkv4,
         __half* __restrict__ yh, __half* __restrict__ yl) {
    extern __shared__ char fsm[];
    const uint32_t sb = cvta_smem(fsm);
    const int tid = threadIdx.x, lane = tid & 31, w = tid >> 5;   // w 0..3
    const int q0 = blockIdx.x * 64, bh = blockIdx.y;
    const __half *qh_g = qkv4,            *ql_g = qkv4 + BHTD_;
    const __half *kh_g = qkv4 + 2*BHTD_,  *vh_g = qkv4 + 3*BHTD_;
    const size_t hb = (size_t)bh * T_ * D_;

    // ---- stage Q (64 x 64) hi/lo, pull A-frags ----
    #pragma unroll
    for (int i = 0; i < 8; i++) {
        int j = tid + i*128;                 // 0..1023
        int arr = j >> 9;                    // 0 hi, 1 lo
        int row = (j >> 3) & 63, ch = j & 7;
        const __half* src = (arr ? ql_g : qh_g) + hb + (size_t)(q0+row)*D_ + ch*8;
        cpa16(sb + (uint32_t)arr*9216u + (uint32_t)(row*FROW + ch*16), src);
    }
    asm volatile("cp.async.commit_group;" ::: "memory");
    asm volatile("cp.async.wait_group 0;" ::: "memory");
    __syncthreads();

    uint32_t qah[4][4], qal[4][4];
    {
        uint32_t base = sb + (uint32_t)((w*16 + (lane&15))*FROW) + (uint32_t)((lane>>4)*16);
        #pragma unroll
        for (int kc = 0; kc < 4; kc++) {
            ldsm4(qah[kc], base + kc*32);
            ldsm4(qal[kc], base + 9216u + kc*32);
        }
    }
    __syncthreads();

    const uint32_t Kh = sb, Vh = sb + 9216u;
    float m0 = -1e30f, m1 = -1e30f, l0 = 0.f, l1 = 0.f;
    float acc[8][4];
    #pragma unroll
    for (int nj = 0; nj < 8; nj++)
        #pragma unroll
        for (int t = 0; t < 4; t++) acc[nj][t] = 0.f;

    const int nkt = blockIdx.x + 1;
    for (int kt = 0; kt < nkt; kt++) {
        __syncthreads();
        #pragma unroll
        for (int i = 0; i < 8; i++) {
            int j = tid + i*128;             // 0..1023
            int arr = j >> 9;                // 0 K, 1 V
            int row = (j >> 3) & 63, ch = j & 7;
            const __half* src = (arr ? vh_g : kh_g)
                + hb + (size_t)(kt*64+row)*D_ + ch*8;
            cpa16(sb + (uint32_t)arr*9216u + (uint32_t)(row*FROW + ch*16), src);
        }
        asm volatile("cp.async.commit_group;" ::: "memory");
        asm volatile("cp.async.wait_group 0;" ::: "memory");
        __syncthreads();

        float f[8][4];
        #pragma unroll
        for (int nj = 0; nj < 8; nj++)
            #pragma unroll
            for (int t = 0; t < 4; t++) f[nj][t] = 0.f;
        #pragma unroll
        for (int kc = 0; kc < 4; kc++) {
            uint32_t koff = (uint32_t)(((lane&7) + ((lane>>4)<<3))*FROW)
                          + (uint32_t)(kc*32 + (((lane>>3)&1)<<4));
            #pragma unroll
            for (int ng = 0; ng < 4; ng++) {
                uint32_t th[4];
                ldsm4(th, Kh + (uint32_t)(ng*16*FROW) + koff);
                mma16816(f[2*ng],   qah[kc], th);
                mma16816(f[2*ng],   qal[kc], th);
                mma16816(f[2*ng+1], qah[kc], th+2);
                mma16816(f[2*ng+1], qal[kc], th+2);
            }
        }
        if (kt*64 + 63 > q0 + w*16) {
            int qg0 = q0 + w*16 + (lane>>2), qg1 = qg0 + 8;
            #pragma unroll
            for (int nj = 0; nj < 8; nj++) {
                int cc0 = kt*64 + nj*8 + 2*(lane&3), cc1 = cc0 + 1;
                if (cc0 > qg0) f[nj][0] = -1e30f;
                if (cc1 > qg0) f[nj][1] = -1e30f;
                if (cc0 > qg1) f[nj][2] = -1e30f;
                if (cc1 > qg1) f[nj][3] = -1e30f;
            }
        }
        float mx0 = -1e30f, mx1 = -1e30f;
        #pragma unroll
        for (int nj = 0; nj < 8; nj++) {
            mx0 = fmaxf(mx0, fmaxf(f[nj][0], f[nj][1]));
            mx1 = fmaxf(mx1, fmaxf(f[nj][2], f[nj][3]));
        }
        mx0 = fmaxf(mx0, __shfl_xor_sync(0xffffffffu, mx0, 1));
        mx0 = fmaxf(mx0, __shfl_xor_sync(0xffffffffu, mx0, 2));
        mx1 = fmaxf(mx1, __shfl_xor_sync(0xffffffffu, mx1, 1));
        mx1 = fmaxf(mx1, __shfl_xor_sync(0xffffffffu, mx1, 2));
        float nm0 = fmaxf(m0, mx0), nm1 = fmaxf(m1, mx1);
        float al0 = __expf(m0 - nm0), al1 = __expf(m1 - nm1);
        m0 = nm0; m1 = nm1;

        float s0 = 0.f, s1 = 0.f;
        uint32_t ph[4][4], pl[4][4];
        #pragma unroll
        for (int kc = 0; kc < 4; kc++) {
            float e0 = __expf(f[2*kc][0]   - nm0), e1 = __expf(f[2*kc][1]   - nm0);
            float e2 = __expf(f[2*kc][2]   - nm1), e3 = __expf(f[2*kc][3]   - nm1);
            float g0 = __expf(f[2*kc+1][0] - nm0), g1 = __expf(f[2*kc+1][1] - nm0);
            float g2 = __expf(f[2*kc+1][2] - nm1), g3 = __expf(f[2*kc+1][3] - nm1);
            s0 += e0 + e1 + g0 + g1;
            s1 += e2 + e3 + g2 + g3;
            ph[kc][0] = packh(e0, e1);  pl[kc][0] = packh(e0-hhi(e0), e1-hhi(e1));
            ph[kc][1] = packh(e2, e3);  pl[kc][1] = packh(e2-hhi(e2), e3-hhi(e3));
            ph[kc][2] = packh(g0, g1);  pl[kc][2] = packh(g0-hhi(g0), g1-hhi(g1));
            ph[kc][3] = packh(g2, g3);  pl[kc][3] = packh(g2-hhi(g2), g3-hhi(g3));
        }
        s0 += __shfl_xor_sync(0xffffffffu, s0, 1);
        s0 += __shfl_xor_sync(0xffffffffu, s0, 2);
        s1 += __shfl_xor_sync(0xffffffffu, s1, 1);
        s1 += __shfl_xor_sync(0xffffffffu, s1, 2);
        l0 = l0 * al0 + s0;
        l1 = l1 * al1 + s1;
        #pragma unroll
        for (int nj = 0; nj < 8; nj++) {
            acc[nj][0] *= al0; acc[nj][1] *= al0;
            acc[nj][2] *= al1; acc[nj][3] *= al1;
        }
        #pragma unroll
        for (int kc = 0; kc < 4; kc++) {
            uint32_t voff = (uint32_t)((kc*16 + (lane&7) + (((lane>>3)&1)<<3))*FROW)
                          + (uint32_t)((lane>>4)*16);
            #pragma unroll
            for (int ng = 0; ng < 4; ng++) {
                uint32_t th[4];
                ldsm4t(th, Vh + voff + (uint32_t)(ng*32));
                mma16816(acc[2*ng],   ph[kc], th);
                mma16816(acc[2*ng],   pl[kc], th);
                mma16816(acc[2*ng+1], ph[kc], th+2);
                mma16816(acc[2*ng+1], pl[kc], th+2);
            }
        }
    }

    const float inv0 = 1.f / l0, inv1 = 1.f / l1;
    const int b = bh / H_, h = bh % H_;
    const int r0g = q0 + w*16 + (lane >> 2);
    const size_t base0 = (size_t)(b*T_ + r0g)*E_ + h*64 + 2*(lane & 3);
    const size_t base1 = base0 + (size_t)8*E_;
    #pragma unroll
    for (int nj = 0; nj < 8; nj++) {
        float o0 = acc[nj][0]*inv0, o1 = acc[nj][1]*inv0;
        float o2 = acc[nj][2]*inv1, o3 = acc[nj][3]*inv1;
        __half h0,lo0,h1,lo1,h2,lo2,h3,lo3;
        split_h(o0,h0,lo0); split_h(o1,h1,lo1);
        split_h(o2,h2,lo2); split_h(o3,h3,lo3);
        __half2 a; a.x=h0; a.y=h1;
        __half2 c; c.x=lo0; c.y=lo1;
        __half2 d2; d2.x=h2; d2.y=h3;
        __half2 e2; e2.x=lo2; e2.y=lo3;
        *(__half2*)(yh + base0 + nj*8) = a;
        *(__half2*)(yl + base0 + nj*8) = c;
        *(__half2*)(yh + base1 + nj*8) = d2;
        *(__half2*)(yl + base1 + nj*8) = e2;
    }
}

// ---------------- weight transpose (hi only): W[K,N] -> WTh[N,K] fp16 --------
__global__ void transpose_split_k(const float* __restrict__ W,
                                  __half* __restrict__ WTh,
                                  int K, int N) {
    __shared__ float t[32][33];
    const size_t lstride = (size_t)K * N;
    const float* Wl = W + lstride * blockIdx.z;
    __half* Hh = WTh + lstride * blockIdx.z;
    int n0 = blockIdx.x * 32, k0 = blockIdx.y * 32;
    int x = threadIdx.x, y = threadIdx.y;
    #pragma unroll
    for (int i = 0; i < 32; i += 8)
        t[y + i][x] = Wl[(size_t)(k0 + y + i) * N + n0 + x];
    __syncthreads();
    #pragma unroll
    for (int i = 0; i < 32; i += 8)
        Hh[(size_t)(n0 + y + i) * K + k0 + x] = __float2half_rn(t[x][y + i]);
}

// ---------------- wte pad+split (hi/lo fp16) ----------------
__global__ void wte_split_k(const float* __restrict__ wte,
                            __half* __restrict__ wh, __half* __restrict__ wl) {
    int i = blockIdx.x * blockDim.x + threadIdx.x;
    if (i >= VP_*E_) return;
    int row = i / E_;
    float v = (row < V_) ? wte[i] : 0.f;
    __half h, l; split_h(v, h, l);
    wh[i] = h; wl[i] = l;
}

// ---------------- embedding ----------------
__global__ void embed_k(const int* __restrict__ idx, const float* __restrict__ wte,
                        const float* __restrict__ wpe, float* __restrict__ x) {
    int i = blockIdx.x * blockDim.x + threadIdx.x;
    if (i >= M_*E_) return;
    int row = i / E_, e = i % E_;
    int t = row & (T_-1);
    x[i] = wte[(size_t)idx[row]*E_ + e] + wpe[t*E_ + e];
}

// ---------------- layernorm: 1 warp / row -> fp16 hi/lo ----------------
__global__ void __launch_bounds__(256)
ln_k(const float* __restrict__ x, const float* __restrict__ g,
     const float* __restrict__ b,
     __half* __restrict__ oh, __half* __restrict__ ol) {
    const int lane = threadIdx.x & 31;
    const int row = blockIdx.x * 8 + (threadIdx.x >> 5);
    const float* xr = x + (size_t)row*E_;
    float4 v4[6];
    float a = 0.f, q = 0.f;
    #pragma unroll
    for (int i = 0; i < 6; i++) {
        v4[i] = *(const float4*)(xr + (i*32 + lane)*4);
        a += v4[i].x + v4[i].y + v4[i].z + v4[i].w;
        q += v4[i].x*v4[i].x + v4[i].y*v4[i].y + v4[i].z*v4[i].z + v4[i].w*v4[i].w;
    }
    #pragma unroll
    for (int off = 16; off > 0; off >>= 1) {
        a += __shfl_xor_sync(0xffffffffu, a, off);
        q += __shfl_xor_sync(0xffffffffu, q, off);
    }
    float mu  = a * (1.f/E_);
    float var = q * (1.f/E_) - mu*mu;
    float inv = rsqrtf(var + 1e-5f);
    #pragma unroll
    for (int i = 0; i < 6; i++) {
        int e = (i*32 + lane)*4;
        float o0 = (v4[i].x - mu)*inv*g[e+0] + b[e+0];
        float o1 = (v4[i].y - mu)*inv*g[e+1] + b[e+1];
        float o2 = (v4[i].z - mu)*inv*g[e+2] + b[e+2];
        float o3 = (v4[i].w - mu)*inv*g[e+3] + b[e+3];
        __half h0,l0,h1,l1,h2,l2,h3,l3;
        split_h(o0,h0,l0); split_h(o1,h1,l1);
        split_h(o2,h2,l2); split_h(o3,h3,l3);
        __half2 hv0; hv0.x=h0; hv0.y=h1;
        __half2 hv1; hv1.x=h2; hv1.y=h3;
        __half2 lv0; lv0.x=l0; lv0.y=l1;
        __half2 lv1; lv1.x=l2; lv1.y=l3;
        *(__half2*)(oh + (size_t)row*E_ + e)     = hv0;
        *(__half2*)(oh + (size_t)row*E_ + e + 2) = hv1;
        *(__half2*)(ol + (size_t)row*E_ + e)     = lv0;
        *(__half2*)(ol + (size_t)row*E_ + e + 2) = lv1;
    }
}

// ---------------- launch ----------------
extern "C" void kernel_launch(void* const* d_in, const int* in_sizes, int n_in,
                              void* d_out, int out_size) {
    const int*   idx    = (const int*)  d_in[0];
    const float* wte    = (const float*)d_in[1];
    const float* wpe    = (const float*)d_in[2];
    const float* ln1_g  = (const float*)d_in[3];
    const float* ln1_b  = (const float*)d_in[4];
    const float* attn_w = (const float*)d_in[5];
    const float* attn_b = (const float*)d_in[6];
    const float* proj_w = (const float*)d_in[7];
    const float* proj_b = (const float*)d_in[8];
    const float* ln2_g  = (const float*)d_in[9];
    const float* ln2_b  = (const float*)d_in[10];
    const float* fc_w   = (const float*)d_in[11];
    const float* fc_b   = (const float*)d_in[12];
    const float* fcp_w  = (const float*)d_in[13];
    const float* fcp_b  = (const float*)d_in[14];
    const float* lnf_g  = (const float*)d_in[15];
    const float* lnf_b  = (const float*)d_in[16];
    float* out = (float*)d_out;

    float *x;
    __half *qkv4, *xh, *xl, *yh, *yl, *h4h, *h4l;
    __half *attnTh, *projTh, *fcTh, *fcpTh, *wteh, *wtel;
    cudaGetSymbolAddress((void**)&x,    g_x);
    cudaGetSymbolAddress((void**)&qkv4, g_qkv4);
    cudaGetSymbolAddress((void**)&xh,   g_xh);   cudaGetSymbolAddress((void**)&xl,  g_xl);
    cudaGetSymbolAddress((void**)&yh,   g_yh);   cudaGetSymbolAddress((void**)&yl,  g_yl);
    cudaGetSymbolAddress((void**)&h4h,  g_h4h);  cudaGetSymbolAddress((void**)&h4l, g_h4l);
    cudaGetSymbolAddress((void**)&attnTh, g_attnTh);
    cudaGetSymbolAddress((void**)&projTh, g_projTh);
    cudaGetSymbolAddress((void**)&fcTh,   g_fcTh);
    cudaGetSymbolAddress((void**)&fcpTh,  g_fcpTh);
    cudaGetSymbolAddress((void**)&wteh,   g_wteh);
    cudaGetSymbolAddress((void**)&wtel,   g_wtel);

    cudaFuncSetAttribute(gemm_hf<1,2,false>, cudaFuncAttributeMaxDynamicSharedMemorySize, GSMEM2);
    cudaFuncSetAttribute(gemm_hf<3,0,false>, cudaFuncAttributeMaxDynamicSharedMemorySize, GSMEM2);
    cudaFuncSetAttribute(gemm_hf<2,1,false>, cudaFuncAttributeMaxDynamicSharedMemorySize, GSMEM2);
    cudaFuncSetAttribute(gemm_hf<0,0,true>,  cudaFuncAttributeMaxDynamicSharedMemorySize, GSMEM3);
    cudaFuncSetAttribute(flash2_k,           cudaFuncAttributeMaxDynamicSharedMemorySize, FA2_SMEM);

    dim3 tb(32, 8);
    transpose_split_k<<<dim3(3*E_/32, E_/32, L_), tb>>>(attn_w, attnTh, E_, 3*E_);
    transpose_split_k<<<dim3(E_/32,   E_/32, L_), tb>>>(proj_w, projTh, E_, E_);
    transpose_split_k<<<dim3(4*E_/32, E_/32, L_), tb>>>(fc_w,   fcTh,   E_, 4*E_);
    transpose_split_k<<<dim3(E_/32, 4*E_/32, L_), tb>>>(fcp_w,  fcpTh,  4*E_, E_);
    wte_split_k<<<(VP_*E_ + 255)/256, 256>>>(wte, wteh, wtel);

    embed_k<<<(M_*E_ + 255)/256, 256>>>(idx, wte, wpe, x);

    for (int l = 0; l < L_; l++) {
        ln_k<<<M_/8, 256>>>(x, ln1_g + l*E_, ln1_b + l*E_, xh, xl);
        gemm_hf<1,2,false><<<dim3(M_/128, 3*E_/128), 256, GSMEM2>>>(
            xh, xl, attnTh + (size_t)l*3*E_*E_, nullptr,
            attn_b + l*3*E_, nullptr, nullptr, qkv4, nullptr, M_, 3*E_, E_);
        flash2_k<<<dim3(T_/64, B_*H_), 128, FA2_SMEM>>>(qkv4, yh, yl);
        gemm_hf<3,0,false><<<dim3(M_/128, E_/128), 256, GSMEM2>>>(
            yh, yl, projTh + (size_t)l*E_*E_, nullptr,
            proj_b + l*E_, x, x, nullptr, nullptr, M_, E_, E_);
        ln_k<<<M_/8, 256>>>(x, ln2_g + l*E_, ln2_b + l*E_, xh, xl);
        gemm_hf<2,1,false><<<dim3(M_/128, 4*E_/128), 256, GSMEM2>>>(
            xh, xl, fcTh + (size_t)l*4*E_*E_, nullptr,
            fc_b + l*4*E_, nullptr, nullptr, h4h, h4l, M_, 4*E_, E_);
        gemm_hf<3,0,false><<<dim3(M_/128, E_/128), 256, GSMEM2>>>(
            h4h, h4l, fcpTh + (size_t)l*4*E_*E_, nullptr,
            fcp_b + l*E_, x, x, nullptr, nullptr, M_, E_, 4*E_);
    }

    ln_k<<<M_/8, 256>>>(x, lnf_g, lnf_b, xh, xl);
    gemm_hf<0,0,true><<<dim3(M_/128, VP_/128), 256, GSMEM3>>>(
        xh, xl, wteh, wtel, nullptr, nullptr, out, nullptr, nullptr, M_, V_, E_);
}

// round 14
// speedup vs baseline: 1.4074x; 1.0713x over previous
#include <cuda_runtime.h>
#include <cuda_fp16.h>
#include <math.h>
#include <stdint.h>

#define E_ 768
#define L_ 12
#define H_ 12
#define D_ 64
#define B_ 2
#define T_ 1024
#define V_ 50257
#define VP_ 50304
#define M_ (B_*T_)
#define BHTD_ (B_*H_*T_*D_)

// ---------------- scratch ----------------
__device__ float g_x   [M_*E_];
__device__ __half g_qkv4[4*BHTD_];           // qh,ql,kh,vh each [B,H,T,D]
__device__ __half g_xh [M_*E_],  g_xl [M_*E_];
__device__ __half g_yh [M_*E_],  g_yl [M_*E_];
__device__ __half g_h4h[M_*4*E_],g_h4l[M_*4*E_];
// weights: hi only (2-term everywhere now)
__device__ __half g_attnTh[L_*3*E_*E_];
__device__ __half g_projTh[L_*E_*E_];
__device__ __half g_fcTh  [L_*4*E_*E_];
__device__ __half g_fcpTh [L_*4*E_*E_];
__device__ __half g_wteh  [VP_*E_];

// ---------------- helpers ----------------
__device__ __forceinline__ uint32_t cvta_smem(const void* p){
    uint32_t a;
    asm("{.reg .u64 t; cvta.to.shared.u64 t, %1; cvt.u32.u64 %0, t;}" : "=r"(a) : "l"(p));
    return a;
}
__device__ __forceinline__ void ldsm4(uint32_t* r, uint32_t addr){
    asm volatile("ldmatrix.sync.aligned.m8n8.x4.shared.b16 {%0,%1,%2,%3}, [%4];"
        : "=r"(r[0]),"=r"(r[1]),"=r"(r[2]),"=r"(r[3]) : "r"(addr));
}
__device__ __forceinline__ void ldsm4t(uint32_t* r, uint32_t addr){
    asm volatile("ldmatrix.sync.aligned.m8n8.x4.trans.shared.b16 {%0,%1,%2,%3}, [%4];"
        : "=r"(r[0]),"=r"(r[1]),"=r"(r[2]),"=r"(r[3]) : "r"(addr));
}
__device__ __forceinline__ void mma16816(float* d, const uint32_t* a, const uint32_t* b){
    asm volatile("mma.sync.aligned.m16n8k16.row.col.f32.f16.f16.f32 "
        "{%0,%1,%2,%3}, {%4,%5,%6,%7}, {%8,%9}, {%0,%1,%2,%3};"
        : "+f"(d[0]),"+f"(d[1]),"+f"(d[2]),"+f"(d[3])
        : "r"(a[0]),"r"(a[1]),"r"(a[2]),"r"(a[3]), "r"(b[0]),"r"(b[1]));
}
__device__ __forceinline__ void cpa16(uint32_t s, const void* g){
    asm volatile("cp.async.cg.shared.global [%0], [%1], 16;" :: "r"(s), "l"(g));
}
__device__ __forceinline__ float gelu_f(float v){
    return 0.5f * v * (1.0f + erff(v * 0.70710678118654752f));
}
__device__ __forceinline__ uint32_t packh(float a, float b){
    __half2 t = __floats2half2_rn(a, b);
    return *reinterpret_cast<uint32_t*>(&t);
}
__device__ __forceinline__ float hhi(float a){
    return __half2float(__float2half_rn(a));
}
__device__ __forceinline__ void split_h(float v, __half& h, __half& l){
    h = __float2half_rn(v);
    l = __float2half_rn(v - __half2float(h));
}

// ------ fp16 2-term mma.sync GEMM: 128x128x32, 3-stage single-sync ring ------
// A rows 144B: [32 h hi | 32 h lo | pad16]. B rows 80B: [32 h hi | pad16].
#define GROWB 144
#define GOPB  18432
#define BSTR  80u
#define GSTG  (GOPB + 10240)
#define GSMEM2 (3*GSTG)             // 86016

// EPI: 0 none, 1 +bias, 2 gelu(+bias), 3 +bias+residual
// OUT: 0 fp32 C, 1 fp16 hi/lo (Ch,Cl), 2 qkv head-scatter into Ch (4 arrays)
template<int EPI, int OUT>
__global__ void __launch_bounds__(256, 2)
gemm_hf(const __half* __restrict__ Ahg, const __half* __restrict__ Alg,
        const __half* __restrict__ Bhg,
        const float* __restrict__ bias, const float* __restrict__ res,
        float* __restrict__ C, __half* __restrict__ Ch,
        __half* __restrict__ Cl, int M, int N, int K) {
    extern __shared__ char smraw[];
    const uint32_t sb = cvta_smem(smraw);
    const int tid = threadIdx.x;
    const int lane = tid & 31, wid = tid >> 5;
    const int wm = wid & 3, wn = wid >> 2;
    const int m0 = blockIdx.x * 128, n0 = blockIdx.y * 128;
    const int nkb = K >> 5;

    float acc[2][8][4];
    #pragma unroll
    for (int i = 0; i < 2; i++)
        #pragma unroll
        for (int j = 0; j < 8; j++)
            #pragma unroll
            for (int t = 0; t < 4; t++) acc[i][j][t] = 0.f;

    auto load_stage = [&](int kb){
        const uint32_t st = sb + (uint32_t)(kb % 3) * GSTG;
        const int k0 = kb * 32;
        #pragma unroll
        for (int i = 0; i < 6; i++) {
            int j = tid + (i << 8);
            if (j < 1024) {
                int row = j >> 3, ch = j & 7;
                const __half* src = (ch < 4 ? Ahg : Alg)
                    + (size_t)(m0 + row) * K + k0 + (ch & 3) * 8;
                cpa16(st + (uint32_t)(row*GROWB + ch*16), src);
            } else {
                int jj = j - 1024;
                int row = jj >> 2, ch = jj & 3;
                const __half* src = Bhg + (size_t)(n0 + row) * K + k0 + ch * 8;
                cpa16(st + GOPB + (uint32_t)(row*80 + ch*16), src);
            }
        }
    };

    load_stage(0);
    asm volatile("cp.async.commit_group;" ::: "memory");
    load_stage(1);
    asm volatile("cp.async.commit_group;" ::: "memory");

    for (int kb = 0; kb < nkb; kb++) {
        asm volatile("cp.async.wait_group 1;" ::: "memory");
        __syncthreads();
        if (kb + 2 < nkb) load_stage(kb + 2);
        asm volatile("cp.async.commit_group;" ::: "memory");

        const uint32_t st = sb + (uint32_t)(kb % 3) * GSTG;
        const uint32_t Ab = st, Bb = st + GOPB;
        #pragma unroll
        for (int ks = 0; ks < 2; ks++) {
            uint32_t ah[2][4], al[2][4], bhf[8][2];
            #pragma unroll
            for (int mi = 0; mi < 2; mi++) {
                int row = wm*32 + mi*16 + (lane & 15);
                int ch  = 2*ks + (lane >> 4);
                uint32_t off = (uint32_t)(row*GROWB + ch*16);
                ldsm4(ah[mi], Ab + off);
                ldsm4(al[mi], Ab + off + 64);
            }
            #pragma unroll
            for (int p2 = 0; p2 < 4; p2++) {
                int nr = wn*64 + p2*16 + (lane & 7) + ((lane >> 4) << 3);
                int ch = 2*ks + ((lane >> 3) & 1);
                uint32_t off = (uint32_t)nr*BSTR + (uint32_t)(ch*16);
                uint32_t t[4];
                ldsm4(t, Bb + off);
                bhf[2*p2][0]=t[0]; bhf[2*p2][1]=t[1]; bhf[2*p2+1][0]=t[2]; bhf[2*p2+1][1]=t[3];
            }
            #pragma unroll
            for (int mi = 0; mi < 2; mi++)
                #pragma unroll
                for (int nj = 0; nj < 8; nj++) {
                    mma16816(acc[mi][nj], ah[mi], bhf[nj]);
                    mma16816(acc[mi][nj], al[mi], bhf[nj]);
                }
        }
    }

    // ---- epilogue ----
    const int mrow = m0 + wm*32 + (lane >> 2);
    const int ncol = n0 + wn*64 + 2*(lane & 3);
    const bool vec_ok = ((N & 1) == 0);
    #pragma unroll
    for (int mi = 0; mi < 2; mi++) {
        #pragma unroll
        for (int nj = 0; nj < 8; nj++) {
            int c = ncol + nj*8;
            #pragma unroll
            for (int h2 = 0; h2 < 2; h2++) {
                int rr = mrow + mi*16 + h2*8;
                float v0 = acc[mi][nj][h2*2], v1 = acc[mi][nj][h2*2+1];
                if (EPI >= 1 && c < N)     v0 += bias[c];
                if (EPI >= 1 && c+1 < N)   v1 += bias[c+1];
                if (EPI == 2) { v0 = gelu_f(v0); v1 = gelu_f(v1); }
                if (OUT == 2) {
                    int which = c / E_, e = c % E_;
                    int hh2 = e >> 6, d = e & 63;
                    int b = rr >> 10, t = rr & (T_-1);
                    size_t off = (((size_t)(b*H_ + hh2)*T_) + t)*D_ + d;
                    if (which == 0) {
                        v0 *= 0.125f; v1 *= 0.125f;
                        __half h0, l0, h1, l1;
                        split_h(v0, h0, l0); split_h(v1, h1, l1);
                        __half2 hv; hv.x = h0; hv.y = h1;
                        __half2 lv; lv.x = l0; lv.y = l1;
                        *(__half2*)(Ch + off)          = hv;
                        *(__half2*)(Ch + BHTD_ + off)  = lv;
                    } else {
                        __half2 hv = __floats2half2_rn(v0, v1);
                        *(__half2*)(Ch + (size_t)(which+1)*BHTD_ + off) = hv;
                    }
                } else if (OUT == 1) {
                    if (EPI == 3) {
                        v0 += res[(size_t)rr*N + c]; v1 += res[(size_t)rr*N + c + 1];
                    }
                    __half h0, l0, h1, l1;
                    split_h(v0, h0, l0); split_h(v1, h1, l1);
                    __half2 hv; hv.x = h0; hv.y = h1;
                    __half2 lv; lv.x = l0; lv.y = l1;
                    *(__half2*)(Ch + (size_t)rr*N + c) = hv;
                    *(__half2*)(Cl + (size_t)rr*N + c) = lv;
                } else {
                    if (vec_ok && c + 1 < N) {
                        if (EPI == 3) {
                            v0 += res[(size_t)rr*N + c]; v1 += res[(size_t)rr*N + c + 1];
                        }
                        float2 o; o.x = v0; o.y = v1;
                        *(float2*)(C + (size_t)rr*N + c) = o;
                    } else {
                        if (c < N) {
                            if (EPI == 3) v0 += res[(size_t)rr*N + c];
                            C[(size_t)rr*N + c] = v0;
                        }
                        if (c + 1 < N) {
                            if (EPI == 3) v1 += res[(size_t)rr*N + c + 1];
                            C[(size_t)rr*N + c + 1] = v1;
                        }
                    }
                }
            }
        }
    }
}

// ------ fp16 flash attention: 64-q-row CTAs, 2-term (Q,P split; K,V hi) ------
#define FROW 144
#define FA2_SMEM 18432

__global__ void __launch_bounds__(128)
flash2_k(const __half* __restrict__ qkv4,
         __half* __restrict__ yh, __half* __restrict__ yl) {
    extern __shared__ char fsm[];
    const uint32_t sb = cvta_smem(fsm);
    const int tid = threadIdx.x, lane = tid & 31, w = tid >> 5;
    const int q0 = blockIdx.x * 64, bh = blockIdx.y;
    const __half *qh_g = qkv4,            *ql_g = qkv4 + BHTD_;
    const __half *kh_g = qkv4 + 2*BHTD_,  *vh_g = qkv4 + 3*BHTD_;
    const size_t hb = (size_t)bh * T_ * D_;

    #pragma unroll
    for (int i = 0; i < 8; i++) {
        int j = tid + i*128;
        int arr = j >> 9;
        int row = (j >> 3) & 63, ch = j & 7;
        const __half* src = (arr ? ql_g : qh_g) + hb + (size_t)(q0+row)*D_ + ch*8;
        cpa16(sb + (uint32_t)arr*9216u + (uint32_t)(row*FROW + ch*16), src);
    }
    asm volatile("cp.async.commit_group;" ::: "memory");
    asm volatile("cp.async.wait_group 0;" ::: "memory");
    __syncthreads();

    uint32_t qah[4][4], qal[4][4];
    {
        uint32_t base = sb + (uint32_t)((w*16 + (lane&15))*FROW) + (uint32_t)((lane>>4)*16);
        #pragma unroll
        for (int kc = 0; kc < 4; kc++) {
            ldsm4(qah[kc], base + kc*32);
            ldsm4(qal[kc], base + 9216u + kc*32);
        }
    }
    __syncthreads();

    const uint32_t Kh = sb, Vh = sb + 9216u;
    float m0 = -1e30f, m1 = -1e30f, l0 = 0.f, l1 = 0.f;
    float acc[8][4];
    #pragma unroll
    for (int nj = 0; nj < 8; nj++)
        #pragma unroll
        for (int t = 0; t < 4; t++) acc[nj][t] = 0.f;

    const int nkt = blockIdx.x + 1;
    for (int kt = 0; kt < nkt; kt++) {
        __syncthreads();
        #pragma unroll
        for (int i = 0; i < 8; i++) {
            int j = tid + i*128;
            int arr = j >> 9;
            int row = (j >> 3) & 63, ch = j & 7;
            const __half* src = (arr ? vh_g : kh_g)
                + hb + (size_t)(kt*64+row)*D_ + ch*8;
            cpa16(sb + (uint32_t)arr*9216u + (uint32_t)(row*FROW + ch*16), src);
        }
        asm volatile("cp.async.commit_group;" ::: "memory");
        asm volatile("cp.async.wait_group 0;" ::: "memory");
        __syncthreads();

        float f[8][4];
        #pragma unroll
        for (int nj = 0; nj < 8; nj++)
            #pragma unroll
            for (int t = 0; t < 4; t++) f[nj][t] = 0.f;
        #pragma unroll
        for (int kc = 0; kc < 4; kc++) {
            uint32_t koff = (uint32_t)(((lane&7) + ((lane>>4)<<3))*FROW)
                          + (uint32_t)(kc*32 + (((lane>>3)&1)<<4));
            #pragma unroll
            for (int ng = 0; ng < 4; ng++) {
                uint32_t th[4];
                ldsm4(th, Kh + (uint32_t)(ng*16*FROW) + koff);
                mma16816(f[2*ng],   qah[kc], th);
                mma16816(f[2*ng],   qal[kc], th);
                mma16816(f[2*ng+1], qah[kc], th+2);
                mma16816(f[2*ng+1], qal[kc], th+2);
            }
        }
        if (kt*64 + 63 > q0 + w*16) {
            int qg0 = q0 + w*16 + (lane>>2), qg1 = qg0 + 8;
            #pragma unroll
            for (int nj = 0; nj < 8; nj++) {
                int cc0 = kt*64 + nj*8 + 2*(lane&3), cc1 = cc0 + 1;
                if (cc0 > qg0) f[nj][0] = -1e30f;
                if (cc1 > qg0) f[nj][1] = -1e30f;
                if (cc0 > qg1) f[nj][2] = -1e30f;
                if (cc1 > qg1) f[nj][3] = -1e30f;
            }
        }
        float mx0 = -1e30f, mx1 = -1e30f;
        #pragma unroll
        for (int nj = 0; nj < 8; nj++) {
            mx0 = fmaxf(mx0, fmaxf(f[nj][0], f[nj][1]));
            mx1 = fmaxf(mx1, fmaxf(f[nj][2], f[nj][3]));
        }
        mx0 = fmaxf(mx0, __shfl_xor_sync(0xffffffffu, mx0, 1));
        mx0 = fmaxf(mx0, __shfl_xor_sync(0xffffffffu, mx0, 2));
        mx1 = fmaxf(mx1, __shfl_xor_sync(0xffffffffu, mx1, 1));
        mx1 = fmaxf(mx1, __shfl_xor_sync(0xffffffffu, mx1, 2));
        float nm0 = fmaxf(m0, mx0), nm1 = fmaxf(m1, mx1);
        float al0 = __expf(m0 - nm0), al1 = __expf(m1 - nm1);
        m0 = nm0; m1 = nm1;

        float s0 = 0.f, s1 = 0.f;
        uint32_t ph[4][4], pl[4][4];
        #pragma unroll
        for (int kc = 0; kc < 4; kc++) {
            float e0 = __expf(f[2*kc][0]   - nm0), e1 = __expf(f[2*kc][1]   - nm0);
            float e2 = __expf(f[2*kc][2]   - nm1), e3 = __expf(f[2*kc][3]   - nm1);
            float g0 = __expf(f[2*kc+1][0] - nm0), g1 = __expf(f[2*kc+1][1] - nm0);
            float g2 = __expf(f[2*kc+1][2] - nm1), g3 = __expf(f[2*kc+1][3] - nm1);
            s0 += e0 + e1 + g0 + g1;
            s1 += e2 + e3 + g2 + g3;
            ph[kc][0] = packh(e0, e1);  pl[kc][0] = packh(e0-hhi(e0), e1-hhi(e1));
            ph[kc][1] = packh(e2, e3);  pl[kc][1] = packh(e2-hhi(e2), e3-hhi(e3));
            ph[kc][2] = packh(g0, g1);  pl[kc][2] = packh(g0-hhi(g0), g1-hhi(g1));
            ph[kc][3] = packh(g2, g3);  pl[kc][3] = packh(g2-hhi(g2), g3-hhi(g3));
        }
        s0 += __shfl_xor_sync(0xffffffffu, s0, 1);
        s0 += __shfl_xor_sync(0xffffffffu, s0, 2);
        s1 += __shfl_xor_sync(0xffffffffu, s1, 1);
        s1 += __shfl_xor_sync(0xffffffffu, s1, 2);
        l0 = l0 * al0 + s0;
        l1 = l1 * al1 + s1;
        #pragma unroll
        for (int nj = 0; nj < 8; nj++) {
            acc[nj][0] *= al0; acc[nj][1] *= al0;
            acc[nj][2] *= al1; acc[nj][3] *= al1;
        }
        #pragma unroll
        for (int kc = 0; kc < 4; kc++) {
            uint32_t voff = (uint32_t)((kc*16 + (lane&7) + (((lane>>3)&1)<<3))*FROW)
                          + (uint32_t)((lane>>4)*16);
            #pragma unroll
            for (int ng = 0; ng < 4; ng++) {
                uint32_t th[4];
                ldsm4t(th, Vh + voff + (uint32_t)(ng*32));
                mma16816(acc[2*ng],   ph[kc], th);
                mma16816(acc[2*ng],   pl[kc], th);
                mma16816(acc[2*ng+1], ph[kc], th+2);
                mma16816(acc[2*ng+1], pl[kc], th+2);
            }
        }
    }

    const float inv0 = 1.f / l0, inv1 = 1.f / l1;
    const int b = bh / H_, h = bh % H_;
    const int r0g = q0 + w*16 + (lane >> 2);
    const size_t base0 = (size_t)(b*T_ + r0g)*E_ + h*64 + 2*(lane & 3);
    const size_t base1 = base0 + (size_t)8*E_;
    #pragma unroll
    for (int nj = 0; nj < 8; nj++) {
        float o0 = acc[nj][0]*inv0, o1 = acc[nj][1]*inv0;
        float o2 = acc[nj][2]*inv1, o3 = acc[nj][3]*inv1;
        __half h0,lo0,h1,lo1,h2,lo2,h3,lo3;
        split_h(o0,h0,lo0); split_h(o1,h1,lo1);
        split_h(o2,h2,lo2); split_h(o3,h3,lo3);
        __half2 a; a.x=h0; a.y=h1;
        __half2 c; c.x=lo0; c.y=lo1;
        __half2 d2; d2.x=h2; d2.y=h3;
        __half2 e2; e2.x=lo2; e2.y=lo3;
        *(__half2*)(yh + base0 + nj*8) = a;
        *(__half2*)(yl + base0 + nj*8) = c;
        *(__half2*)(yh + base1 + nj*8) = d2;
        *(__half2*)(yl + base1 + nj*8) = e2;
    }
}

// ---------------- weight transpose (hi only) ----------------
__global__ void transpose_split_k(const float* __restrict__ W,
                                  __half* __restrict__ WTh,
                                  int K, int N) {
    __shared__ float t[32][33];
    const size_t lstride = (size_t)K * N;
    const float* Wl = W + lstride * blockIdx.z;
    __half* Hh = WTh + lstride * blockIdx.z;
    int n0 = blockIdx.x * 32, k0 = blockIdx.y * 32;
    int x = threadIdx.x, y = threadIdx.y;
    #pragma unroll
    for (int i = 0; i < 32; i += 8)
        t[y + i][x] = Wl[(size_t)(k0 + y + i) * N + n0 + x];
    __syncthreads();
    #pragma unroll
    for (int i = 0; i < 32; i += 8)
        Hh[(size_t)(n0 + y + i) * K + k0 + x] = __float2half_rn(t[x][y + i]);
}

// ---------------- wte pad (hi only fp16) ----------------
__global__ void wte_split_k(const float* __restrict__ wte,
                            __half* __restrict__ wh) {
    int i = blockIdx.x * blockDim.x + threadIdx.x;
    if (i >= VP_*E_) return;
    int row = i / E_;
    float v = (row < V_) ? wte[i] : 0.f;
    wh[i] = __float2half_rn(v);
}

// ---------------- embedding ----------------
__global__ void embed_k(const int* __restrict__ idx, const float* __restrict__ wte,
                        const float* __restrict__ wpe, float* __restrict__ x) {
    int i = blockIdx.x * blockDim.x + threadIdx.x;
    if (i >= M_*E_) return;
    int row = i / E_, e = i % E_;
    int t = row & (T_-1);
    x[i] = wte[(size_t)idx[row]*E_ + e] + wpe[t*E_ + e];
}

// ---------------- layernorm: 1 warp / row -> fp16 hi/lo ----------------
__global__ void __launch_bounds__(256)
ln_k(const float* __restrict__ x, const float* __restrict__ g,
     const float* __restrict__ b,
     __half* __restrict__ oh, __half* __restrict__ ol) {
    const int lane = threadIdx.x & 31;
    const int row = blockIdx.x * 8 + (threadIdx.x >> 5);
    const float* xr = x + (size_t)row*E_;
    float4 v4[6];
    float a = 0.f, q = 0.f;
    #pragma unroll
    for (int i = 0; i < 6; i++) {
        v4[i] = *(const float4*)(xr + (i*32 + lane)*4);
        a += v4[i].x + v4[i].y + v4[i].z + v4[i].w;
        q += v4[i].x*v4[i].x + v4[i].y*v4[i].y + v4[i].z*v4[i].z + v4[i].w*v4[i].w;
    }
    #pragma unroll
    for (int off = 16; off > 0; off >>= 1) {
        a += __shfl_xor_sync(0xffffffffu, a, off);
        q += __shfl_xor_sync(0xffffffffu, q, off);
    }
    float mu  = a * (1.f/E_);
    float var = q * (1.f/E_) - mu*mu;
    float inv = rsqrtf(var + 1e-5f);
    #pragma unroll
    for (int i = 0; i < 6; i++) {
        int e = (i*32 + lane)*4;
        float o0 = (v4[i].x - mu)*inv*g[e+0] + b[e+0];
        float o1 = (v4[i].y - mu)*inv*g[e+1] + b[e+1];
        float o2 = (v4[i].z - mu)*inv*g[e+2] + b[e+2];
        float o3 = (v4[i].w - mu)*inv*g[e+3] + b[e+3];
        __half h0,l0,h1,l1,h2,l2,h3,l3;
        split_h(o0,h0,l0); split_h(o1,h1,l1);
        split_h(o2,h2,l2); split_h(o3,h3,l3);
        __half2 hv0; hv0.x=h0; hv0.y=h1;
        __half2 hv1; hv1.x=h2; hv1.y=h3;
        __half2 lv0; lv0.x=l0; lv0.y=l1;
        __half2 lv1; lv1.x=l2; lv1.y=l3;
        *(__half2*)(oh + (size_t)row*E_ + e)     = hv0;
        *(__half2*)(oh + (size_t)row*E_ + e + 2) = hv1;
        *(__half2*)(ol + (size_t)row*E_ + e)     = lv0;
        *(__half2*)(ol + (size_t)row*E_ + e + 2) = lv1;
    }
}

// ---------------- launch ----------------
extern "C" void kernel_launch(void* const* d_in, const int* in_sizes, int n_in,
                              void* d_out, int out_size) {
    const int*   idx    = (const int*)  d_in[0];
    const float* wte    = (const float*)d_in[1];
    const float* wpe    = (const float*)d_in[2];
    const float* ln1_g  = (const float*)d_in[3];
    const float* ln1_b  = (const float*)d_in[4];
    const float* attn_w = (const float*)d_in[5];
    const float* attn_b = (const float*)d_in[6];
    const float* proj_w = (const float*)d_in[7];
    const float* proj_b = (const float*)d_in[8];
    const float* ln2_g  = (const float*)d_in[9];
    const float* ln2_b  = (const float*)d_in[10];
    const float* fc_w   = (const float*)d_in[11];
    const float* fc_b   = (const float*)d_in[12];
    const float* fcp_w  = (const float*)d_in[13];
    const float* fcp_b  = (const float*)d_in[14];
    const float* lnf_g  = (const float*)d_in[15];
    const float* lnf_b  = (const float*)d_in[16];
    float* out = (float*)d_out;

    float *x;
    __half *qkv4, *xh, *xl, *yh, *yl, *h4h, *h4l;
    __half *attnTh, *projTh, *fcTh, *fcpTh, *wteh;
    cudaGetSymbolAddress((void**)&x,    g_x);
    cudaGetSymbolAddress((void**)&qkv4, g_qkv4);
    cudaGetSymbolAddress((void**)&xh,   g_xh);   cudaGetSymbolAddress((void**)&xl,  g_xl);
    cudaGetSymbolAddress((void**)&yh,   g_yh);   cudaGetSymbolAddress((void**)&yl,  g_yl);
    cudaGetSymbolAddress((void**)&h4h,  g_h4h);  cudaGetSymbolAddress((void**)&h4l, g_h4l);
    cudaGetSymbolAddress((void**)&attnTh, g_attnTh);
    cudaGetSymbolAddress((void**)&projTh, g_projTh);
    cudaGetSymbolAddress((void**)&fcTh,   g_fcTh);
    cudaGetSymbolAddress((void**)&fcpTh,  g_fcpTh);
    cudaGetSymbolAddress((void**)&wteh,   g_wteh);

    cudaFuncSetAttribute(gemm_hf<1,2>, cudaFuncAttributeMaxDynamicSharedMemorySize, GSMEM2);
    cudaFuncSetAttribute(gemm_hf<3,0>, cudaFuncAttributeMaxDynamicSharedMemorySize, GSMEM2);
    cudaFuncSetAttribute(gemm_hf<2,1>, cudaFuncAttributeMaxDynamicSharedMemorySize, GSMEM2);
    cudaFuncSetAttribute(gemm_hf<0,0>, cudaFuncAttributeMaxDynamicSharedMemorySize, GSMEM2);
    cudaFuncSetAttribute(flash2_k,     cudaFuncAttributeMaxDynamicSharedMemorySize, FA2_SMEM);

    dim3 tb(32, 8);
    transpose_split_k<<<dim3(3*E_/32, E_/32, L_), tb>>>(attn_w, attnTh, E_, 3*E_);
    transpose_split_k<<<dim3(E_/32,   E_/32, L_), tb>>>(proj_w, projTh, E_, E_);
    transpose_split_k<<<dim3(4*E_/32, E_/32, L_), tb>>>(fc_w,   fcTh,   E_, 4*E_);
    transpose_split_k<<<dim3(E_/32, 4*E_/32, L_), tb>>>(fcp_w,  fcpTh,  4*E_, E_);
    wte_split_k<<<(VP_*E_ + 255)/256, 256>>>(wte, wteh);

    embed_k<<<(M_*E_ + 255)/256, 256>>>(idx, wte, wpe, x);

    for (int l = 0; l < L_; l++) {
        ln_k<<<M_/8, 256>>>(x, ln1_g + l*E_, ln1_b + l*E_, xh, xl);
        gemm_hf<1,2><<<dim3(M_/128, 3*E_/128), 256, GSMEM2>>>(
            xh, xl, attnTh + (size_t)l*3*E_*E_,
            attn_b + l*3*E_, nullptr, nullptr, qkv4, nullptr, M_, 3*E_, E_);
        flash2_k<<<dim3(T_/64, B_*H_), 128, FA2_SMEM>>>(qkv4, yh, yl);
        gemm_hf<3,0><<<dim3(M_/128, E_/128), 256, GSMEM2>>>(
            yh, yl, projTh + (size_t)l*E_*E_,
            proj_b + l*E_, x, x, nullptr, nullptr, M_, E_, E_);
        ln_k<<<M_/8, 256>>>(x, ln2_g + l*E_, ln2_b + l*E_, xh, xl);
        gemm_hf<2,1><<<dim3(M_/128, 4*E_/128), 256, GSMEM2>>>(
            xh, xl, fcTh + (size_t)l*4*E_*E_,
            fc_b + l*4*E_, nullptr, nullptr, h4h, h4l, M_, 4*E_, E_);
        gemm_hf<3,0><<<dim3(M_/128, E_/128), 256, GSMEM2>>>(
            h4h, h4l, fcpTh + (size_t)l*4*E_*E_,
            fcp_b + l*E_, x, x, nullptr, nullptr, M_, E_, 4*E_);
    }

    ln_k<<<M_/8, 256>>>(x, lnf_g, lnf_b, xh, xl);
    gemm_hf<0,0><<<dim3(M_/128, VP_/128), 256, GSMEM2>>>(
        xh, xl, wteh, nullptr, nullptr, out, nullptr, nullptr, M_, V_, E_);
}

// round 15
// speedup vs baseline: 1.4386x; 1.0221x over previous
#include <cuda_runtime.h>
#include <cuda_fp16.h>
#include <math.h>
#include <stdint.h>

#define E_ 768
#define L_ 12
#define H_ 12
#define D_ 64
#define B_ 2
#define T_ 1024
#define V_ 50257
#define VP_ 50304
#define M_ (B_*T_)
#define BHTD_ (B_*H_*T_*D_)

// ---------------- scratch ----------------
__device__ float g_x   [M_*E_];
__device__ __half g_qkv3[3*BHTD_];           // qh,kh,vh each [B,H,T,D] (q pre-scaled)
__device__ __half g_xh [M_*E_],  g_xl [M_*E_];
__device__ __half g_yh [M_*E_],  g_yl [M_*E_];
__device__ __half g_h4h[M_*4*E_],g_h4l[M_*4*E_];
// weights: hi only (2-term everywhere)
__device__ __half g_attnTh[L_*3*E_*E_];
__device__ __half g_projTh[L_*E_*E_];
__device__ __half g_fcTh  [L_*4*E_*E_];
__device__ __half g_fcpTh [L_*4*E_*E_];
__device__ __half g_wteh  [VP_*E_];

// ---------------- helpers ----------------
__device__ __forceinline__ uint32_t cvta_smem(const void* p){
    uint32_t a;
    asm("{.reg .u64 t; cvta.to.shared.u64 t, %1; cvt.u32.u64 %0, t;}" : "=r"(a) : "l"(p));
    return a;
}
__device__ __forceinline__ void ldsm4(uint32_t* r, uint32_t addr){
    asm volatile("ldmatrix.sync.aligned.m8n8.x4.shared.b16 {%0,%1,%2,%3}, [%4];"
        : "=r"(r[0]),"=r"(r[1]),"=r"(r[2]),"=r"(r[3]) : "r"(addr));
}
__device__ __forceinline__ void ldsm4t(uint32_t* r, uint32_t addr){
    asm volatile("ldmatrix.sync.aligned.m8n8.x4.trans.shared.b16 {%0,%1,%2,%3}, [%4];"
        : "=r"(r[0]),"=r"(r[1]),"=r"(r[2]),"=r"(r[3]) : "r"(addr));
}
__device__ __forceinline__ void mma16816(float* d, const uint32_t* a, const uint32_t* b){
    asm volatile("mma.sync.aligned.m16n8k16.row.col.f32.f16.f16.f32 "
        "{%0,%1,%2,%3}, {%4,%5,%6,%7}, {%8,%9}, {%0,%1,%2,%3};"
        : "+f"(d[0]),"+f"(d[1]),"+f"(d[2]),"+f"(d[3])
        : "r"(a[0]),"r"(a[1]),"r"(a[2]),"r"(a[3]), "r"(b[0]),"r"(b[1]));
}
__device__ __forceinline__ void cpa16(uint32_t s, const void* g){
    asm volatile("cp.async.cg.shared.global [%0], [%1], 16;" :: "r"(s), "l"(g));
}
__device__ __forceinline__ float gelu_f(float v){
    return 0.5f * v * (1.0f + erff(v * 0.70710678118654752f));
}
__device__ __forceinline__ uint32_t packh(float a, float b){
    __half2 t = __floats2half2_rn(a, b);
    return *reinterpret_cast<uint32_t*>(&t);
}
__device__ __forceinline__ float hhi(float a){
    return __half2float(__float2half_rn(a));
}
__device__ __forceinline__ void split_h(float v, __half& h, __half& l){
    h = __float2half_rn(v);
    l = __float2half_rn(v - __half2float(h));
}

// ------ fp16 2-term mma.sync GEMM: 128x128x32, 3-stage single-sync ring ------
// A rows 144B: [32 h hi | 32 h lo | pad16]. B rows 80B: [32 h hi | pad16].
#define GROWB 144
#define GOPB  18432
#define BSTR  80u
#define GSTG  (GOPB + 10240)
#define GSMEM2 (3*GSTG)             // 86016

// EPI: 0 none, 1 +bias, 2 gelu(+bias), 3 +bias+residual
// OUT: 0 fp32 C, 1 fp16 hi/lo (Ch,Cl), 2 qkv head-scatter into Ch (3 arrays, q scaled)
template<int EPI, int OUT>
__global__ void __launch_bounds__(256, 2)
gemm_hf(const __half* __restrict__ Ahg, const __half* __restrict__ Alg,
        const __half* __restrict__ Bhg,
        const float* __restrict__ bias, const float* __restrict__ res,
        float* __restrict__ C, __half* __restrict__ Ch,
        __half* __restrict__ Cl, int M, int N, int K) {
    extern __shared__ char smraw[];
    const uint32_t sb = cvta_smem(smraw);
    const int tid = threadIdx.x;
    const int lane = tid & 31, wid = tid >> 5;
    const int wm = wid & 3, wn = wid >> 2;
    const int m0 = blockIdx.x * 128, n0 = blockIdx.y * 128;
    const int nkb = K >> 5;

    float acc[2][8][4];
    #pragma unroll
    for (int i = 0; i < 2; i++)
        #pragma unroll
        for (int j = 0; j < 8; j++)
            #pragma unroll
            for (int t = 0; t < 4; t++) acc[i][j][t] = 0.f;

    auto load_stage = [&](int kb){
        const uint32_t st = sb + (uint32_t)(kb % 3) * GSTG;
        const int k0 = kb * 32;
        #pragma unroll
        for (int i = 0; i < 6; i++) {
            int j = tid + (i << 8);
            if (j < 1024) {
                int row = j >> 3, ch = j & 7;
                const __half* src = (ch < 4 ? Ahg : Alg)
                    + (size_t)(m0 + row) * K + k0 + (ch & 3) * 8;
                cpa16(st + (uint32_t)(row*GROWB + ch*16), src);
            } else {
                int jj = j - 1024;
                int row = jj >> 2, ch = jj & 3;
                const __half* src = Bhg + (size_t)(n0 + row) * K + k0 + ch * 8;
                cpa16(st + GOPB + (uint32_t)(row*80 + ch*16), src);
            }
        }
    };

    load_stage(0);
    asm volatile("cp.async.commit_group;" ::: "memory");
    load_stage(1);
    asm volatile("cp.async.commit_group;" ::: "memory");

    for (int kb = 0; kb < nkb; kb++) {
        asm volatile("cp.async.wait_group 1;" ::: "memory");
        __syncthreads();
        if (kb + 2 < nkb) load_stage(kb + 2);
        asm volatile("cp.async.commit_group;" ::: "memory");

        const uint32_t st = sb + (uint32_t)(kb % 3) * GSTG;
        const uint32_t Ab = st, Bb = st + GOPB;
        #pragma unroll
        for (int ks = 0; ks < 2; ks++) {
            uint32_t ah[2][4], al[2][4], bhf[8][2];
            #pragma unroll
            for (int mi = 0; mi < 2; mi++) {
                int row = wm*32 + mi*16 + (lane & 15);
                int ch  = 2*ks + (lane >> 4);
                uint32_t off = (uint32_t)(row*GROWB + ch*16);
                ldsm4(ah[mi], Ab + off);
                ldsm4(al[mi], Ab + off + 64);
            }
            #pragma unroll
            for (int p2 = 0; p2 < 4; p2++) {
                int nr = wn*64 + p2*16 + (lane & 7) + ((lane >> 4) << 3);
                int ch = 2*ks + ((lane >> 3) & 1);
                uint32_t off = (uint32_t)nr*BSTR + (uint32_t)(ch*16);
                uint32_t t[4];
                ldsm4(t, Bb + off);
                bhf[2*p2][0]=t[0]; bhf[2*p2][1]=t[1]; bhf[2*p2+1][0]=t[2]; bhf[2*p2+1][1]=t[3];
            }
            #pragma unroll
            for (int mi = 0; mi < 2; mi++)
                #pragma unroll
                for (int nj = 0; nj < 8; nj++) {
                    mma16816(acc[mi][nj], ah[mi], bhf[nj]);
                    mma16816(acc[mi][nj], al[mi], bhf[nj]);
                }
        }
    }

    // ---- epilogue ----
    const int mrow = m0 + wm*32 + (lane >> 2);
    const int ncol = n0 + wn*64 + 2*(lane & 3);
    const bool vec_ok = ((N & 1) == 0);
    #pragma unroll
    for (int mi = 0; mi < 2; mi++) {
        #pragma unroll
        for (int nj = 0; nj < 8; nj++) {
            int c = ncol + nj*8;
            #pragma unroll
            for (int h2 = 0; h2 < 2; h2++) {
                int rr = mrow + mi*16 + h2*8;
                float v0 = acc[mi][nj][h2*2], v1 = acc[mi][nj][h2*2+1];
                if (EPI >= 1 && c < N)     v0 += bias[c];
                if (EPI >= 1 && c+1 < N)   v1 += bias[c+1];
                if (EPI == 2) { v0 = gelu_f(v0); v1 = gelu_f(v1); }
                if (OUT == 2) {
                    int which = c / E_, e = c % E_;
                    int hh2 = e >> 6, d = e & 63;
                    int b = rr >> 10, t = rr & (T_-1);
                    size_t off = (((size_t)(b*H_ + hh2)*T_) + t)*D_ + d;
                    if (which == 0) { v0 *= 0.125f; v1 *= 0.125f; }
                    __half2 hv = __floats2half2_rn(v0, v1);
                    *(__half2*)(Ch + (size_t)which*BHTD_ + off) = hv;
                } else if (OUT == 1) {
                    if (EPI == 3) {
                        v0 += res[(size_t)rr*N + c]; v1 += res[(size_t)rr*N + c + 1];
                    }
                    __half h0, l0, h1, l1;
                    split_h(v0, h0, l0); split_h(v1, h1, l1);
                    __half2 hv; hv.x = h0; hv.y = h1;
                    __half2 lv; lv.x = l0; lv.y = l1;
                    *(__half2*)(Ch + (size_t)rr*N + c) = hv;
                    *(__half2*)(Cl + (size_t)rr*N + c) = lv;
                } else {
                    if (vec_ok && c + 1 < N) {
                        if (EPI == 3) {
                            v0 += res[(size_t)rr*N + c]; v1 += res[(size_t)rr*N + c + 1];
                        }
                        float2 o; o.x = v0; o.y = v1;
                        *(float2*)(C + (size_t)rr*N + c) = o;
                    } else {
                        if (c < N) {
                            if (EPI == 3) v0 += res[(size_t)rr*N + c];
                            C[(size_t)rr*N + c] = v0;
                        }
                        if (c + 1 < N) {
                            if (EPI == 3) v1 += res[(size_t)rr*N + c + 1];
                            C[(size_t)rr*N + c + 1] = v1;
                        }
                    }
                }
            }
        }
    }
}

// ------ fp16 flash attention: 64-q-row CTAs; Q 1-term, P 2-term --------------
#define FROW 144
#define FA2_SMEM 18432

__global__ void __launch_bounds__(128)
flash2_k(const __half* __restrict__ qkv3,
         __half* __restrict__ yh, __half* __restrict__ yl) {
    extern __shared__ char fsm[];
    const uint32_t sb = cvta_smem(fsm);
    const int tid = threadIdx.x, lane = tid & 31, w = tid >> 5;
    const int q0 = blockIdx.x * 64, bh = blockIdx.y;
    const __half *qh_g = qkv3;
    const __half *kh_g = qkv3 + BHTD_, *vh_g = qkv3 + 2*BHTD_;
    const size_t hb = (size_t)bh * T_ * D_;

    // ---- stage Q (64 x 64) hi, pull A-frags ----
    #pragma unroll
    for (int i = 0; i < 4; i++) {
        int j = tid + i*128;                 // 0..511
        int row = j >> 3, ch = j & 7;
        const __half* src = qh_g + hb + (size_t)(q0+row)*D_ + ch*8;
        cpa16(sb + (uint32_t)(row*FROW + ch*16), src);
    }
    asm volatile("cp.async.commit_group;" ::: "memory");
    asm volatile("cp.async.wait_group 0;" ::: "memory");
    __syncthreads();

    uint32_t qah[4][4];
    {
        uint32_t base = sb + (uint32_t)((w*16 + (lane&15))*FROW) + (uint32_t)((lane>>4)*16);
        #pragma unroll
        for (int kc = 0; kc < 4; kc++)
            ldsm4(qah[kc], base + kc*32);
    }
    __syncthreads();

    const uint32_t Kh = sb, Vh = sb + 9216u;
    float m0 = -1e30f, m1 = -1e30f, l0 = 0.f, l1 = 0.f;
    float acc[8][4];
    #pragma unroll
    for (int nj = 0; nj < 8; nj++)
        #pragma unroll
        for (int t = 0; t < 4; t++) acc[nj][t] = 0.f;

    const int nkt = blockIdx.x + 1;
    for (int kt = 0; kt < nkt; kt++) {
        __syncthreads();
        #pragma unroll
        for (int i = 0; i < 8; i++) {
            int j = tid + i*128;
            int arr = j >> 9;
            int row = (j >> 3) & 63, ch = j & 7;
            const __half* src = (arr ? vh_g : kh_g)
                + hb + (size_t)(kt*64+row)*D_ + ch*8;
            cpa16(sb + (uint32_t)arr*9216u + (uint32_t)(row*FROW + ch*16), src);
        }
        asm volatile("cp.async.commit_group;" ::: "memory");
        asm volatile("cp.async.wait_group 0;" ::: "memory");
        __syncthreads();

        float f[8][4];
        #pragma unroll
        for (int nj = 0; nj < 8; nj++)
            #pragma unroll
            for (int t = 0; t < 4; t++) f[nj][t] = 0.f;
        #pragma unroll
        for (int kc = 0; kc < 4; kc++) {
            uint32_t koff = (uint32_t)(((lane&7) + ((lane>>4)<<3))*FROW)
                          + (uint32_t)(kc*32 + (((lane>>3)&1)<<4));
            #pragma unroll
            for (int ng = 0; ng < 4; ng++) {
                uint32_t th[4];
                ldsm4(th, Kh + (uint32_t)(ng*16*FROW) + koff);
                mma16816(f[2*ng],   qah[kc], th);
                mma16816(f[2*ng+1], qah[kc], th+2);
            }
        }
        if (kt*64 + 63 > q0 + w*16) {
            int qg0 = q0 + w*16 + (lane>>2), qg1 = qg0 + 8;
            #pragma unroll
            for (int nj = 0; nj < 8; nj++) {
                int cc0 = kt*64 + nj*8 + 2*(lane&3), cc1 = cc0 + 1;
                if (cc0 > qg0) f[nj][0] = -1e30f;
                if (cc1 > qg0) f[nj][1] = -1e30f;
                if (cc0 > qg1) f[nj][2] = -1e30f;
                if (cc1 > qg1) f[nj][3] = -1e30f;
            }
        }
        float mx0 = -1e30f, mx1 = -1e30f;
        #pragma unroll
        for (int nj = 0; nj < 8; nj++) {
            mx0 = fmaxf(mx0, fmaxf(f[nj][0], f[nj][1]));
            mx1 = fmaxf(mx1, fmaxf(f[nj][2], f[nj][3]));
        }
        mx0 = fmaxf(mx0, __shfl_xor_sync(0xffffffffu, mx0, 1));
        mx0 = fmaxf(mx0, __shfl_xor_sync(0xffffffffu, mx0, 2));
        mx1 = fmaxf(mx1, __shfl_xor_sync(0xffffffffu, mx1, 1));
        mx1 = fmaxf(mx1, __shfl_xor_sync(0xffffffffu, mx1, 2));
        float nm0 = fmaxf(m0, mx0), nm1 = fmaxf(m1, mx1);
        float al0 = __expf(m0 - nm0), al1 = __expf(m1 - nm1);
        m0 = nm0; m1 = nm1;

        float s0 = 0.f, s1 = 0.f;
        uint32_t ph[4][4], pl[4][4];
        #pragma unroll
        for (int kc = 0; kc < 4; kc++) {
            float e0 = __expf(f[2*kc][0]   - nm0), e1 = __expf(f[2*kc][1]   - nm0);
            float e2 = __expf(f[2*kc][2]   - nm1), e3 = __expf(f[2*kc][3]   - nm1);
            float g0 = __expf(f[2*kc+1][0] - nm0), g1 = __expf(f[2*kc+1][1] - nm0);
            float g2 = __expf(f[2*kc+1][2] - nm1), g3 = __expf(f[2*kc+1][3] - nm1);
            s0 += e0 + e1 + g0 + g1;
            s1 += e2 + e3 + g2 + g3;
            ph[kc][0] = packh(e0, e1);  pl[kc][0] = packh(e0-hhi(e0), e1-hhi(e1));
            ph[kc][1] = packh(e2, e3);  pl[kc][1] = packh(e2-hhi(e2), e3-hhi(e3));
            ph[kc][2] = packh(g0, g1);  pl[kc][2] = packh(g0-hhi(g0), g1-hhi(g1));
            ph[kc][3] = packh(g2, g3);  pl[kc][3] = packh(g2-hhi(g2), g3-hhi(g3));
        }
        s0 += __shfl_xor_sync(0xffffffffu, s0, 1);
        s0 += __shfl_xor_sync(0xffffffffu, s0, 2);
        s1 += __shfl_xor_sync(0xffffffffu, s1, 1);
        s1 += __shfl_xor_sync(0xffffffffu, s1, 2);
        l0 = l0 * al0 + s0;
        l1 = l1 * al1 + s1;
        #pragma unroll
        for (int nj = 0; nj < 8; nj++) {
            acc[nj][0] *= al0; acc[nj][1] *= al0;
            acc[nj][2] *= al1; acc[nj][3] *= al1;
        }
        #pragma unroll
        for (int kc = 0; kc < 4; kc++) {
            uint32_t voff = (uint32_t)((kc*16 + (lane&7) + (((lane>>3)&1)<<3))*FROW)
                          + (uint32_t)((lane>>4)*16);
            #pragma unroll
            for (int ng = 0; ng < 4; ng++) {
                uint32_t th[4];
                ldsm4t(th, Vh + voff + (uint32_t)(ng*32));
                mma16816(acc[2*ng],   ph[kc], th);
                mma16816(acc[2*ng],   pl[kc], th);
                mma16816(acc[2*ng+1], ph[kc], th+2);
                mma16816(acc[2*ng+1], pl[kc], th+2);
            }
        }
    }

    const float inv0 = 1.f / l0, inv1 = 1.f / l1;
    const int b = bh / H_, h = bh % H_;
    const int r0g = q0 + w*16 + (lane >> 2);
    const size_t base0 = (size_t)(b*T_ + r0g)*E_ + h*64 + 2*(lane & 3);
    const size_t base1 = base0 + (size_t)8*E_;
    #pragma unroll
    for (int nj = 0; nj < 8; nj++) {
        float o0 = acc[nj][0]*inv0, o1 = acc[nj][1]*inv0;
        float o2 = acc[nj][2]*inv1, o3 = acc[nj][3]*inv1;
        __half h0,lo0,h1,lo1,h2,lo2,h3,lo3;
        split_h(o0,h0,lo0); split_h(o1,h1,lo1);
        split_h(o2,h2,lo2); split_h(o3,h3,lo3);
        __half2 a; a.x=h0; a.y=h1;
        __half2 c; c.x=lo0; c.y=lo1;
        __half2 d2; d2.x=h2; d2.y=h3;
        __half2 e2; e2.x=lo2; e2.y=lo3;
        *(__half2*)(yh + base0 + nj*8) = a;
        *(__half2*)(yl + base0 + nj*8) = c;
        *(__half2*)(yh + base1 + nj*8) = d2;
        *(__half2*)(yl + base1 + nj*8) = e2;
    }
}

// ---------------- weight transpose (hi only) ----------------
__global__ void transpose_split_k(const float* __restrict__ W,
                                  __half* __restrict__ WTh,
                                  int K, int N) {
    __shared__ float t[32][33];
    const size_t lstride = (size_t)K * N;
    const float* Wl = W + lstride * blockIdx.z;
    __half* Hh = WTh + lstride * blockIdx.z;
    int n0 = blockIdx.x * 32, k0 = blockIdx.y * 32;
    int x = threadIdx.x, y = threadIdx.y;
    #pragma unroll
    for (int i = 0; i < 32; i += 8)
        t[y + i][x] = Wl[(size_t)(k0 + y + i) * N + n0 + x];
    __syncthreads();
    #pragma unroll
    for (int i = 0; i < 32; i += 8)
        Hh[(size_t)(n0 + y + i) * K + k0 + x] = __float2half_rn(t[x][y + i]);
}

// ---------------- wte pad (hi only fp16) ----------------
__global__ void wte_split_k(const float* __restrict__ wte,
                            __half* __restrict__ wh) {
    int i = blockIdx.x * blockDim.x + threadIdx.x;
    if (i >= VP_*E_) return;
    int row = i / E_;
    float v = (row < V_) ? wte[i] : 0.f;
    wh[i] = __float2half_rn(v);
}

// ---------------- embedding ----------------
__global__ void embed_k(const int* __restrict__ idx, const float* __restrict__ wte,
                        const float* __restrict__ wpe, float* __restrict__ x) {
    int i = blockIdx.x * blockDim.x + threadIdx.x;
    if (i >= M_*E_) return;
    int row = i / E_, e = i % E_;
    int t = row & (T_-1);
    x[i] = wte[(size_t)idx[row]*E_ + e] + wpe[t*E_ + e];
}

// ---------------- layernorm: 1 warp / row -> fp16 hi/lo ----------------
__global__ void __launch_bounds__(256)
ln_k(const float* __restrict__ x, const float* __restrict__ g,
     const float* __restrict__ b,
     __half* __restrict__ oh, __half* __restrict__ ol) {
    const int lane = threadIdx.x & 31;
    const int row = blockIdx.x * 8 + (threadIdx.x >> 5);
    const float* xr = x + (size_t)row*E_;
    float4 v4[6];
    float a = 0.f, q = 0.f;
    #pragma unroll
    for (int i = 0; i < 6; i++) {
        v4[i] = *(const float4*)(xr + (i*32 + lane)*4);
        a += v4[i].x + v4[i].y + v4[i].z + v4[i].w;
        q += v4[i].x*v4[i].x + v4[i].y*v4[i].y + v4[i].z*v4[i].z + v4[i].w*v4[i].w;
    }
    #pragma unroll
    for (int off = 16; off > 0; off >>= 1) {
        a += __shfl_xor_sync(0xffffffffu, a, off);
        q += __shfl_xor_sync(0xffffffffu, q, off);
    }
    float mu  = a * (1.f/E_);
    float var = q * (1.f/E_) - mu*mu;
    float inv = rsqrtf(var + 1e-5f);
    #pragma unroll
    for (int i = 0; i < 6; i++) {
        int e = (i*32 + lane)*4;
        float o0 = (v4[i].x - mu)*inv*g[e+0] + b[e+0];
        float o1 = (v4[i].y - mu)*inv*g[e+1] + b[e+1];
        float o2 = (v4[i].z - mu)*inv*g[e+2] + b[e+2];
        float o3 = (v4[i].w - mu)*inv*g[e+3] + b[e+3];
        __half h0,l0,h1,l1,h2,l2,h3,l3;
        split_h(o0,h0,l0); split_h(o1,h1,l1);
        split_h(o2,h2,l2); split_h(o3,h3,l3);
        __half2 hv0; hv0.x=h0; hv0.y=h1;
        __half2 hv1; hv1.x=h2; hv1.y=h3;
        __half2 lv0; lv0.x=l0; lv0.y=l1;
        __half2 lv1; lv1.x=l2; lv1.y=l3;
        *(__half2*)(oh + (size_t)row*E_ + e)     = hv0;
        *(__half2*)(oh + (size_t)row*E_ + e + 2) = hv1;
        *(__half2*)(ol + (size_t)row*E_ + e)     = lv0;
        *(__half2*)(ol + (size_t)row*E_ + e + 2) = lv1;
    }
}

// ---------------- launch ----------------
extern "C" void kernel_launch(void* const* d_in, const int* in_sizes, int n_in,
                              void* d_out, int out_size) {
    const int*   idx    = (const int*)  d_in[0];
    const float* wte    = (const float*)d_in[1];
    const float* wpe    = (const float*)d_in[2];
    const float* ln1_g  = (const float*)d_in[3];
    const float* ln1_b  = (const float*)d_in[4];
    const float* attn_w = (const float*)d_in[5];
    const float* attn_b = (const float*)d_in[6];
    const float* proj_w = (const float*)d_in[7];
    const float* proj_b = (const float*)d_in[8];
    const float* ln2_g  = (const float*)d_in[9];
    const float* ln2_b  = (const float*)d_in[10];
    const float* fc_w   = (const float*)d_in[11];
    const float* fc_b   = (const float*)d_in[12];
    const float* fcp_w  = (const float*)d_in[13];
    const float* fcp_b  = (const float*)d_in[14];
    const float* lnf_g  = (const float*)d_in[15];
    const float* lnf_b  = (const float*)d_in[16];
    float* out = (float*)d_out;

    float *x;
    __half *qkv3, *xh, *xl, *yh, *yl, *h4h, *h4l;
    __half *attnTh, *projTh, *fcTh, *fcpTh, *wteh;
    cudaGetSymbolAddress((void**)&x,    g_x);
    cudaGetSymbolAddress((void**)&qkv3, g_qkv3);
    cudaGetSymbolAddress((void**)&xh,   g_xh);   cudaGetSymbolAddress((void**)&xl,  g_xl);
    cudaGetSymbolAddress((void**)&yh,   g_yh);   cudaGetSymbolAddress((void**)&yl,  g_yl);
    cudaGetSymbolAddress((void**)&h4h,  g_h4h);  cudaGetSymbolAddress((void**)&h4l, g_h4l);
    cudaGetSymbolAddress((void**)&attnTh, g_attnTh);
    cudaGetSymbolAddress((void**)&projTh, g_projTh);
    cudaGetSymbolAddress((void**)&fcTh,   g_fcTh);
    cudaGetSymbolAddress((void**)&fcpTh,  g_fcpTh);
    cudaGetSymbolAddress((void**)&wteh,   g_wteh);

    cudaFuncSetAttribute(gemm_hf<1,2>, cudaFuncAttributeMaxDynamicSharedMemorySize, GSMEM2);
    cudaFuncSetAttribute(gemm_hf<3,0>, cudaFuncAttributeMaxDynamicSharedMemorySize, GSMEM2);
    cudaFuncSetAttribute(gemm_hf<2,1>, cudaFuncAttributeMaxDynamicSharedMemorySize, GSMEM2);
    cudaFuncSetAttribute(gemm_hf<0,0>, cudaFuncAttributeMaxDynamicSharedMemorySize, GSMEM2);
    cudaFuncSetAttribute(flash2_k,     cudaFuncAttributeMaxDynamicSharedMemorySize, FA2_SMEM);

    dim3 tb(32, 8);
    transpose_split_k<<<dim3(3*E_/32, E_/32, L_), tb>>>(attn_w, attnTh, E_, 3*E_);
    transpose_split_k<<<dim3(E_/32,   E_/32, L_), tb>>>(proj_w, projTh, E_, E_);
    transpose_split_k<<<dim3(4*E_/32, E_/32, L_), tb>>>(fc_w,   fcTh,   E_, 4*E_);
    transpose_split_k<<<dim3(E_/32, 4*E_/32, L_), tb>>>(fcp_w,  fcpTh,  4*E_, E_);
    wte_split_k<<<(VP_*E_ + 255)/256, 256>>>(wte, wteh);

    embed_k<<<(M_*E_ + 255)/256, 256>>>(idx, wte, wpe, x);

    for (int l = 0; l < L_; l++) {
        ln_k<<<M_/8, 256>>>(x, ln1_g + l*E_, ln1_b + l*E_, xh, xl);
        gemm_hf<1,2><<<dim3(M_/128, 3*E_/128), 256, GSMEM2>>>(
            xh, xl, attnTh + (size_t)l*3*E_*E_,
            attn_b + l*3*E_, nullptr, nullptr, qkv3, nullptr, M_, 3*E_, E_);
        flash2_k<<<dim3(T_/64, B_*H_), 128, FA2_SMEM>>>(qkv3, yh, yl);
        gemm_hf<3,0><<<dim3(M_/128, E_/128), 256, GSMEM2>>>(
            yh, yl, projTh + (size_t)l*E_*E_,
            proj_b + l*E_, x, x, nullptr, nullptr, M_, E_, E_);
        ln_k<<<M_/8, 256>>>(x, ln2_g + l*E_, ln2_b + l*E_, xh, xl);
        gemm_hf<2,1><<<dim3(M_/128, 4*E_/128), 256, GSMEM2>>>(
            xh, xl, fcTh + (size_t)l*4*E_*E_,
            fc_b + l*4*E_, nullptr, nullptr, h4h, h4l, M_, 4*E_, E_);
        gemm_hf<3,0><<<dim3(M_/128, E_/128), 256, GSMEM2>>>(
            h4h, h4l, fcpTh + (size_t)l*4*E_*E_,
            fcp_b + l*E_, x, x, nullptr, nullptr, M_, E_, 4*E_);
    }

    ln_k<<<M_/8, 256>>>(x, lnf_g, lnf_b, xh, xl);
    gemm_hf<0,0><<<dim3(M_/128, VP_/128), 256, GSMEM2>>>(
        xh, xl, wteh, nullptr, nullptr, out, nullptr, nullptr, M_, V_, E_);
}

// round 16
// speedup vs baseline: 1.6619x; 1.1552x over previous
#include <cuda_runtime.h>
#include <cuda_fp16.h>
#include <math.h>
#include <stdint.h>

#define E_ 768
#define L_ 12
#define H_ 12
#define D_ 64
#define B_ 2
#define T_ 1024
#define V_ 50257
#define VP_ 50304
#define M_ (B_*T_)
#define BHTD_ (B_*H_*T_*D_)

// ---------------- scratch ----------------
__device__ float g_x   [M_*E_];
__device__ __half g_qkv3[3*BHTD_];           // qh,kh,vh each [B,H,T,D] (q pre-scaled)
__device__ __half g_xh [M_*E_],  g_xl [M_*E_];
__device__ __half g_yh [M_*E_];              // attention out (1-term)
__device__ __half g_h4h[M_*4*E_];            // gelu out (1-term)
// weights: hi only
__device__ __half g_attnTh[L_*3*E_*E_];
__device__ __half g_projTh[L_*E_*E_];
__device__ __half g_fcTh  [L_*4*E_*E_];
__device__ __half g_fcpTh [L_*4*E_*E_];
__device__ __half g_wteh  [VP_*E_];

// ---------------- helpers ----------------
__device__ __forceinline__ uint32_t cvta_smem(const void* p){
    uint32_t a;
    asm("{.reg .u64 t; cvta.to.shared.u64 t, %1; cvt.u32.u64 %0, t;}" : "=r"(a) : "l"(p));
    return a;
}
__device__ __forceinline__ void ldsm4(uint32_t* r, uint32_t addr){
    asm volatile("ldmatrix.sync.aligned.m8n8.x4.shared.b16 {%0,%1,%2,%3}, [%4];"
        : "=r"(r[0]),"=r"(r[1]),"=r"(r[2]),"=r"(r[3]) : "r"(addr));
}
__device__ __forceinline__ void ldsm4t(uint32_t* r, uint32_t addr){
    asm volatile("ldmatrix.sync.aligned.m8n8.x4.trans.shared.b16 {%0,%1,%2,%3}, [%4];"
        : "=r"(r[0]),"=r"(r[1]),"=r"(r[2]),"=r"(r[3]) : "r"(addr));
}
__device__ __forceinline__ void mma16816(float* d, const uint32_t* a, const uint32_t* b){
    asm volatile("mma.sync.aligned.m16n8k16.row.col.f32.f16.f16.f32 "
        "{%0,%1,%2,%3}, {%4,%5,%6,%7}, {%8,%9}, {%0,%1,%2,%3};"
        : "+f"(d[0]),"+f"(d[1]),"+f"(d[2]),"+f"(d[3])
        : "r"(a[0]),"r"(a[1]),"r"(a[2]),"r"(a[3]), "r"(b[0]),"r"(b[1]));
}
__device__ __forceinline__ void cpa16(uint32_t s, const void* g){
    asm volatile("cp.async.cg.shared.global [%0], [%1], 16;" :: "r"(s), "l"(g));
}
__device__ __forceinline__ float gelu_f(float v){
    return 0.5f * v * (1.0f + erff(v * 0.70710678118654752f));
}
__device__ __forceinline__ uint32_t packh(float a, float b){
    __half2 t = __floats2half2_rn(a, b);
    return *reinterpret_cast<uint32_t*>(&t);
}
__device__ __forceinline__ float hhi(float a){
    return __half2float(__float2half_rn(a));
}
__device__ __forceinline__ void split_h(float v, __half& h, __half& l){
    h = __float2half_rn(v);
    l = __float2half_rn(v - __half2float(h));
}

// ------ fp16 mma.sync GEMM: 128x128x32, 3-stage single-sync ring -------------
// A2=true : A rows 144B [hi|lo|pad]; 2-term.  A2=false: A rows 80B hi-only.
// B rows 80B hi-only always.
#define GROWB 144
#define BSTR  80u

// EPI: 0 none, 1 +bias, 2 gelu(+bias), 3 +bias+residual
// OUT: 0 fp32 C, 1 fp16 hi/lo, 2 qkv scatter (3 arrays, q scaled), 3 fp16 hi
template<int EPI, int OUT, bool A2>
__global__ void __launch_bounds__(256, 2)
gemm_hf(const __half* __restrict__ Ahg, const __half* __restrict__ Alg,
        const __half* __restrict__ Bhg,
        const float* __restrict__ bias, const float* __restrict__ res,
        float* __restrict__ C, __half* __restrict__ Ch,
        __half* __restrict__ Cl, int M, int N, int K) {
    constexpr uint32_t ASTR = A2 ? 144u : 80u;
    constexpr uint32_t AOPB = A2 ? 18432u : 10240u;
    constexpr uint32_t GSTG = AOPB + 10240u;
    extern __shared__ char smraw[];
    const uint32_t sb = cvta_smem(smraw);
    const int tid = threadIdx.x;
    const int lane = tid & 31, wid = tid >> 5;
    const int wm = wid & 3, wn = wid >> 2;
    const int m0 = blockIdx.x * 128, n0 = blockIdx.y * 128;
    const int nkb = K >> 5;

    float acc[2][8][4];
    #pragma unroll
    for (int i = 0; i < 2; i++)
        #pragma unroll
        for (int j = 0; j < 8; j++)
            #pragma unroll
            for (int t = 0; t < 4; t++) acc[i][j][t] = 0.f;

    auto load_stage = [&](int kb){
        const uint32_t st = sb + (uint32_t)(kb % 3) * GSTG;
        const int k0 = kb * 32;
        if (A2) {
            #pragma unroll
            for (int i = 0; i < 6; i++) {
                int j = tid + (i << 8);
                if (j < 1024) {
                    int row = j >> 3, ch = j & 7;
                    const __half* src = (ch < 4 ? Ahg : Alg)
                        + (size_t)(m0 + row) * K + k0 + (ch & 3) * 8;
                    cpa16(st + (uint32_t)(row*GROWB + ch*16), src);
                } else {
                    int jj = j - 1024;
                    int row = jj >> 2, ch = jj & 3;
                    const __half* src = Bhg + (size_t)(n0 + row) * K + k0 + ch * 8;
                    cpa16(st + AOPB + (uint32_t)(row*80 + ch*16), src);
                }
            }
        } else {
            #pragma unroll
            for (int i = 0; i < 4; i++) {
                int j = tid + (i << 8);
                bool isB = j >= 512;
                int jj = isB ? j - 512 : j;
                int row = jj >> 2, ch = jj & 3;
                const __half* src = (isB ? Bhg : Ahg)
                    + (size_t)((isB ? n0 : m0) + row) * K + k0 + ch * 8;
                cpa16(st + (isB ? AOPB : 0u) + (uint32_t)(row*80 + ch*16), src);
            }
        }
    };

    load_stage(0);
    asm volatile("cp.async.commit_group;" ::: "memory");
    load_stage(1);
    asm volatile("cp.async.commit_group;" ::: "memory");

    for (int kb = 0; kb < nkb; kb++) {
        asm volatile("cp.async.wait_group 1;" ::: "memory");
        __syncthreads();
        if (kb + 2 < nkb) load_stage(kb + 2);
        asm volatile("cp.async.commit_group;" ::: "memory");

        const uint32_t st = sb + (uint32_t)(kb % 3) * GSTG;
        const uint32_t Ab = st, Bb = st + AOPB;
        #pragma unroll
        for (int ks = 0; ks < 2; ks++) {
            uint32_t ah[2][4], al[2][4], bhf[8][2];
            #pragma unroll
            for (int mi = 0; mi < 2; mi++) {
                int row = wm*32 + mi*16 + (lane & 15);
                int ch  = 2*ks + (lane >> 4);
                uint32_t off = (uint32_t)row*ASTR + (uint32_t)(ch*16);
                ldsm4(ah[mi], Ab + off);
                if (A2) ldsm4(al[mi], Ab + off + 64);
            }
            #pragma unroll
            for (int p2 = 0; p2 < 4; p2++) {
                int nr = wn*64 + p2*16 + (lane & 7) + ((lane >> 4) << 3);
                int ch = 2*ks + ((lane >> 3) & 1);
                uint32_t off = (uint32_t)nr*BSTR + (uint32_t)(ch*16);
                uint32_t t[4];
                ldsm4(t, Bb + off);
                bhf[2*p2][0]=t[0]; bhf[2*p2][1]=t[1]; bhf[2*p2+1][0]=t[2]; bhf[2*p2+1][1]=t[3];
            }
            #pragma unroll
            for (int mi = 0; mi < 2; mi++)
                #pragma unroll
                for (int nj = 0; nj < 8; nj++) {
                    mma16816(acc[mi][nj], ah[mi], bhf[nj]);
                    if (A2) mma16816(acc[mi][nj], al[mi], bhf[nj]);
                }
        }
    }

    // ---- epilogue ----
    const int mrow = m0 + wm*32 + (lane >> 2);
    const int ncol = n0 + wn*64 + 2*(lane & 3);
    const bool vec_ok = ((N & 1) == 0);
    #pragma unroll
    for (int mi = 0; mi < 2; mi++) {
        #pragma unroll
        for (int nj = 0; nj < 8; nj++) {
            int c = ncol + nj*8;
            #pragma unroll
            for (int h2 = 0; h2 < 2; h2++) {
                int rr = mrow + mi*16 + h2*8;
                float v0 = acc[mi][nj][h2*2], v1 = acc[mi][nj][h2*2+1];
                if (EPI >= 1 && c < N)     v0 += bias[c];
                if (EPI >= 1 && c+1 < N)   v1 += bias[c+1];
                if (EPI == 2) { v0 = gelu_f(v0); v1 = gelu_f(v1); }
                if (OUT == 2) {
                    int which = c / E_, e = c % E_;
                    int hh2 = e >> 6, d = e & 63;
                    int b = rr >> 10, t = rr & (T_-1);
                    size_t off = (((size_t)(b*H_ + hh2)*T_) + t)*D_ + d;
                    if (which == 0) { v0 *= 0.125f; v1 *= 0.125f; }
                    __half2 hv = __floats2half2_rn(v0, v1);
                    *(__half2*)(Ch + (size_t)which*BHTD_ + off) = hv;
                } else if (OUT == 1) {
                    if (EPI == 3) {
                        v0 += res[(size_t)rr*N + c]; v1 += res[(size_t)rr*N + c + 1];
                    }
                    __half h0, l0, h1, l1;
                    split_h(v0, h0, l0); split_h(v1, h1, l1);
                    __half2 hv; hv.x = h0; hv.y = h1;
                    __half2 lv; lv.x = l0; lv.y = l1;
                    *(__half2*)(Ch + (size_t)rr*N + c) = hv;
                    *(__half2*)(Cl + (size_t)rr*N + c) = lv;
                } else if (OUT == 3) {
                    __half2 hv = __floats2half2_rn(v0, v1);
                    *(__half2*)(Ch + (size_t)rr*N + c) = hv;
                } else {
                    if (vec_ok && c + 1 < N) {
                        if (EPI == 3) {
                            v0 += res[(size_t)rr*N + c]; v1 += res[(size_t)rr*N + c + 1];
                        }
                        float2 o; o.x = v0; o.y = v1;
                        *(float2*)(C + (size_t)rr*N + c) = o;
                    } else {
                        if (c < N) {
                            if (EPI == 3) v0 += res[(size_t)rr*N + c];
                            C[(size_t)rr*N + c] = v0;
                        }
                        if (c + 1 < N) {
                            if (EPI == 3) v1 += res[(size_t)rr*N + c + 1];
                            C[(size_t)rr*N + c + 1] = v1;
                        }
                    }
                }
            }
        }
    }
}

#define GSMEM_A2 (3*(18432 + 10240))   // 86016
#define GSMEM_A1 (3*(10240 + 10240))   // 61440

// ------ fp16 flash attention: 64-q-row CTAs; Q 1-term, P 2-term, y hi only ---
#define FROW 144
#define FA2_SMEM 18432

__global__ void __launch_bounds__(128)
flash2_k(const __half* __restrict__ qkv3, __half* __restrict__ yh) {
    extern __shared__ char fsm[];
    const uint32_t sb = cvta_smem(fsm);
    const int tid = threadIdx.x, lane = tid & 31, w = tid >> 5;
    const int q0 = blockIdx.x * 64, bh = blockIdx.y;
    const __half *qh_g = qkv3;
    const __half *kh_g = qkv3 + BHTD_, *vh_g = qkv3 + 2*BHTD_;
    const size_t hb = (size_t)bh * T_ * D_;

    #pragma unroll
    for (int i = 0; i < 4; i++) {
        int j = tid + i*128;
        int row = j >> 3, ch = j & 7;
        const __half* src = qh_g + hb + (size_t)(q0+row)*D_ + ch*8;
        cpa16(sb + (uint32_t)(row*FROW + ch*16), src);
    }
    asm volatile("cp.async.commit_group;" ::: "memory");
    asm volatile("cp.async.wait_group 0;" ::: "memory");
    __syncthreads();

    uint32_t qah[4][4];
    {
        uint32_t base = sb + (uint32_t)((w*16 + (lane&15))*FROW) + (uint32_t)((lane>>4)*16);
        #pragma unroll
        for (int kc = 0; kc < 4; kc++)
            ldsm4(qah[kc], base + kc*32);
    }
    __syncthreads();

    const uint32_t Kh = sb, Vh = sb + 9216u;
    float m0 = -1e30f, m1 = -1e30f, l0 = 0.f, l1 = 0.f;
    float acc[8][4];
    #pragma unroll
    for (int nj = 0; nj < 8; nj++)
        #pragma unroll
        for (int t = 0; t < 4; t++) acc[nj][t] = 0.f;

    const int nkt = blockIdx.x + 1;
    for (int kt = 0; kt < nkt; kt++) {
        __syncthreads();
        #pragma unroll
        for (int i = 0; i < 8; i++) {
            int j = tid + i*128;
            int arr = j >> 9;
            int row = (j >> 3) & 63, ch = j & 7;
            const __half* src = (arr ? vh_g : kh_g)
                + hb + (size_t)(kt*64+row)*D_ + ch*8;
            cpa16(sb + (uint32_t)arr*9216u + (uint32_t)(row*FROW + ch*16), src);
        }
        asm volatile("cp.async.commit_group;" ::: "memory");
        asm volatile("cp.async.wait_group 0;" ::: "memory");
        __syncthreads();

        float f[8][4];
        #pragma unroll
        for (int nj = 0; nj < 8; nj++)
            #pragma unroll
            for (int t = 0; t < 4; t++) f[nj][t] = 0.f;
        #pragma unroll
        for (int kc = 0; kc < 4; kc++) {
            uint32_t koff = (uint32_t)(((lane&7) + ((lane>>4)<<3))*FROW)
                          + (uint32_t)(kc*32 + (((lane>>3)&1)<<4));
            #pragma unroll
            for (int ng = 0; ng < 4; ng++) {
                uint32_t th[4];
                ldsm4(th, Kh + (uint32_t)(ng*16*FROW) + koff);
                mma16816(f[2*ng],   qah[kc], th);
                mma16816(f[2*ng+1], qah[kc], th+2);
            }
        }
        if (kt*64 + 63 > q0 + w*16) {
            int qg0 = q0 + w*16 + (lane>>2), qg1 = qg0 + 8;
            #pragma unroll
            for (int nj = 0; nj < 8; nj++) {
                int cc0 = kt*64 + nj*8 + 2*(lane&3), cc1 = cc0 + 1;
                if (cc0 > qg0) f[nj][0] = -1e30f;
                if (cc1 > qg0) f[nj][1] = -1e30f;
                if (cc0 > qg1) f[nj][2] = -1e30f;
                if (cc1 > qg1) f[nj][3] = -1e30f;
            }
        }
        float mx0 = -1e30f, mx1 = -1e30f;
        #pragma unroll
        for (int nj = 0; nj < 8; nj++) {
            mx0 = fmaxf(mx0, fmaxf(f[nj][0], f[nj][1]));
            mx1 = fmaxf(mx1, fmaxf(f[nj][2], f[nj][3]));
        }
        mx0 = fmaxf(mx0, __shfl_xor_sync(0xffffffffu, mx0, 1));
        mx0 = fmaxf(mx0, __shfl_xor_sync(0xffffffffu, mx0, 2));
        mx1 = fmaxf(mx1, __shfl_xor_sync(0xffffffffu, mx1, 1));
        mx1 = fmaxf(mx1, __shfl_xor_sync(0xffffffffu, mx1, 2));
        float nm0 = fmaxf(m0, mx0), nm1 = fmaxf(m1, mx1);
        float al0 = __expf(m0 - nm0), al1 = __expf(m1 - nm1);
        m0 = nm0; m1 = nm1;

        float s0 = 0.f, s1 = 0.f;
        uint32_t ph[4][4], pl[4][4];
        #pragma unroll
        for (int kc = 0; kc < 4; kc++) {
            float e0 = __expf(f[2*kc][0]   - nm0), e1 = __expf(f[2*kc][1]   - nm0);
            float e2 = __expf(f[2*kc][2]   - nm1), e3 = __expf(f[2*kc][3]   - nm1);
            float g0 = __expf(f[2*kc+1][0] - nm0), g1 = __expf(f[2*kc+1][1] - nm0);
            float g2 = __expf(f[2*kc+1][2] - nm1), g3 = __expf(f[2*kc+1][3] - nm1);
            s0 += e0 + e1 + g0 + g1;
            s1 += e2 + e3 + g2 + g3;
            ph[kc][0] = packh(e0, e1);  pl[kc][0] = packh(e0-hhi(e0), e1-hhi(e1));
            ph[kc][1] = packh(e2, e3);  pl[kc][1] = packh(e2-hhi(e2), e3-hhi(e3));
            ph[kc][2] = packh(g0, g1);  pl[kc][2] = packh(g0-hhi(g0), g1-hhi(g1));
            ph[kc][3] = packh(g2, g3);  pl[kc][3] = packh(g2-hhi(g2), g3-hhi(g3));
        }
        s0 += __shfl_xor_sync(0xffffffffu, s0, 1);
        s0 += __shfl_xor_sync(0xffffffffu, s0, 2);
        s1 += __shfl_xor_sync(0xffffffffu, s1, 1);
        s1 += __shfl_xor_sync(0xffffffffu, s1, 2);
        l0 = l0 * al0 + s0;
        l1 = l1 * al1 + s1;
        #pragma unroll
        for (int nj = 0; nj < 8; nj++) {
            acc[nj][0] *= al0; acc[nj][1] *= al0;
            acc[nj][2] *= al1; acc[nj][3] *= al1;
        }
        #pragma unroll
        for (int kc = 0; kc < 4; kc++) {
            uint32_t voff = (uint32_t)((kc*16 + (lane&7) + (((lane>>3)&1)<<3))*FROW)
                          + (uint32_t)((lane>>4)*16);
            #pragma unroll
            for (int ng = 0; ng < 4; ng++) {
                uint32_t th[4];
                ldsm4t(th, Vh + voff + (uint32_t)(ng*32));
                mma16816(acc[2*ng],   ph[kc], th);
                mma16816(acc[2*ng],   pl[kc], th);
                mma16816(acc[2*ng+1], ph[kc], th+2);
                mma16816(acc[2*ng+1], pl[kc], th+2);
            }
        }
    }

    const float inv0 = 1.f / l0, inv1 = 1.f / l1;
    const int b = bh / H_, h = bh % H_;
    const int r0g = q0 + w*16 + (lane >> 2);
    const size_t base0 = (size_t)(b*T_ + r0g)*E_ + h*64 + 2*(lane & 3);
    const size_t base1 = base0 + (size_t)8*E_;
    #pragma unroll
    for (int nj = 0; nj < 8; nj++) {
        __half2 a = __floats2half2_rn(acc[nj][0]*inv0, acc[nj][1]*inv0);
        __half2 d2 = __floats2half2_rn(acc[nj][2]*inv1, acc[nj][3]*inv1);
        *(__half2*)(yh + base0 + nj*8) = a;
        *(__half2*)(yh + base1 + nj*8) = d2;
    }
}

// ---------------- weight transpose (hi only) ----------------
__global__ void transpose_split_k(const float* __restrict__ W,
                                  __half* __restrict__ WTh,
                                  int K, int N) {
    __shared__ float t[32][33];
    const size_t lstride = (size_t)K * N;
    const float* Wl = W + lstride * blockIdx.z;
    __half* Hh = WTh + lstride * blockIdx.z;
    int n0 = blockIdx.x * 32, k0 = blockIdx.y * 32;
    int x = threadIdx.x, y = threadIdx.y;
    #pragma unroll
    for (int i = 0; i < 32; i += 8)
        t[y + i][x] = Wl[(size_t)(k0 + y + i) * N + n0 + x];
    __syncthreads();
    #pragma unroll
    for (int i = 0; i < 32; i += 8)
        Hh[(size_t)(n0 + y + i) * K + k0 + x] = __float2half_rn(t[x][y + i]);
}

// ---------------- wte pad (hi only fp16) ----------------
__global__ void wte_split_k(const float* __restrict__ wte,
                            __half* __restrict__ wh) {
    int i = blockIdx.x * blockDim.x + threadIdx.x;
    if (i >= VP_*E_) return;
    int row = i / E_;
    float v = (row < V_) ? wte[i] : 0.f;
    wh[i] = __float2half_rn(v);
}

// ---------------- embedding ----------------
__global__ void embed_k(const int* __restrict__ idx, const float* __restrict__ wte,
                        const float* __restrict__ wpe, float* __restrict__ x) {
    int i = blockIdx.x * blockDim.x + threadIdx.x;
    if (i >= M_*E_) return;
    int row = i / E_, e = i % E_;
    int t = row & (T_-1);
    x[i] = wte[(size_t)idx[row]*E_ + e] + wpe[t*E_ + e];
}

// ---------------- layernorm: 1 warp / row -> fp16 hi/lo ----------------
__global__ void __launch_bounds__(256)
ln_k(const float* __restrict__ x, const float* __restrict__ g,
     const float* __restrict__ b,
     __half* __restrict__ oh, __half* __restrict__ ol) {
    const int lane = threadIdx.x & 31;
    const int row = blockIdx.x * 8 + (threadIdx.x >> 5);
    const float* xr = x + (size_t)row*E_;
    float4 v4[6];
    float a = 0.f, q = 0.f;
    #pragma unroll
    for (int i = 0; i < 6; i++) {
        v4[i] = *(const float4*)(xr + (i*32 + lane)*4);
        a += v4[i].x + v4[i].y + v4[i].z + v4[i].w;
        q += v4[i].x*v4[i].x + v4[i].y*v4[i].y + v4[i].z*v4[i].z + v4[i].w*v4[i].w;
    }
    #pragma unroll
    for (int off = 16; off > 0; off >>= 1) {
        a += __shfl_xor_sync(0xffffffffu, a, off);
        q += __shfl_xor_sync(0xffffffffu, q, off);
    }
    float mu  = a * (1.f/E_);
    float var = q * (1.f/E_) - mu*mu;
    float inv = rsqrtf(var + 1e-5f);
    #pragma unroll
    for (int i = 0; i < 6; i++) {
        int e = (i*32 + lane)*4;
        float o0 = (v4[i].x - mu)*inv*g[e+0] + b[e+0];
        float o1 = (v4[i].y - mu)*inv*g[e+1] + b[e+1];
        float o2 = (v4[i].z - mu)*inv*g[e+2] + b[e+2];
        float o3 = (v4[i].w - mu)*inv*g[e+3] + b[e+3];
        __half h0,l0,h1,l1,h2,l2,h3,l3;
        split_h(o0,h0,l0); split_h(o1,h1,l1);
        split_h(o2,h2,l2); split_h(o3,h3,l3);
        __half2 hv0; hv0.x=h0; hv0.y=h1;
        __half2 hv1; hv1.x=h2; hv1.y=h3;
        __half2 lv0; lv0.x=l0; lv0.y=l1;
        __half2 lv1; lv1.x=l2; lv1.y=l3;
        *(__half2*)(oh + (size_t)row*E_ + e)     = hv0;
        *(__half2*)(oh + (size_t)row*E_ + e + 2) = hv1;
        *(__half2*)(ol + (size_t)row*E_ + e)     = lv0;
        *(__half2*)(ol + (size_t)row*E_ + e + 2) = lv1;
    }
}

// ---------------- launch ----------------
extern "C" void kernel_launch(void* const* d_in, const int* in_sizes, int n_in,
                              void* d_out, int out_size) {
    const int*   idx    = (const int*)  d_in[0];
    const float* wte    = (const float*)d_in[1];
    const float* wpe    = (const float*)d_in[2];
    const float* ln1_g  = (const float*)d_in[3];
    const float* ln1_b  = (const float*)d_in[4];
    const float* attn_w = (const float*)d_in[5];
    const float* attn_b = (const float*)d_in[6];
    const float* proj_w = (const float*)d_in[7];
    const float* proj_b = (const float*)d_in[8];
    const float* ln2_g  = (const float*)d_in[9];
    const float* ln2_b  = (const float*)d_in[10];
    const float* fc_w   = (const float*)d_in[11];
    const float* fc_b   = (const float*)d_in[12];
    const float* fcp_w  = (const float*)d_in[13];
    const float* fcp_b  = (const float*)d_in[14];
    const float* lnf_g  = (const float*)d_in[15];
    const float* lnf_b  = (const float*)d_in[16];
    float* out = (float*)d_out;

    float *x;
    __half *qkv3, *xh, *xl, *yh, *h4h;
    __half *attnTh, *projTh, *fcTh, *fcpTh, *wteh;
    cudaGetSymbolAddress((void**)&x,    g_x);
    cudaGetSymbolAddress((void**)&qkv3, g_qkv3);
    cudaGetSymbolAddress((void**)&xh,   g_xh);   cudaGetSymbolAddress((void**)&xl,  g_xl);
    cudaGetSymbolAddress((void**)&yh,   g_yh);
    cudaGetSymbolAddress((void**)&h4h,  g_h4h);
    cudaGetSymbolAddress((void**)&attnTh, g_attnTh);
    cudaGetSymbolAddress((void**)&projTh, g_projTh);
    cudaGetSymbolAddress((void**)&fcTh,   g_fcTh);
    cudaGetSymbolAddress((void**)&fcpTh,  g_fcpTh);
    cudaGetSymbolAddress((void**)&wteh,   g_wteh);

    cudaFuncSetAttribute(gemm_hf<1,2,true>,  cudaFuncAttributeMaxDynamicSharedMemorySize, GSMEM_A2);
    cudaFuncSetAttribute(gemm_hf<3,0,false>, cudaFuncAttributeMaxDynamicSharedMemorySize, GSMEM_A1);
    cudaFuncSetAttribute(gemm_hf<2,3,true>,  cudaFuncAttributeMaxDynamicSharedMemorySize, GSMEM_A2);
    cudaFuncSetAttribute(gemm_hf<0,0,true>,  cudaFuncAttributeMaxDynamicSharedMemorySize, GSMEM_A2);
    cudaFuncSetAttribute(flash2_k,           cudaFuncAttributeMaxDynamicSharedMemorySize, FA2_SMEM);

    dim3 tb(32, 8);
    transpose_split_k<<<dim3(3*E_/32, E_/32, L_), tb>>>(attn_w, attnTh, E_, 3*E_);
    transpose_split_k<<<dim3(E_/32,   E_/32, L_), tb>>>(proj_w, projTh, E_, E_);
    transpose_split_k<<<dim3(4*E_/32, E_/32, L_), tb>>>(fc_w,   fcTh,   E_, 4*E_);
    transpose_split_k<<<dim3(E_/32, 4*E_/32, L_), tb>>>(fcp_w,  fcpTh,  4*E_, E_);
    wte_split_k<<<(VP_*E_ + 255)/256, 256>>>(wte, wteh);

    embed_k<<<(M_*E_ + 255)/256, 256>>>(idx, wte, wpe, x);

    for (int l = 0; l < L_; l++) {
        ln_k<<<M_/8, 256>>>(x, ln1_g + l*E_, ln1_b + l*E_, xh, xl);
        gemm_hf<1,2,true><<<dim3(M_/128, 3*E_/128), 256, GSMEM_A2>>>(
            xh, xl, attnTh + (size_t)l*3*E_*E_,
            attn_b + l*3*E_, nullptr, nullptr, qkv3, nullptr, M_, 3*E_, E_);
        flash2_k<<<dim3(T_/64, B_*H_), 128, FA2_SMEM>>>(qkv3, yh);
        gemm_hf<3,0,false><<<dim3(M_/128, E_/128), 256, GSMEM_A1>>>(
            yh, nullptr, projTh + (size_t)l*E_*E_,
            proj_b + l*E_, x, x, nullptr, nullptr, M_, E_, E_);
        ln_k<<<M_/8, 256>>>(x, ln2_g + l*E_, ln2_b + l*E_, xh, xl);
        gemm_hf<2,3,true><<<dim3(M_/128, 4*E_/128), 256, GSMEM_A2>>>(
            xh, xl, fcTh + (size_t)l*4*E_*E_,
            fc_b + l*4*E_, nullptr, nullptr, h4h, nullptr, M_, 4*E_, E_);
        gemm_hf<3,0,false><<<dim3(M_/128, E_/128), 256, GSMEM_A1>>>(
            h4h, nullptr, fcpTh + (size_t)l*4*E_*E_,
            fcp_b + l*E_, x, x, nullptr, nullptr, M_, E_, 4*E_);
    }

    ln_k<<<M_/8, 256>>>(x, lnf_g, lnf_b, xh, xl);
    gemm_hf<0,0,true><<<dim3(M_/128, VP_/128), 256, GSMEM_A2>>>(
        xh, xl, wteh, nullptr, nullptr, out, nullptr, nullptr, M_, V_, E_);
}

// round 17
// speedup vs baseline: 1.9535x; 1.1755x over previous
#include <cuda_runtime.h>
#include <cuda_fp16.h>
#include <math.h>
#include <stdint.h>

#define E_ 768
#define L_ 12
#define H_ 12
#define D_ 64
#define B_ 2
#define T_ 1024
#define V_ 50257
#define VP_ 50304
#define M_ (B_*T_)
#define BHTD_ (B_*H_*T_*D_)

// ---------------- scratch ----------------
__device__ float g_x   [M_*E_];
__device__ __half g_qkv3[3*BHTD_];           // qh,kh,vh each [B,H,T,D] (q pre-scaled)
__device__ __half g_xh [M_*E_],  g_xl [M_*E_];   // lo used only for final LN
__device__ __half g_yh [M_*E_];
__device__ __half g_h4h[M_*4*E_];
// weights: hi only
__device__ __half g_attnTh[L_*3*E_*E_];
__device__ __half g_projTh[L_*E_*E_];
__device__ __half g_fcTh  [L_*4*E_*E_];
__device__ __half g_fcpTh [L_*4*E_*E_];
__device__ __half g_wteh  [VP_*E_];

// ---------------- helpers ----------------
__device__ __forceinline__ uint32_t cvta_smem(const void* p){
    uint32_t a;
    asm("{.reg .u64 t; cvta.to.shared.u64 t, %1; cvt.u32.u64 %0, t;}" : "=r"(a) : "l"(p));
    return a;
}
__device__ __forceinline__ void ldsm4(uint32_t* r, uint32_t addr){
    asm volatile("ldmatrix.sync.aligned.m8n8.x4.shared.b16 {%0,%1,%2,%3}, [%4];"
        : "=r"(r[0]),"=r"(r[1]),"=r"(r[2]),"=r"(r[3]) : "r"(addr));
}
__device__ __forceinline__ void ldsm4t(uint32_t* r, uint32_t addr){
    asm volatile("ldmatrix.sync.aligned.m8n8.x4.trans.shared.b16 {%0,%1,%2,%3}, [%4];"
        : "=r"(r[0]),"=r"(r[1]),"=r"(r[2]),"=r"(r[3]) : "r"(addr));
}
__device__ __forceinline__ void mma16816(float* d, const uint32_t* a, const uint32_t* b){
    asm volatile("mma.sync.aligned.m16n8k16.row.col.f32.f16.f16.f32 "
        "{%0,%1,%2,%3}, {%4,%5,%6,%7}, {%8,%9}, {%0,%1,%2,%3};"
        : "+f"(d[0]),"+f"(d[1]),"+f"(d[2]),"+f"(d[3])
        : "r"(a[0]),"r"(a[1]),"r"(a[2]),"r"(a[3]), "r"(b[0]),"r"(b[1]));
}
__device__ __forceinline__ void cpa16(uint32_t s, const void* g){
    asm volatile("cp.async.cg.shared.global [%0], [%1], 16;" :: "r"(s), "l"(g));
}
__device__ __forceinline__ float gelu_f(float v){
    return 0.5f * v * (1.0f + erff(v * 0.70710678118654752f));
}
__device__ __forceinline__ uint32_t packh(float a, float b){
    __half2 t = __floats2half2_rn(a, b);
    return *reinterpret_cast<uint32_t*>(&t);
}
__device__ __forceinline__ float hhi(float a){
    return __half2float(__float2half_rn(a));
}
__device__ __forceinline__ void split_h(float v, __half& h, __half& l){
    h = __float2half_rn(v);
    l = __float2half_rn(v - __half2float(h));
}

// ------ fp16 mma.sync GEMM: 128x128x32, 3-stage single-sync ring -------------
// A2=true : A rows 144B [hi|lo|pad]; 2-term.  A2=false: A rows 80B hi-only.
// B rows 80B hi-only always.
#define GROWB 144
#define BSTR  80u

// EPI: 0 none, 1 +bias, 2 gelu(+bias), 3 +bias+residual
// OUT: 0 fp32 C, 2 qkv scatter (3 arrays, q scaled), 3 fp16 hi
template<int EPI, int OUT, bool A2>
__global__ void __launch_bounds__(256, 2)
gemm_hf(const __half* __restrict__ Ahg, const __half* __restrict__ Alg,
        const __half* __restrict__ Bhg,
        const float* __restrict__ bias, const float* __restrict__ res,
        float* __restrict__ C, __half* __restrict__ Ch,
        int M, int N, int K) {
    constexpr uint32_t ASTR = A2 ? 144u : 80u;
    constexpr uint32_t AOPB = A2 ? 18432u : 10240u;
    constexpr uint32_t GSTG = AOPB + 10240u;
    extern __shared__ char smraw[];
    const uint32_t sb = cvta_smem(smraw);
    const int tid = threadIdx.x;
    const int lane = tid & 31, wid = tid >> 5;
    const int wm = wid & 3, wn = wid >> 2;
    const int m0 = blockIdx.x * 128, n0 = blockIdx.y * 128;
    const int nkb = K >> 5;

    float acc[2][8][4];
    #pragma unroll
    for (int i = 0; i < 2; i++)
        #pragma unroll
        for (int j = 0; j < 8; j++)
            #pragma unroll
            for (int t = 0; t < 4; t++) acc[i][j][t] = 0.f;

    auto load_stage = [&](int kb){
        const uint32_t st = sb + (uint32_t)(kb % 3) * GSTG;
        const int k0 = kb * 32;
        if (A2) {
            #pragma unroll
            for (int i = 0; i < 6; i++) {
                int j = tid + (i << 8);
                if (j < 1024) {
                    int row = j >> 3, ch = j & 7;
                    const __half* src = (ch < 4 ? Ahg : Alg)
                        + (size_t)(m0 + row) * K + k0 + (ch & 3) * 8;
                    cpa16(st + (uint32_t)(row*GROWB + ch*16), src);
                } else {
                    int jj = j - 1024;
                    int row = jj >> 2, ch = jj & 3;
                    const __half* src = Bhg + (size_t)(n0 + row) * K + k0 + ch * 8;
                    cpa16(st + AOPB + (uint32_t)(row*80 + ch*16), src);
                }
            }
        } else {
            #pragma unroll
            for (int i = 0; i < 4; i++) {
                int j = tid + (i << 8);
                bool isB = j >= 512;
                int jj = isB ? j - 512 : j;
                int row = jj >> 2, ch = jj & 3;
                const __half* src = (isB ? Bhg : Ahg)
                    + (size_t)((isB ? n0 : m0) + row) * K + k0 + ch * 8;
                cpa16(st + (isB ? AOPB : 0u) + (uint32_t)(row*80 + ch*16), src);
            }
        }
    };

    load_stage(0);
    asm volatile("cp.async.commit_group;" ::: "memory");
    load_stage(1);
    asm volatile("cp.async.commit_group;" ::: "memory");

    for (int kb = 0; kb < nkb; kb++) {
        asm volatile("cp.async.wait_group 1;" ::: "memory");
        __syncthreads();
        if (kb + 2 < nkb) load_stage(kb + 2);
        asm volatile("cp.async.commit_group;" ::: "memory");

        const uint32_t st = sb + (uint32_t)(kb % 3) * GSTG;
        const uint32_t Ab = st, Bb = st + AOPB;
        #pragma unroll
        for (int ks = 0; ks < 2; ks++) {
            uint32_t ah[2][4], al[2][4], bhf[8][2];
            #pragma unroll
            for (int mi = 0; mi < 2; mi++) {
                int row = wm*32 + mi*16 + (lane & 15);
                int ch  = 2*ks + (lane >> 4);
                uint32_t off = (uint32_t)row*ASTR + (uint32_t)(ch*16);
                ldsm4(ah[mi], Ab + off);
                if (A2) ldsm4(al[mi], Ab + off + 64);
            }
            #pragma unroll
            for (int p2 = 0; p2 < 4; p2++) {
                int nr = wn*64 + p2*16 + (lane & 7) + ((lane >> 4) << 3);
                int ch = 2*ks + ((lane >> 3) & 1);
                uint32_t off = (uint32_t)nr*BSTR + (uint32_t)(ch*16);
                uint32_t t[4];
                ldsm4(t, Bb + off);
                bhf[2*p2][0]=t[0]; bhf[2*p2][1]=t[1]; bhf[2*p2+1][0]=t[2]; bhf[2*p2+1][1]=t[3];
            }
            #pragma unroll
            for (int mi = 0; mi < 2; mi++)
                #pragma unroll
                for (int nj = 0; nj < 8; nj++) {
                    mma16816(acc[mi][nj], ah[mi], bhf[nj]);
                    if (A2) mma16816(acc[mi][nj], al[mi], bhf[nj]);
                }
        }
    }

    // ---- epilogue ----
    const int mrow = m0 + wm*32 + (lane >> 2);
    const int ncol = n0 + wn*64 + 2*(lane & 3);
    const bool vec_ok = ((N & 1) == 0);
    #pragma unroll
    for (int mi = 0; mi < 2; mi++) {
        #pragma unroll
        for (int nj = 0; nj < 8; nj++) {
            int c = ncol + nj*8;
            #pragma unroll
            for (int h2 = 0; h2 < 2; h2++) {
                int rr = mrow + mi*16 + h2*8;
                float v0 = acc[mi][nj][h2*2], v1 = acc[mi][nj][h2*2+1];
                if (EPI >= 1 && c < N)     v0 += bias[c];
                if (EPI >= 1 && c+1 < N)   v1 += bias[c+1];
                if (EPI == 2) { v0 = gelu_f(v0); v1 = gelu_f(v1); }
                if (OUT == 2) {
                    int which = c / E_, e = c % E_;
                    int hh2 = e >> 6, d = e & 63;
                    int b = rr >> 10, t = rr & (T_-1);
                    size_t off = (((size_t)(b*H_ + hh2)*T_) + t)*D_ + d;
                    if (which == 0) { v0 *= 0.125f; v1 *= 0.125f; }
                    __half2 hv = __floats2half2_rn(v0, v1);
                    *(__half2*)(Ch + (size_t)which*BHTD_ + off) = hv;
                } else if (OUT == 3) {
                    __half2 hv = __floats2half2_rn(v0, v1);
                    *(__half2*)(Ch + (size_t)rr*N + c) = hv;
                } else {
                    if (vec_ok && c + 1 < N) {
                        if (EPI == 3) {
                            v0 += res[(size_t)rr*N + c]; v1 += res[(size_t)rr*N + c + 1];
                        }
                        float2 o; o.x = v0; o.y = v1;
                        *(float2*)(C + (size_t)rr*N + c) = o;
                    } else {
                        if (c < N) {
                            if (EPI == 3) v0 += res[(size_t)rr*N + c];
                            C[(size_t)rr*N + c] = v0;
                        }
                        if (c + 1 < N) {
                            if (EPI == 3) v1 += res[(size_t)rr*N + c + 1];
                            C[(size_t)rr*N + c + 1] = v1;
                        }
                    }
                }
            }
        }
    }
}

#define GSMEM_A2 (3*(18432 + 10240))   // 86016
#define GSMEM_A1 (3*(10240 + 10240))   // 61440

// ------ fp16 flash attention: 64-q-row CTAs; Q 1-term, P 2-term, y hi only ---
#define FROW 144
#define FA2_SMEM 18432

__global__ void __launch_bounds__(128)
flash2_k(const __half* __restrict__ qkv3, __half* __restrict__ yh) {
    extern __shared__ char fsm[];
    const uint32_t sb = cvta_smem(fsm);
    const int tid = threadIdx.x, lane = tid & 31, w = tid >> 5;
    const int q0 = blockIdx.x * 64, bh = blockIdx.y;
    const __half *qh_g = qkv3;
    const __half *kh_g = qkv3 + BHTD_, *vh_g = qkv3 + 2*BHTD_;
    const size_t hb = (size_t)bh * T_ * D_;

    #pragma unroll
    for (int i = 0; i < 4; i++) {
        int j = tid + i*128;
        int row = j >> 3, ch = j & 7;
        const __half* src = qh_g + hb + (size_t)(q0+row)*D_ + ch*8;
        cpa16(sb + (uint32_t)(row*FROW + ch*16), src);
    }
    asm volatile("cp.async.commit_group;" ::: "memory");
    asm volatile("cp.async.wait_group 0;" ::: "memory");
    __syncthreads();

    uint32_t qah[4][4];
    {
        uint32_t base = sb + (uint32_t)((w*16 + (lane&15))*FROW) + (uint32_t)((lane>>4)*16);
        #pragma unroll
        for (int kc = 0; kc < 4; kc++)
            ldsm4(qah[kc], base + kc*32);
    }
    __syncthreads();

    const uint32_t Kh = sb, Vh = sb + 9216u;
    float m0 = -1e30f, m1 = -1e30f, l0 = 0.f, l1 = 0.f;
    float acc[8][4];
    #pragma unroll
    for (int nj = 0; nj < 8; nj++)
        #pragma unroll
        for (int t = 0; t < 4; t++) acc[nj][t] = 0.f;

    const int nkt = blockIdx.x + 1;
    for (int kt = 0; kt < nkt; kt++) {
        __syncthreads();
        #pragma unroll
        for (int i = 0; i < 8; i++) {
            int j = tid + i*128;
            int arr = j >> 9;
            int row = (j >> 3) & 63, ch = j & 7;
            const __half* src = (arr ? vh_g : kh_g)
                + hb + (size_t)(kt*64+row)*D_ + ch*8;
            cpa16(sb + (uint32_t)arr*9216u + (uint32_t)(row*FROW + ch*16), src);
        }
        asm volatile("cp.async.commit_group;" ::: "memory");
        asm volatile("cp.async.wait_group 0;" ::: "memory");
        __syncthreads();

        float f[8][4];
        #pragma unroll
        for (int nj = 0; nj < 8; nj++)
            #pragma unroll
            for (int t = 0; t < 4; t++) f[nj][t] = 0.f;
        #pragma unroll
        for (int kc = 0; kc < 4; kc++) {
            uint32_t koff = (uint32_t)(((lane&7) + ((lane>>4)<<3))*FROW)
                          + (uint32_t)(kc*32 + (((lane>>3)&1)<<4));
            #pragma unroll
            for (int ng = 0; ng < 4; ng++) {
                uint32_t th[4];
                ldsm4(th, Kh + (uint32_t)(ng*16*FROW) + koff);
                mma16816(f[2*ng],   qah[kc], th);
                mma16816(f[2*ng+1], qah[kc], th+2);
            }
        }
        if (kt*64 + 63 > q0 + w*16) {
            int qg0 = q0 + w*16 + (lane>>2), qg1 = qg0 + 8;
            #pragma unroll
            for (int nj = 0; nj < 8; nj++) {
                int cc0 = kt*64 + nj*8 + 2*(lane&3), cc1 = cc0 + 1;
                if (cc0 > qg0) f[nj][0] = -1e30f;
                if (cc1 > qg0) f[nj][1] = -1e30f;
                if (cc0 > qg1) f[nj][2] = -1e30f;
                if (cc1 > qg1) f[nj][3] = -1e30f;
            }
        }
        float mx0 = -1e30f, mx1 = -1e30f;
        #pragma unroll
        for (int nj = 0; nj < 8; nj++) {
            mx0 = fmaxf(mx0, fmaxf(f[nj][0], f[nj][1]));
            mx1 = fmaxf(mx1, fmaxf(f[nj][2], f[nj][3]));
        }
        mx0 = fmaxf(mx0, __shfl_xor_sync(0xffffffffu, mx0, 1));
        mx0 = fmaxf(mx0, __shfl_xor_sync(0xffffffffu, mx0, 2));
        mx1 = fmaxf(mx1, __shfl_xor_sync(0xffffffffu, mx1, 1));
        mx1 = fmaxf(mx1, __shfl_xor_sync(0xffffffffu, mx1, 2));
        float nm0 = fmaxf(m0, mx0), nm1 = fmaxf(m1, mx1);
        float al0 = __expf(m0 - nm0), al1 = __expf(m1 - nm1);
        m0 = nm0; m1 = nm1;

        float s0 = 0.f, s1 = 0.f;
        uint32_t ph[4][4], pl[4][4];
        #pragma unroll
        for (int kc = 0; kc < 4; kc++) {
            float e0 = __expf(f[2*kc][0]   - nm0), e1 = __expf(f[2*kc][1]   - nm0);
            float e2 = __expf(f[2*kc][2]   - nm1), e3 = __expf(f[2*kc][3]   - nm1);
            float g0 = __expf(f[2*kc+1][0] - nm0), g1 = __expf(f[2*kc+1][1] - nm0);
            float g2 = __expf(f[2*kc+1][2] - nm1), g3 = __expf(f[2*kc+1][3] - nm1);
            s0 += e0 + e1 + g0 + g1;
            s1 += e2 + e3 + g2 + g3;
            ph[kc][0] = packh(e0, e1);  pl[kc][0] = packh(e0-hhi(e0), e1-hhi(e1));
            ph[kc][1] = packh(e2, e3);  pl[kc][1] = packh(e2-hhi(e2), e3-hhi(e3));
            ph[kc][2] = packh(g0, g1);  pl[kc][2] = packh(g0-hhi(g0), g1-hhi(g1));
            ph[kc][3] = packh(g2, g3);  pl[kc][3] = packh(g2-hhi(g2), g3-hhi(g3));
        }
        s0 += __shfl_xor_sync(0xffffffffu, s0, 1);
        s0 += __shfl_xor_sync(0xffffffffu, s0, 2);
        s1 += __shfl_xor_sync(0xffffffffu, s1, 1);
        s1 += __shfl_xor_sync(0xffffffffu, s1, 2);
        l0 = l0 * al0 + s0;
        l1 = l1 * al1 + s1;
        #pragma unroll
        for (int nj = 0; nj < 8; nj++) {
            acc[nj][0] *= al0; acc[nj][1] *= al0;
            acc[nj][2] *= al1; acc[nj][3] *= al1;
        }
        #pragma unroll
        for (int kc = 0; kc < 4; kc++) {
            uint32_t voff = (uint32_t)((kc*16 + (lane&7) + (((lane>>3)&1)<<3))*FROW)
                          + (uint32_t)((lane>>4)*16);
            #pragma unroll
            for (int ng = 0; ng < 4; ng++) {
                uint32_t th[4];
                ldsm4t(th, Vh + voff + (uint32_t)(ng*32));
                mma16816(acc[2*ng],   ph[kc], th);
                mma16816(acc[2*ng],   pl[kc], th);
                mma16816(acc[2*ng+1], ph[kc], th+2);
                mma16816(acc[2*ng+1], pl[kc], th+2);
            }
        }
    }

    const float inv0 = 1.f / l0, inv1 = 1.f / l1;
    const int b = bh / H_, h = bh % H_;
    const int r0g = q0 + w*16 + (lane >> 2);
    const size_t base0 = (size_t)(b*T_ + r0g)*E_ + h*64 + 2*(lane & 3);
    const size_t base1 = base0 + (size_t)8*E_;
    #pragma unroll
    for (int nj = 0; nj < 8; nj++) {
        __half2 a = __floats2half2_rn(acc[nj][0]*inv0, acc[nj][1]*inv0);
        __half2 d2 = __floats2half2_rn(acc[nj][2]*inv1, acc[nj][3]*inv1);
        *(__half2*)(yh + base0 + nj*8) = a;
        *(__half2*)(yh + base1 + nj*8) = d2;
    }
}

// ---------------- weight transpose (hi only) ----------------
__global__ void transpose_split_k(const float* __restrict__ W,
                                  __half* __restrict__ WTh,
                                  int K, int N) {
    __shared__ float t[32][33];
    const size_t lstride = (size_t)K * N;
    const float* Wl = W + lstride * blockIdx.z;
    __half* Hh = WTh + lstride * blockIdx.z;
    int n0 = blockIdx.x * 32, k0 = blockIdx.y * 32;
    int x = threadIdx.x, y = threadIdx.y;
    #pragma unroll
    for (int i = 0; i < 32; i += 8)
        t[y + i][x] = Wl[(size_t)(k0 + y + i) * N + n0 + x];
    __syncthreads();
    #pragma unroll
    for (int i = 0; i < 32; i += 8)
        Hh[(size_t)(n0 + y + i) * K + k0 + x] = __float2half_rn(t[x][y + i]);
}

// ---------------- wte pad (hi only fp16) ----------------
__global__ void wte_split_k(const float* __restrict__ wte,
                            __half* __restrict__ wh) {
    int i = blockIdx.x * blockDim.x + threadIdx.x;
    if (i >= VP_*E_) return;
    int row = i / E_;
    float v = (row < V_) ? wte[i] : 0.f;
    wh[i] = __float2half_rn(v);
}

// ---------------- embedding ----------------
__global__ void embed_k(const int* __restrict__ idx, const float* __restrict__ wte,
                        const float* __restrict__ wpe, float* __restrict__ x) {
    int i = blockIdx.x * blockDim.x + threadIdx.x;
    if (i >= M_*E_) return;
    int row = i / E_, e = i % E_;
    int t = row & (T_-1);
    x[i] = wte[(size_t)idx[row]*E_ + e] + wpe[t*E_ + e];
}

// ------ layernorm: 1 warp / row -> fp16; LO controls lo-channel output -------
template<bool LO>
__global__ void __launch_bounds__(256)
ln_k(const float* __restrict__ x, const float* __restrict__ g,
     const float* __restrict__ b,
     __half* __restrict__ oh, __half* __restrict__ ol) {
    const int lane = threadIdx.x & 31;
    const int row = blockIdx.x * 8 + (threadIdx.x >> 5);
    const float* xr = x + (size_t)row*E_;
    float4 v4[6];
    float a = 0.f, q = 0.f;
    #pragma unroll
    for (int i = 0; i < 6; i++) {
        v4[i] = *(const float4*)(xr + (i*32 + lane)*4);
        a += v4[i].x + v4[i].y + v4[i].z + v4[i].w;
        q += v4[i].x*v4[i].x + v4[i].y*v4[i].y + v4[i].z*v4[i].z + v4[i].w*v4[i].w;
    }
    #pragma unroll
    for (int off = 16; off > 0; off >>= 1) {
        a += __shfl_xor_sync(0xffffffffu, a, off);
        q += __shfl_xor_sync(0xffffffffu, q, off);
    }
    float mu  = a * (1.f/E_);
    float var = q * (1.f/E_) - mu*mu;
    float inv = rsqrtf(var + 1e-5f);
    #pragma unroll
    for (int i = 0; i < 6; i++) {
        int e = (i*32 + lane)*4;
        float o0 = (v4[i].x - mu)*inv*g[e+0] + b[e+0];
        float o1 = (v4[i].y - mu)*inv*g[e+1] + b[e+1];
        float o2 = (v4[i].z - mu)*inv*g[e+2] + b[e+2];
        float o3 = (v4[i].w - mu)*inv*g[e+3] + b[e+3];
        if (LO) {
            __half h0,l0,h1,l1,h2,l2,h3,l3;
            split_h(o0,h0,l0); split_h(o1,h1,l1);
            split_h(o2,h2,l2); split_h(o3,h3,l3);
            __half2 hv0; hv0.x=h0; hv0.y=h1;
            __half2 hv1; hv1.x=h2; hv1.y=h3;
            __half2 lv0; lv0.x=l0; lv0.y=l1;
            __half2 lv1; lv1.x=l2; lv1.y=l3;
            *(__half2*)(oh + (size_t)row*E_ + e)     = hv0;
            *(__half2*)(oh + (size_t)row*E_ + e + 2) = hv1;
            *(__half2*)(ol + (size_t)row*E_ + e)     = lv0;
            *(__half2*)(ol + (size_t)row*E_ + e + 2) = lv1;
        } else {
            __half2 hv0 = __floats2half2_rn(o0, o1);
            __half2 hv1 = __floats2half2_rn(o2, o3);
            *(__half2*)(oh + (size_t)row*E_ + e)     = hv0;
            *(__half2*)(oh + (size_t)row*E_ + e + 2) = hv1;
        }
    }
}

// ---------------- launch ----------------
extern "C" void kernel_launch(void* const* d_in, const int* in_sizes, int n_in,
                              void* d_out, int out_size) {
    const int*   idx    = (const int*)  d_in[0];
    const float* wte    = (const float*)d_in[1];
    const float* wpe    = (const float*)d_in[2];
    const float* ln1_g  = (const float*)d_in[3];
    const float* ln1_b  = (const float*)d_in[4];
    const float* attn_w = (const float*)d_in[5];
    const float* attn_b = (const float*)d_in[6];
    const float* proj_w = (const float*)d_in[7];
    const float* proj_b = (const float*)d_in[8];
    const float* ln2_g  = (const float*)d_in[9];
    const float* ln2_b  = (const float*)d_in[10];
    const float* fc_w   = (const float*)d_in[11];
    const float* fc_b   = (const float*)d_in[12];
    const float* fcp_w  = (const float*)d_in[13];
    const float* fcp_b  = (const float*)d_in[14];
    const float* lnf_g  = (const float*)d_in[15];
    const float* lnf_b  = (const float*)d_in[16];
    float* out = (float*)d_out;

    float *x;
    __half *qkv3, *xh, *xl, *yh, *h4h;
    __half *attnTh, *projTh, *fcTh, *fcpTh, *wteh;
    cudaGetSymbolAddress((void**)&x,    g_x);
    cudaGetSymbolAddress((void**)&qkv3, g_qkv3);
    cudaGetSymbolAddress((void**)&xh,   g_xh);   cudaGetSymbolAddress((void**)&xl,  g_xl);
    cudaGetSymbolAddress((void**)&yh,   g_yh);
    cudaGetSymbolAddress((void**)&h4h,  g_h4h);
    cudaGetSymbolAddress((void**)&attnTh, g_attnTh);
    cudaGetSymbolAddress((void**)&projTh, g_projTh);
    cudaGetSymbolAddress((void**)&fcTh,   g_fcTh);
    cudaGetSymbolAddress((void**)&fcpTh,  g_fcpTh);
    cudaGetSymbolAddress((void**)&wteh,   g_wteh);

    cudaFuncSetAttribute(gemm_hf<1,2,false>, cudaFuncAttributeMaxDynamicSharedMemorySize, GSMEM_A1);
    cudaFuncSetAttribute(gemm_hf<3,0,false>, cudaFuncAttributeMaxDynamicSharedMemorySize, GSMEM_A1);
    cudaFuncSetAttribute(gemm_hf<2,3,false>, cudaFuncAttributeMaxDynamicSharedMemorySize, GSMEM_A1);
    cudaFuncSetAttribute(gemm_hf<0,0,true>,  cudaFuncAttributeMaxDynamicSharedMemorySize, GSMEM_A2);
    cudaFuncSetAttribute(flash2_k,           cudaFuncAttributeMaxDynamicSharedMemorySize, FA2_SMEM);

    dim3 tb(32, 8);
    transpose_split_k<<<dim3(3*E_/32, E_/32, L_), tb>>>(attn_w, attnTh, E_, 3*E_);
    transpose_split_k<<<dim3(E_/32,   E_/32, L_), tb>>>(proj_w, projTh, E_, E_);
    transpose_split_k<<<dim3(4*E_/32, E_/32, L_), tb>>>(fc_w,   fcTh,   E_, 4*E_);
    transpose_split_k<<<dim3(E_/32, 4*E_/32, L_), tb>>>(fcp_w,  fcpTh,  4*E_, E_);
    wte_split_k<<<(VP_*E_ + 255)/256, 256>>>(wte, wteh);

    embed_k<<<(M_*E_ + 255)/256, 256>>>(idx, wte, wpe, x);

    for (int l = 0; l < L_; l++) {
        ln_k<false><<<M_/8, 256>>>(x, ln1_g + l*E_, ln1_b + l*E_, xh, nullptr);
        gemm_hf<1,2,false><<<dim3(M_/128, 3*E_/128), 256, GSMEM_A1>>>(
            xh, nullptr, attnTh + (size_t)l*3*E_*E_,
            attn_b + l*3*E_, nullptr, nullptr, qkv3, M_, 3*E_, E_);
        flash2_k<<<dim3(T_/64, B_*H_), 128, FA2_SMEM>>>(qkv3, yh);
        gemm_hf<3,0,false><<<dim3(M_/128, E_/128), 256, GSMEM_A1>>>(
            yh, nullptr, projTh + (size_t)l*E_*E_,
            proj_b + l*E_, x, x, nullptr, M_, E_, E_);
        ln_k<false><<<M_/8, 256>>>(x, ln2_g + l*E_, ln2_b + l*E_, xh, nullptr);
        gemm_hf<2,3,false><<<dim3(M_/128, 4*E_/128), 256, GSMEM_A1>>>(
            xh, nullptr, fcTh + (size_t)l*4*E_*E_,
            fc_b + l*4*E_, nullptr, nullptr, h4h, M_, 4*E_, E_);
        gemm_hf<3,0,false><<<dim3(M_/128, E_/128), 256, GSMEM_A1>>>(
            h4h, nullptr, fcpTh + (size_t)l*4*E_*E_,
            fcp_b + l*E_, x, x, nullptr, M_, E_, 4*E_);
    }

    ln_k<true><<<M_/8, 256>>>(x, lnf_g, lnf_b, xh, xl);
    gemm_hf<0,0,true><<<dim3(M_/128, VP_/128), 256, GSMEM_A2>>>(
        xh, xl, wteh, nullptr, nullptr, out, nullptr, M_, V_, E_);
}